// round 7
// baseline (speedup 1.0000x reference)
#include <cuda_runtime.h>
#include <cuda_bf16.h>
#include <math.h>
#include <stdint.h>

// Problem dims
#define TT 128
#define BB 32
#define EE 512
#define HH 1024
#define VV 32000
#define GG (3 * HH)       // 3072
#define MM (TT * BB)      // 4096
#define NCTA 128

// ---------------- scratch (device globals) ----------------------------------
__device__ float g_gx[MM * GG];                // [T*B, 3H]
__device__ float g_hall[MM * HH];              // [T*B, H]
__device__ float g_hT[2][HH * BB];             // ping-pong transposed hidden
__device__ unsigned g_cnt = 0;
__device__ unsigned g_gen = 0;
__device__ __nv_bfloat16 g_Ah[VV * EE];        // emb split, then hall split
__device__ __nv_bfloat16 g_Al[VV * EE];
__device__ __nv_bfloat16 g_Bh[VV * HH];        // out_w split
__device__ __nv_bfloat16 g_Bl[VV * HH];
__device__ __nv_bfloat16 g_Wh[GG * EE];        // w_ih split
__device__ __nv_bfloat16 g_Wl[GG * EE];

// ---------------- helpers ----------------------------------------------------
__device__ __forceinline__ uint32_t smem_u32(const void* p) {
    uint32_t a;
    asm("{ .reg .u64 t; cvta.to.shared.u64 t, %1; cvt.u32.u64 %0, t; }"
        : "=r"(a) : "l"(p));
    return a;
}
__device__ __forceinline__ unsigned ld_acq(unsigned* p) {
    unsigned v;
    asm volatile("ld.acquire.gpu.u32 %0, [%1];" : "=r"(v) : "l"(p) : "memory");
    return v;
}
__device__ __forceinline__ float4 ldcg4(const float4* p) {
    float4 v;
    asm volatile("ld.global.cg.v4.f32 {%0,%1,%2,%3}, [%4];"
                 : "=f"(v.x), "=f"(v.y), "=f"(v.z), "=f"(v.w) : "l"(p));
    return v;
}
__device__ __forceinline__ void cp16(uint32_t dst, const void* src) {
    asm volatile("cp.async.cg.shared.global [%0], [%1], 16;"
                 :: "r"(dst), "l"(src) : "memory");
}
__device__ __forceinline__ void cp_commit() {
    asm volatile("cp.async.commit_group;" ::: "memory");
}
__device__ __forceinline__ void cp_wait1() {
    asm volatile("cp.async.wait_group 1;" ::: "memory");
}
__device__ __forceinline__ void ldm_x4(uint32_t* r, uint32_t addr) {
    asm volatile("ldmatrix.sync.aligned.m8n8.x4.shared.b16 {%0,%1,%2,%3}, [%4];"
                 : "=r"(r[0]), "=r"(r[1]), "=r"(r[2]), "=r"(r[3]) : "r"(addr));
}
__device__ __forceinline__ void mma16816(float* d, const uint32_t* a, const uint32_t* b) {
    asm volatile(
        "mma.sync.aligned.m16n8k16.row.col.f32.bf16.bf16.f32 "
        "{%0,%1,%2,%3}, {%4,%5,%6,%7}, {%8,%9}, {%0,%1,%2,%3};"
        : "+f"(d[0]), "+f"(d[1]), "+f"(d[2]), "+f"(d[3])
        : "r"(a[0]), "r"(a[1]), "r"(a[2]), "r"(a[3]), "r"(b[0]), "r"(b[1]));
}

// ---------------- fp32 -> bf16 hi/lo split -----------------------------------
__global__ __launch_bounds__(256)
void split_bf16(const float* __restrict__ src, __nv_bfloat16* __restrict__ hi,
                __nv_bfloat16* __restrict__ lo, int n4)
{
    int i = blockIdx.x * 256 + threadIdx.x;
    if (i >= n4) return;
    float4 v = ((const float4*)src)[i];
    __nv_bfloat16 h0 = __float2bfloat16(v.x);
    __nv_bfloat16 h1 = __float2bfloat16(v.y);
    __nv_bfloat16 h2 = __float2bfloat16(v.z);
    __nv_bfloat16 h3 = __float2bfloat16(v.w);
    __nv_bfloat162* hp = (__nv_bfloat162*)hi;
    __nv_bfloat162* lp = (__nv_bfloat162*)lo;
    hp[2 * i + 0] = __nv_bfloat162(h0, h1);
    hp[2 * i + 1] = __nv_bfloat162(h2, h3);
    lp[2 * i + 0] = __nv_bfloat162(__float2bfloat16(v.x - __bfloat162float(h0)),
                                   __float2bfloat16(v.y - __bfloat162float(h1)));
    lp[2 * i + 1] = __nv_bfloat162(__float2bfloat16(v.z - __bfloat162float(h2)),
                                   __float2bfloat16(v.w - __bfloat162float(h3)));
}

// ---------------- barrier state init ------------------------------------------
__global__ void init_barrier() {
    if (threadIdx.x == 0) { g_cnt = 0; g_gen = 0; }
}

// ---------------- mma.sync bf16x3 GEMM: C = A*B^T + bias ----------------------
// CTA tile 128x128, BK=64, 3-stage cp.async, 512 threads / 16 warps
// (warp tile 32x32 -> 4 warps per SMSP scheduler for latency hiding).
#define BKC 64
#define TILEB 16384                      // 128 rows x 128B
#define STAGEB (4 * TILEB)               // Ah, Al, Bh, Bl
#define NSTAGE 3

__global__ __launch_bounds__(512, 1)
void bgemm_mma(const __nv_bfloat16* __restrict__ Ah, const __nv_bfloat16* __restrict__ Al,
               const __nv_bfloat16* __restrict__ Bh, const __nv_bfloat16* __restrict__ Bl,
               const float* __restrict__ bias, float* __restrict__ C,
               int N, int K, const int* __restrict__ gather)
{
    extern __shared__ char smraw[];
    const uint32_t sbase = smem_u32(smraw);

    const int tid  = threadIdx.x;
    const int lane = tid & 31;
    const int wid  = tid >> 5;
    const int warp_m = wid >> 2;         // 0..3 (32 rows each)
    const int warp_n = wid & 3;          // 0..3 (32 cols each)
    const int bm = blockIdx.x * 128;
    const int bn = blockIdx.y * 128;
    const int nchunk = K / BKC;

    // load plan: 512 threads, each does 2 rows per tile (idx = q*512+tid)
    const int ch0 = tid & 7;
    int arows[2];
    uint32_t dof[2];
#pragma unroll
    for (int q = 0; q < 2; q++) {
        int row = (q * 512 + tid) >> 3;
        int am = bm + row;
        arows[q] = gather ? ((am < BB) ? gather[am] : gather[am - BB]) : am;
        dof[q] = (uint32_t)(row * 128 + ((ch0 ^ (row & 7)) << 4));
    }

    auto load_stage = [&](int c) {
        const uint32_t sb = sbase + (uint32_t)(c % NSTAGE) * STAGEB;
        const int ke0 = c * BKC + ch0 * 8;
#pragma unroll
        for (int q = 0; q < 2; q++) {
            int row = (q * 512 + tid) >> 3;
            cp16(sb + 0 * TILEB + dof[q], Ah + (size_t)arows[q] * K + ke0);
            cp16(sb + 1 * TILEB + dof[q], Al + (size_t)arows[q] * K + ke0);
            cp16(sb + 2 * TILEB + dof[q], Bh + (size_t)(bn + row) * K + ke0);
            cp16(sb + 3 * TILEB + dof[q], Bl + (size_t)(bn + row) * K + ke0);
        }
        cp_commit();
    };

    load_stage(0);
    if (nchunk > 1) load_stage(1); else cp_commit();

    float acc[2][4][4];
#pragma unroll
    for (int mt = 0; mt < 2; mt++)
#pragma unroll
        for (int nt = 0; nt < 4; nt++)
#pragma unroll
            for (int e = 0; e < 4; e++) acc[mt][nt][e] = 0.f;

    const int g = lane >> 3;
    const int r = lane & 7;

    // precompute ldmatrix smem offsets (stage-relative)
    uint32_t aoff[2][4], boff[2][4];     // [mt or np][ks]
#pragma unroll
    for (int ks = 0; ks < 4; ks++) {
#pragma unroll
        for (int mt = 0; mt < 2; mt++) {
            int row = warp_m * 32 + mt * 16 + ((g & 1) << 3) + r;
            int ch  = 2 * ks + (g >> 1);
            aoff[mt][ks] = (uint32_t)(row * 128 + ((ch ^ (row & 7)) << 4));
        }
#pragma unroll
        for (int np = 0; np < 2; np++) {
            int row = warp_n * 32 + np * 16 + ((g >> 1) << 3) + r;
            int ch  = 2 * ks + (g & 1);
            boff[np][ks] = (uint32_t)(row * 128 + ((ch ^ (row & 7)) << 4));
        }
    }

    for (int c = 0; c < nchunk; c++) {
        cp_wait1();
        __syncthreads();
        // issue next stage's copies FIRST so they overlap this chunk's MMAs
        if (c + 2 < nchunk) load_stage(c + 2);
        else cp_commit();

        const uint32_t sb = sbase + (uint32_t)(c % NSTAGE) * STAGEB;
        const uint32_t tAh = sb, tAl = sb + TILEB, tBh = sb + 2 * TILEB, tBl = sb + 3 * TILEB;

#pragma unroll
        for (int ks = 0; ks < 4; ks++) {
            uint32_t ah[2][4], al[2][4];
#pragma unroll
            for (int mt = 0; mt < 2; mt++) {
                ldm_x4(ah[mt], tAh + aoff[mt][ks]);
                ldm_x4(al[mt], tAl + aoff[mt][ks]);
            }
            uint32_t bh[4][2], bl[4][2];
#pragma unroll
            for (int np = 0; np < 2; np++) {
                uint32_t t0[4], t1[4];
                ldm_x4(t0, tBh + boff[np][ks]);
                ldm_x4(t1, tBl + boff[np][ks]);
                bh[2 * np][0] = t0[0]; bh[2 * np][1] = t0[1];
                bh[2 * np + 1][0] = t0[2]; bh[2 * np + 1][1] = t0[3];
                bl[2 * np][0] = t1[0]; bl[2 * np][1] = t1[1];
                bl[2 * np + 1][0] = t1[2]; bl[2 * np + 1][1] = t1[3];
            }
#pragma unroll
            for (int mt = 0; mt < 2; mt++)
#pragma unroll
                for (int nt = 0; nt < 4; nt++) {
                    mma16816(acc[mt][nt], ah[mt], bh[nt]);
                    mma16816(acc[mt][nt], ah[mt], bl[nt]);
                    mma16816(acc[mt][nt], al[mt], bh[nt]);
                }
        }
    }

    // epilogue
#pragma unroll
    for (int mt = 0; mt < 2; mt++) {
        int row0 = bm + warp_m * 32 + mt * 16 + (lane >> 2);
#pragma unroll
        for (int nt = 0; nt < 4; nt++) {
            int col = bn + warp_n * 32 + nt * 8 + ((lane & 3) << 1);
            float b0 = bias[col], b1 = bias[col + 1];
            float2 v0 = make_float2(acc[mt][nt][0] + b0, acc[mt][nt][1] + b1);
            float2 v1 = make_float2(acc[mt][nt][2] + b0, acc[mt][nt][3] + b1);
            *(float2*)(C + (size_t)row0 * N + col) = v0;
            *(float2*)(C + (size_t)(row0 + 8) * N + col) = v1;
        }
    }
}

// ---------------- persistent GRU recurrence (unchanged, passing) --------------
__global__ __launch_bounds__(256, 1)
void gru_persistent(const float* __restrict__ w_hh,
                    const float* __restrict__ b_hh,
                    const float* __restrict__ gx,
                    float* __restrict__ hall,
                    float* __restrict__ hidden)
{
    extern __shared__ float smem[];
    float* w_s = smem;
    float* h_s = smem + 24 * 1024;
    float* red = h_s;

    const int tid = threadIdx.x;
    const int c = blockIdx.x;

    for (int idx = tid; idx < 24 * 256; idx += 256) {
        int rr = idx >> 8;
        int kq = idx & 255;
        int uu = rr / 3, gg = rr % 3;
        int j = c * 8 + uu;
        float4 v = *(const float4*)(w_hh + ((size_t)(gg * HH + j)) * HH + kq * 4);
        *(float4*)&w_s[rr * HH + kq * 4] = v;
    }
    for (int idx = tid; idx < HH * (BB / 4); idx += 256)
        *(float4*)&h_s[idx * 4] = make_float4(0.f, 0.f, 0.f, 0.f);
    __syncthreads();

    const int warp = tid >> 5, lane = tid & 31;
    const int pair = warp & 3, khalf = warp >> 2;
    const int kg = lane >> 3, bg = lane & 7;
    const int j0 = c * 8 + pair * 2;

    float bh[2][3];
#pragma unroll
    for (int u = 0; u < 2; u++)
#pragma unroll
        for (int gg = 0; gg < 3; gg++)
            bh[u][gg] = b_hh[gg * HH + j0 + u];

    unsigned gen_base = 0;
    if (tid == 0) gen_base = ld_acq(&g_gen);

    for (int t = 0; t < TT; t++) {
        float acc[2][3][4];
#pragma unroll
        for (int u = 0; u < 2; u++)
#pragma unroll
            for (int gg = 0; gg < 3; gg++)
#pragma unroll
                for (int b = 0; b < 4; b++) acc[u][gg][b] = 0.f;

        const int kofs = khalf * 512 + kg * 4;
        const float* w0 = &w_s[(pair * 2 + 0) * 3 * HH];
        const float* w1 = &w_s[(pair * 2 + 1) * 3 * HH];

        for (int i = 0; i < 32; i++) {
            const int k = kofs + i * 16;
            float hm[4][4];
#pragma unroll
            for (int m = 0; m < 4; m++)
                *(float4*)hm[m] = *(const float4*)&h_s[(k + m) * BB + bg * 4];
            float wv[2][3][4];
#pragma unroll
            for (int gg = 0; gg < 3; gg++) {
                *(float4*)wv[0][gg] = *(const float4*)&w0[gg * HH + k];
                *(float4*)wv[1][gg] = *(const float4*)&w1[gg * HH + k];
            }
#pragma unroll
            for (int u = 0; u < 2; u++)
#pragma unroll
                for (int gg = 0; gg < 3; gg++)
#pragma unroll
                    for (int b = 0; b < 4; b++)
                        acc[u][gg][b] += hm[0][b] * wv[u][gg][0]
                                       + hm[1][b] * wv[u][gg][1]
                                       + hm[2][b] * wv[u][gg][2]
                                       + hm[3][b] * wv[u][gg][3];
        }

#pragma unroll
        for (int u = 0; u < 2; u++)
#pragma unroll
            for (int gg = 0; gg < 3; gg++)
#pragma unroll
                for (int b = 0; b < 4; b++) {
                    float v = acc[u][gg][b];
                    v += __shfl_xor_sync(0xffffffffu, v, 8);
                    v += __shfl_xor_sync(0xffffffffu, v, 16);
                    acc[u][gg][b] = v;
                }

        float hold[2][4];
        if (lane < 8) {
#pragma unroll
            for (int u = 0; u < 2; u++)
#pragma unroll
                for (int b = 0; b < 4; b++)
                    hold[u][b] = h_s[(j0 + u) * BB + bg * 4 + b];
        }
        __syncthreads();

        if (khalf == 1 && lane < 8) {
#pragma unroll
            for (int u = 0; u < 2; u++)
#pragma unroll
                for (int gg = 0; gg < 3; gg++)
#pragma unroll
                    for (int b = 0; b < 4; b++)
                        red[pair * 192 + bg * 24 + u * 12 + gg * 4 + b] = acc[u][gg][b];
        }
        __syncthreads();

        if (khalf == 0 && lane < 8) {
#pragma unroll
            for (int u = 0; u < 2; u++) {
                const int j = j0 + u;
#pragma unroll
                for (int b4 = 0; b4 < 4; b4++) {
                    const int b = bg * 4 + b4;
                    float hr = acc[u][0][b4] + red[pair * 192 + bg * 24 + u * 12 + 0 * 4 + b4] + bh[u][0];
                    float hz = acc[u][1][b4] + red[pair * 192 + bg * 24 + u * 12 + 1 * 4 + b4] + bh[u][1];
                    float hn = acc[u][2][b4] + red[pair * 192 + bg * 24 + u * 12 + 2 * 4 + b4] + bh[u][2];

                    const float* gxp = gx + ((size_t)t * BB + b) * GG;
                    float xr = gxp[j];
                    float xz = gxp[HH + j];
                    float xn = gxp[2 * HH + j];

                    float rr = 1.f / (1.f + expf(-(xr + hr)));
                    float zz = 1.f / (1.f + expf(-(xz + hz)));
                    float nn = tanhf(xn + rr * hn);
                    float hnew = (1.f - zz) * nn + zz * hold[u][b4];

                    hall[((size_t)t * BB + b) * HH + j] = hnew;
                    g_hT[t & 1][j * BB + b] = hnew;
                    if (t == TT - 1) hidden[b * HH + j] = hnew;
                }
            }
        }

        __threadfence();
        __syncthreads();
        if (tid == 0) {
            if (atomicAdd(&g_cnt, 1u) == NCTA - 1) {
                atomicExch(&g_cnt, 0u);
                __threadfence();
                atomicAdd(&g_gen, 1u);
            }
            unsigned target = gen_base + (unsigned)(t + 1);
            while ((int)(ld_acq(&g_gen) - target) < 0) {}
        }
        __syncthreads();

        if (t < TT - 1) {
            const float* hT = &g_hT[t & 1][0];
            for (int idx = tid; idx < HH * (BB / 4); idx += 256) {
                float4 v = ldcg4((const float4*)(hT + idx * 4));
                *(float4*)&h_s[idx * 4] = v;
            }
            __syncthreads();
        }
    }
}

// ---------------- launch -------------------------------------------------------
extern "C" void kernel_launch(void* const* d_in, const int* in_sizes, int n_in,
                              void* d_out, int out_size)
{
    const int*   inputs = (const int*)  d_in[0];
    const float* emb    = (const float*)d_in[3];
    const float* w_ih   = (const float*)d_in[4];
    const float* w_hh   = (const float*)d_in[5];
    const float* b_ih   = (const float*)d_in[6];
    const float* b_hh   = (const float*)d_in[7];
    const float* out_w  = (const float*)d_in[8];
    const float* out_b  = (const float*)d_in[9];

    float* logits = (float*)d_out;
    float* hidden = (float*)d_out + (size_t)MM * VV;

    float* gx;   cudaGetSymbolAddress((void**)&gx,   g_gx);
    float* hall; cudaGetSymbolAddress((void**)&hall, g_hall);
    __nv_bfloat16 *Ah, *Al, *Bh, *Bl, *Wh, *Wl;
    cudaGetSymbolAddress((void**)&Ah, g_Ah);
    cudaGetSymbolAddress((void**)&Al, g_Al);
    cudaGetSymbolAddress((void**)&Bh, g_Bh);
    cudaGetSymbolAddress((void**)&Bl, g_Bl);
    cudaGetSymbolAddress((void**)&Wh, g_Wh);
    cudaGetSymbolAddress((void**)&Wl, g_Wl);

    const int gemm_smem = NSTAGE * STAGEB;   // 196608
    cudaFuncSetAttribute(bgemm_mma, cudaFuncAttributeMaxDynamicSharedMemorySize, gemm_smem);

    // 0-2: splits of all weights
    split_bf16<<<(VV * EE / 4 + 255) / 256, 256>>>(emb, Ah, Al, VV * EE / 4);
    split_bf16<<<(GG * EE / 4 + 255) / 256, 256>>>(w_ih, Wh, Wl, GG * EE / 4);
    split_bf16<<<(VV * HH / 4 + 255) / 256, 256>>>(out_w, Bh, Bl, VV * HH / 4);

    // 3: gx = emb[x_idx] @ w_ih^T + b_ih
    {
        dim3 grid(MM / 128, GG / 128);   // (32, 24), m fastest
        bgemm_mma<<<grid, 512, gemm_smem>>>(Ah, Al, Wh, Wl, b_ih, gx, GG, EE, inputs);
    }

    // 4: barrier state init
    init_barrier<<<1, 32>>>();

    // 5: GRU recurrence (persistent)
    {
        const int smem = (24 * HH + HH * BB) * sizeof(float);
        cudaFuncSetAttribute(gru_persistent,
                             cudaFuncAttributeMaxDynamicSharedMemorySize, smem);
        gru_persistent<<<NCTA, 256, smem>>>(w_hh, b_hh, gx, hall, hidden);
    }

    // 6: split hall (reuse emb split buffers)
    split_bf16<<<(MM * HH / 4 + 255) / 256, 256>>>(hall, Ah, Al, MM * HH / 4);

    // 7: logits = hall @ out_w^T + out_b
    {
        dim3 grid(MM / 128, VV / 128);   // (32, 250), m fastest
        bgemm_mma<<<grid, 512, gemm_smem>>>(Ah, Al, Bh, Bl, out_b, logits, VV, HH, nullptr);
    }
}

// round 8
// speedup vs baseline: 1.0040x; 1.0040x over previous
#include <cuda_runtime.h>
#include <cuda_bf16.h>
#include <math.h>
#include <stdint.h>

// Problem dims
#define TT 128
#define BB 32
#define EE 512
#define HH 1024
#define VV 32000
#define GG (3 * HH)       // 3072
#define MM (TT * BB)      // 4096
#define NCTA 128

// ---------------- scratch (device globals) ----------------------------------
__device__ float g_gx[MM * GG];                // [T*B, 3H]
__device__ float g_hall[MM * HH];              // [T*B, H]
__device__ float g_hT[2][HH * BB];             // ping-pong transposed hidden
__device__ unsigned g_cnt = 0;
__device__ unsigned g_gen = 0;
// blocked + pre-swizzled bf16 hi/lo operand buffers
__device__ __nv_bfloat16 g_Xh[MM * EE];        // gathered emb rows (gx A)
__device__ __nv_bfloat16 g_Xl[MM * EE];
__device__ __nv_bfloat16 g_Wh[GG * EE];        // w_ih (gx B)
__device__ __nv_bfloat16 g_Wl[GG * EE];
__device__ __nv_bfloat16 g_Bh[VV * HH];        // out_w (logits B)
__device__ __nv_bfloat16 g_Bl[VV * HH];
__device__ __nv_bfloat16 g_Ah[MM * HH];        // hall (logits A)
__device__ __nv_bfloat16 g_Al[MM * HH];

// ---------------- helpers ----------------------------------------------------
__device__ __forceinline__ uint32_t smem_u32(const void* p) {
    uint32_t a;
    asm("{ .reg .u64 t; cvta.to.shared.u64 t, %1; cvt.u32.u64 %0, t; }"
        : "=r"(a) : "l"(p));
    return a;
}
__device__ __forceinline__ unsigned ld_acq(unsigned* p) {
    unsigned v;
    asm volatile("ld.acquire.gpu.u32 %0, [%1];" : "=r"(v) : "l"(p) : "memory");
    return v;
}
__device__ __forceinline__ float4 ldcg4(const float4* p) {
    float4 v;
    asm volatile("ld.global.cg.v4.f32 {%0,%1,%2,%3}, [%4];"
                 : "=f"(v.x), "=f"(v.y), "=f"(v.z), "=f"(v.w) : "l"(p));
    return v;
}
__device__ __forceinline__ void mbar_init(uint32_t mbar, int cnt) {
    asm volatile("mbarrier.init.shared.b64 [%0], %1;" :: "r"(mbar), "r"(cnt) : "memory");
}
__device__ __forceinline__ void mbar_expect_tx(uint32_t mbar, uint32_t bytes) {
    asm volatile("mbarrier.arrive.expect_tx.shared.b64 _, [%0], %1;"
                 :: "r"(mbar), "r"(bytes) : "memory");
}
__device__ __forceinline__ void bulk_cp(uint32_t dst, const void* src, uint32_t bytes,
                                        uint32_t mbar) {
    asm volatile(
        "cp.async.bulk.shared::cluster.global.mbarrier::complete_tx::bytes "
        "[%0], [%1], %2, [%3];"
        :: "r"(dst), "l"(src), "r"(bytes), "r"(mbar) : "memory");
}
__device__ __forceinline__ void mbar_wait(uint32_t mbar, int ph) {
    asm volatile(
        "{\n\t.reg .pred P1;\n"
        "WL%=:\n\t"
        "mbarrier.try_wait.parity.acquire.cta.shared::cta.b64 P1, [%0], %1, 0x989680;\n\t"
        "@P1 bra.uni WD%=;\n\t"
        "bra.uni WL%=;\n"
        "WD%=:\n\t}"
        :: "r"(mbar), "r"(ph) : "memory");
}
__device__ __forceinline__ void ldm_x4(uint32_t* r, uint32_t addr) {
    asm volatile("ldmatrix.sync.aligned.m8n8.x4.shared.b16 {%0,%1,%2,%3}, [%4];"
                 : "=r"(r[0]), "=r"(r[1]), "=r"(r[2]), "=r"(r[3]) : "r"(addr));
}
__device__ __forceinline__ void mma16816(float* d, const uint32_t* a, const uint32_t* b) {
    asm volatile(
        "mma.sync.aligned.m16n8k16.row.col.f32.bf16.bf16.f32 "
        "{%0,%1,%2,%3}, {%4,%5,%6,%7}, {%8,%9}, {%0,%1,%2,%3};"
        : "+f"(d[0]), "+f"(d[1]), "+f"(d[2]), "+f"(d[3])
        : "r"(a[0]), "r"(a[1]), "r"(a[2]), "r"(a[3]), "r"(b[0]), "r"(b[1]));
}

// ---------------- fp32 -> blocked/swizzled bf16 hi/lo split -------------------
// Reorders [rows,K] fp32 into (128x64)-tile-blocked bf16, each tile stored as
// the exact 16KB smem image with the XOR-16B-chunk swizzle baked in, so the
// GEMM can fetch a whole tile with ONE cp.async.bulk.
// One thread per 16B output chunk (8 elements).
__global__ __launch_bounds__(256)
void split_blk(const float* __restrict__ src, __nv_bfloat16* __restrict__ hi,
               __nv_bfloat16* __restrict__ lo, int rows, int K,
               const int* __restrict__ gather)
{
    int idx = blockIdx.x * 256 + threadIdx.x;
    int ck_per_row = K >> 3;
    if (idx >= rows * ck_per_row) return;
    int row = idx / ck_per_row;
    int ck  = idx - row * ck_per_row;          // 16B chunk within row (k = ck*8)

    int srow = row;
    if (gather) srow = (row < BB) ? gather[row] : gather[row - BB];
    const float4* s = (const float4*)(src + (size_t)srow * K + ck * 8);
    float4 v0 = s[0], v1 = s[1];

    float f[8] = {v0.x, v0.y, v0.z, v0.w, v1.x, v1.y, v1.z, v1.w};
    __nv_bfloat16 hb[8], lb[8];
#pragma unroll
    for (int i = 0; i < 8; i++) {
        hb[i] = __float2bfloat16(f[i]);
        lb[i] = __float2bfloat16(f[i] - __bfloat162float(hb[i]));
    }

    // blocked dst: tile (nb, kc), within-tile swizzled offset
    int nb = row >> 7, nr = row & 127;
    int kc = ck >> 3;                           // k / 64
    int chunk = ck & 7;                         // (k % 64) / 8
    size_t base = (((size_t)nb * (K >> 6)) + kc) << 13;    // *8192 elems (16KB)
    int dof = nr * 64 + ((chunk ^ (nr & 7)) << 3);         // elems
    *(uint4*)(hi + base + dof) = *(uint4*)hb;
    *(uint4*)(lo + base + dof) = *(uint4*)lb;
}

// ---------------- barrier state init ------------------------------------------
__global__ void init_barrier() {
    if (threadIdx.x == 0) { g_cnt = 0; g_gen = 0; }
}

// ---------------- mma.sync bf16x3 GEMM on blocked operands --------------------
// CTA tile 128x128, BK=64, 3-stage pipeline fed by cp.async.bulk (4 bulk ops
// per stage issued by ONE thread; mbarrier complete_tx) -- removes the 4096
// per-chunk LDGSTS that were starving the HMMA issue stream.
#define BKC 64
#define TILEB 16384                      // one blocked tile: 128 rows x 128B
#define STAGEB (4 * TILEB)               // Ah, Al, Bh, Bl
#define NSTAGE 3

__global__ __launch_bounds__(512, 1)
void bgemm_mma(const __nv_bfloat16* __restrict__ Ah, const __nv_bfloat16* __restrict__ Al,
               const __nv_bfloat16* __restrict__ Bh, const __nv_bfloat16* __restrict__ Bl,
               const float* __restrict__ bias, float* __restrict__ C,
               int N, int K)
{
    extern __shared__ char smraw[];
    const uint32_t base = (smem_u32(smraw) + 1023) & ~1023u;
    const uint32_t mb0   = base;               // 3 mbarriers, 8B each
    const uint32_t tiles = base + 1024;

    const int tid  = threadIdx.x;
    const int lane = tid & 31;
    const int wid  = tid >> 5;
    const int warp_m = wid >> 2;
    const int warp_n = wid & 3;
    const int nchunk = K >> 6;

    const size_t aBase = (size_t)blockIdx.x * nchunk;   // tile index row-block * kblk
    const size_t bBase = (size_t)blockIdx.y * nchunk;

    if (tid == 0) {
        mbar_init(mb0 + 0, 1);
        mbar_init(mb0 + 8, 1);
        mbar_init(mb0 + 16, 1);
        asm volatile("fence.proxy.async.shared::cta;" ::: "memory");
    }
    __syncthreads();

    auto load_stage = [&](int c) {             // tid==0 only
        const int s = c % NSTAGE;
        const uint32_t sb = tiles + (uint32_t)s * STAGEB;
        const uint32_t mb = mb0 + s * 8;
        mbar_expect_tx(mb, STAGEB);
        bulk_cp(sb + 0 * TILEB, Ah + ((aBase + c) << 13), TILEB, mb);
        bulk_cp(sb + 1 * TILEB, Al + ((aBase + c) << 13), TILEB, mb);
        bulk_cp(sb + 2 * TILEB, Bh + ((bBase + c) << 13), TILEB, mb);
        bulk_cp(sb + 3 * TILEB, Bl + ((bBase + c) << 13), TILEB, mb);
    };

    if (tid == 0) { load_stage(0); load_stage(1); }

    float acc[2][4][4];
#pragma unroll
    for (int mt = 0; mt < 2; mt++)
#pragma unroll
        for (int nt = 0; nt < 4; nt++)
#pragma unroll
            for (int e = 0; e < 4; e++) acc[mt][nt][e] = 0.f;

    const int g = lane >> 3;
    const int r = lane & 7;

    uint32_t aoff[2][4], boff[2][4];
#pragma unroll
    for (int ks = 0; ks < 4; ks++) {
#pragma unroll
        for (int mt = 0; mt < 2; mt++) {
            int row = warp_m * 32 + mt * 16 + ((g & 1) << 3) + r;
            int ch  = 2 * ks + (g >> 1);
            aoff[mt][ks] = (uint32_t)(row * 128 + ((ch ^ (row & 7)) << 4));
        }
#pragma unroll
        for (int np = 0; np < 2; np++) {
            int row = warp_n * 32 + np * 16 + ((g >> 1) << 3) + r;
            int ch  = 2 * ks + (g & 1);
            boff[np][ks] = (uint32_t)(row * 128 + ((ch ^ (row & 7)) << 4));
        }
    }

    for (int c = 0; c < nchunk; c++) {
        const int s = c % NSTAGE;
        mbar_wait(mb0 + s * 8, (c / NSTAGE) & 1);
        __syncthreads();                        // all warps done with stage (c-1)%3
        if (tid == 0 && c + 2 < nchunk) load_stage(c + 2);

        const uint32_t sb = tiles + (uint32_t)s * STAGEB;
        const uint32_t tAh = sb, tAl = sb + TILEB, tBh = sb + 2 * TILEB, tBl = sb + 3 * TILEB;

#pragma unroll
        for (int ks = 0; ks < 4; ks++) {
            uint32_t ah[2][4], al[2][4];
#pragma unroll
            for (int mt = 0; mt < 2; mt++) {
                ldm_x4(ah[mt], tAh + aoff[mt][ks]);
                ldm_x4(al[mt], tAl + aoff[mt][ks]);
            }
            uint32_t bh[4][2], bl[4][2];
#pragma unroll
            for (int np = 0; np < 2; np++) {
                uint32_t t0[4], t1[4];
                ldm_x4(t0, tBh + boff[np][ks]);
                ldm_x4(t1, tBl + boff[np][ks]);
                bh[2 * np][0] = t0[0]; bh[2 * np][1] = t0[1];
                bh[2 * np + 1][0] = t0[2]; bh[2 * np + 1][1] = t0[3];
                bl[2 * np][0] = t1[0]; bl[2 * np][1] = t1[1];
                bl[2 * np + 1][0] = t1[2]; bl[2 * np + 1][1] = t1[3];
            }
#pragma unroll
            for (int mt = 0; mt < 2; mt++)
#pragma unroll
                for (int nt = 0; nt < 4; nt++) {
                    mma16816(acc[mt][nt], ah[mt], bh[nt]);
                    mma16816(acc[mt][nt], ah[mt], bl[nt]);
                    mma16816(acc[mt][nt], al[mt], bh[nt]);
                }
        }
    }

    const int bm = blockIdx.x * 128;
    const int bn = blockIdx.y * 128;
#pragma unroll
    for (int mt = 0; mt < 2; mt++) {
        int row0 = bm + warp_m * 32 + mt * 16 + (lane >> 2);
#pragma unroll
        for (int nt = 0; nt < 4; nt++) {
            int col = bn + warp_n * 32 + nt * 8 + ((lane & 3) << 1);
            float b0 = bias[col], b1 = bias[col + 1];
            float2 v0 = make_float2(acc[mt][nt][0] + b0, acc[mt][nt][1] + b1);
            float2 v1 = make_float2(acc[mt][nt][2] + b0, acc[mt][nt][3] + b1);
            *(float2*)(C + (size_t)row0 * N + col) = v0;
            *(float2*)(C + (size_t)(row0 + 8) * N + col) = v1;
        }
    }
}

// ---------------- persistent GRU recurrence (unchanged, passing) --------------
__global__ __launch_bounds__(256, 1)
void gru_persistent(const float* __restrict__ w_hh,
                    const float* __restrict__ b_hh,
                    const float* __restrict__ gx,
                    float* __restrict__ hall,
                    float* __restrict__ hidden)
{
    extern __shared__ float smem[];
    float* w_s = smem;
    float* h_s = smem + 24 * 1024;
    float* red = h_s;

    const int tid = threadIdx.x;
    const int c = blockIdx.x;

    for (int idx = tid; idx < 24 * 256; idx += 256) {
        int rr = idx >> 8;
        int kq = idx & 255;
        int uu = rr / 3, gg = rr % 3;
        int j = c * 8 + uu;
        float4 v = *(const float4*)(w_hh + ((size_t)(gg * HH + j)) * HH + kq * 4);
        *(float4*)&w_s[rr * HH + kq * 4] = v;
    }
    for (int idx = tid; idx < HH * (BB / 4); idx += 256)
        *(float4*)&h_s[idx * 4] = make_float4(0.f, 0.f, 0.f, 0.f);
    __syncthreads();

    const int warp = tid >> 5, lane = tid & 31;
    const int pair = warp & 3, khalf = warp >> 2;
    const int kg = lane >> 3, bg = lane & 7;
    const int j0 = c * 8 + pair * 2;

    float bh[2][3];
#pragma unroll
    for (int u = 0; u < 2; u++)
#pragma unroll
        for (int gg = 0; gg < 3; gg++)
            bh[u][gg] = b_hh[gg * HH + j0 + u];

    unsigned gen_base = 0;
    if (tid == 0) gen_base = ld_acq(&g_gen);

    for (int t = 0; t < TT; t++) {
        float acc[2][3][4];
#pragma unroll
        for (int u = 0; u < 2; u++)
#pragma unroll
            for (int gg = 0; gg < 3; gg++)
#pragma unroll
                for (int b = 0; b < 4; b++) acc[u][gg][b] = 0.f;

        const int kofs = khalf * 512 + kg * 4;
        const float* w0 = &w_s[(pair * 2 + 0) * 3 * HH];
        const float* w1 = &w_s[(pair * 2 + 1) * 3 * HH];

        for (int i = 0; i < 32; i++) {
            const int k = kofs + i * 16;
            float hm[4][4];
#pragma unroll
            for (int m = 0; m < 4; m++)
                *(float4*)hm[m] = *(const float4*)&h_s[(k + m) * BB + bg * 4];
            float wv[2][3][4];
#pragma unroll
            for (int gg = 0; gg < 3; gg++) {
                *(float4*)wv[0][gg] = *(const float4*)&w0[gg * HH + k];
                *(float4*)wv[1][gg] = *(const float4*)&w1[gg * HH + k];
            }
#pragma unroll
            for (int u = 0; u < 2; u++)
#pragma unroll
                for (int gg = 0; gg < 3; gg++)
#pragma unroll
                    for (int b = 0; b < 4; b++)
                        acc[u][gg][b] += hm[0][b] * wv[u][gg][0]
                                       + hm[1][b] * wv[u][gg][1]
                                       + hm[2][b] * wv[u][gg][2]
                                       + hm[3][b] * wv[u][gg][3];
        }

#pragma unroll
        for (int u = 0; u < 2; u++)
#pragma unroll
            for (int gg = 0; gg < 3; gg++)
#pragma unroll
                for (int b = 0; b < 4; b++) {
                    float v = acc[u][gg][b];
                    v += __shfl_xor_sync(0xffffffffu, v, 8);
                    v += __shfl_xor_sync(0xffffffffu, v, 16);
                    acc[u][gg][b] = v;
                }

        float hold[2][4];
        if (lane < 8) {
#pragma unroll
            for (int u = 0; u < 2; u++)
#pragma unroll
                for (int b = 0; b < 4; b++)
                    hold[u][b] = h_s[(j0 + u) * BB + bg * 4 + b];
        }
        __syncthreads();

        if (khalf == 1 && lane < 8) {
#pragma unroll
            for (int u = 0; u < 2; u++)
#pragma unroll
                for (int gg = 0; gg < 3; gg++)
#pragma unroll
                    for (int b = 0; b < 4; b++)
                        red[pair * 192 + bg * 24 + u * 12 + gg * 4 + b] = acc[u][gg][b];
        }
        __syncthreads();

        if (khalf == 0 && lane < 8) {
#pragma unroll
            for (int u = 0; u < 2; u++) {
                const int j = j0 + u;
#pragma unroll
                for (int b4 = 0; b4 < 4; b4++) {
                    const int b = bg * 4 + b4;
                    float hr = acc[u][0][b4] + red[pair * 192 + bg * 24 + u * 12 + 0 * 4 + b4] + bh[u][0];
                    float hz = acc[u][1][b4] + red[pair * 192 + bg * 24 + u * 12 + 1 * 4 + b4] + bh[u][1];
                    float hn = acc[u][2][b4] + red[pair * 192 + bg * 24 + u * 12 + 2 * 4 + b4] + bh[u][2];

                    const float* gxp = gx + ((size_t)t * BB + b) * GG;
                    float xr = gxp[j];
                    float xz = gxp[HH + j];
                    float xn = gxp[2 * HH + j];

                    float rr = 1.f / (1.f + expf(-(xr + hr)));
                    float zz = 1.f / (1.f + expf(-(xz + hz)));
                    float nn = tanhf(xn + rr * hn);
                    float hnew = (1.f - zz) * nn + zz * hold[u][b4];

                    hall[((size_t)t * BB + b) * HH + j] = hnew;
                    g_hT[t & 1][j * BB + b] = hnew;
                    if (t == TT - 1) hidden[b * HH + j] = hnew;
                }
            }
        }

        __threadfence();
        __syncthreads();
        if (tid == 0) {
            if (atomicAdd(&g_cnt, 1u) == NCTA - 1) {
                atomicExch(&g_cnt, 0u);
                __threadfence();
                atomicAdd(&g_gen, 1u);
            }
            unsigned target = gen_base + (unsigned)(t + 1);
            while ((int)(ld_acq(&g_gen) - target) < 0) {}
        }
        __syncthreads();

        if (t < TT - 1) {
            const float* hT = &g_hT[t & 1][0];
            for (int idx = tid; idx < HH * (BB / 4); idx += 256) {
                float4 v = ldcg4((const float4*)(hT + idx * 4));
                *(float4*)&h_s[idx * 4] = v;
            }
            __syncthreads();
        }
    }
}

// ---------------- launch -------------------------------------------------------
extern "C" void kernel_launch(void* const* d_in, const int* in_sizes, int n_in,
                              void* d_out, int out_size)
{
    const int*   inputs = (const int*)  d_in[0];
    const float* emb    = (const float*)d_in[3];
    const float* w_ih   = (const float*)d_in[4];
    const float* w_hh   = (const float*)d_in[5];
    const float* b_ih   = (const float*)d_in[6];
    const float* b_hh   = (const float*)d_in[7];
    const float* out_w  = (const float*)d_in[8];
    const float* out_b  = (const float*)d_in[9];

    float* logits = (float*)d_out;
    float* hidden = (float*)d_out + (size_t)MM * VV;

    float* gx;   cudaGetSymbolAddress((void**)&gx,   g_gx);
    float* hall; cudaGetSymbolAddress((void**)&hall, g_hall);
    __nv_bfloat16 *Xh, *Xl, *Wh, *Wl, *Bh, *Bl, *Ah, *Al;
    cudaGetSymbolAddress((void**)&Xh, g_Xh);
    cudaGetSymbolAddress((void**)&Xl, g_Xl);
    cudaGetSymbolAddress((void**)&Wh, g_Wh);
    cudaGetSymbolAddress((void**)&Wl, g_Wl);
    cudaGetSymbolAddress((void**)&Bh, g_Bh);
    cudaGetSymbolAddress((void**)&Bl, g_Bl);
    cudaGetSymbolAddress((void**)&Ah, g_Ah);
    cudaGetSymbolAddress((void**)&Al, g_Al);

    const int gemm_smem = 1024 + NSTAGE * STAGEB + 1024;   // barriers + 3x64KB
    cudaFuncSetAttribute(bgemm_mma, cudaFuncAttributeMaxDynamicSharedMemorySize, gemm_smem);

    // 0-2: blocked/swizzled splits (X is gather-fused: emb[x_idx])
    split_blk<<<(MM * (EE / 8) + 255) / 256, 256>>>(emb, Xh, Xl, MM, EE, inputs);
    split_blk<<<(GG * (EE / 8) + 255) / 256, 256>>>(w_ih, Wh, Wl, GG, EE, nullptr);
    split_blk<<<(VV * (HH / 8) + 255) / 256, 256>>>(out_w, Bh, Bl, VV, HH, nullptr);

    // 3: gx = X @ w_ih^T + b_ih
    {
        dim3 grid(MM / 128, GG / 128);   // (32, 24)
        bgemm_mma<<<grid, 512, gemm_smem>>>(Xh, Xl, Wh, Wl, b_ih, gx, GG, EE);
    }

    // 4: barrier state init
    init_barrier<<<1, 32>>>();

    // 5: GRU recurrence (persistent)
    {
        const int smem = (24 * HH + HH * BB) * sizeof(float);
        cudaFuncSetAttribute(gru_persistent,
                             cudaFuncAttributeMaxDynamicSharedMemorySize, smem);
        gru_persistent<<<NCTA, 256, smem>>>(w_hh, b_hh, gx, hall, hidden);
    }

    // 6: blocked split of hall
    split_blk<<<(MM * (HH / 8) + 255) / 256, 256>>>(hall, Ah, Al, MM, HH, nullptr);

    // 7: logits = hall @ out_w^T + out_b
    {
        dim3 grid(MM / 128, VV / 128);   // (32, 250)
        bgemm_mma<<<grid, 512, gemm_smem>>>(Ah, Al, Bh, Bl, out_b, logits, VV, HH);
    }
}

// round 9
// speedup vs baseline: 1.0728x; 1.0684x over previous
#include <cuda_runtime.h>
#include <cuda_bf16.h>
#include <math.h>
#include <stdint.h>

// Problem dims
#define TT 128
#define BB 32
#define EE 512
#define HH 1024
#define VV 32000
#define GG (3 * HH)       // 3072
#define MM (TT * BB)      // 4096
#define NCTA 128

// ---------------- scratch (device globals) ----------------------------------
__device__ float g_gx[MM * GG];                // [T*B, 3H]
__device__ float g_hall[MM * HH];              // [T*B, H]
__device__ float g_hT[2][HH * BB];             // ping-pong transposed hidden
__device__ unsigned g_cnt = 0;
__device__ unsigned g_gen = 0;
// blocked + pre-swizzled bf16 hi/lo operand buffers
__device__ __nv_bfloat16 g_Xh[MM * EE];        // gathered emb rows (gx A)
__device__ __nv_bfloat16 g_Xl[MM * EE];
__device__ __nv_bfloat16 g_Wh[GG * EE];        // w_ih (gx B)
__device__ __nv_bfloat16 g_Wl[GG * EE];
__device__ __nv_bfloat16 g_Bh[VV * HH];        // out_w (logits B)
__device__ __nv_bfloat16 g_Bl[VV * HH];
__device__ __nv_bfloat16 g_Ah[MM * HH];        // hall (logits A)
__device__ __nv_bfloat16 g_Al[MM * HH];

// ---------------- helpers ----------------------------------------------------
__device__ __forceinline__ uint32_t smem_u32(const void* p) {
    uint32_t a;
    asm("{ .reg .u64 t; cvta.to.shared.u64 t, %1; cvt.u32.u64 %0, t; }"
        : "=r"(a) : "l"(p));
    return a;
}
__device__ __forceinline__ unsigned ld_acq(unsigned* p) {
    unsigned v;
    asm volatile("ld.acquire.gpu.u32 %0, [%1];" : "=r"(v) : "l"(p) : "memory");
    return v;
}
__device__ __forceinline__ float4 ldcg4(const float4* p) {
    float4 v;
    asm volatile("ld.global.cg.v4.f32 {%0,%1,%2,%3}, [%4];"
                 : "=f"(v.x), "=f"(v.y), "=f"(v.z), "=f"(v.w) : "l"(p));
    return v;
}
__device__ __forceinline__ void mbar_init(uint32_t mbar, int cnt) {
    asm volatile("mbarrier.init.shared.b64 [%0], %1;" :: "r"(mbar), "r"(cnt) : "memory");
}
__device__ __forceinline__ void mbar_expect_tx(uint32_t mbar, uint32_t bytes) {
    asm volatile("mbarrier.arrive.expect_tx.shared.b64 _, [%0], %1;"
                 :: "r"(mbar), "r"(bytes) : "memory");
}
__device__ __forceinline__ void mbar_arrive(uint32_t mbar) {
    asm volatile("mbarrier.arrive.shared.b64 _, [%0];" :: "r"(mbar) : "memory");
}
__device__ __forceinline__ void bulk_cp(uint32_t dst, const void* src, uint32_t bytes,
                                        uint32_t mbar) {
    asm volatile(
        "cp.async.bulk.shared::cluster.global.mbarrier::complete_tx::bytes "
        "[%0], [%1], %2, [%3];"
        :: "r"(dst), "l"(src), "r"(bytes), "r"(mbar) : "memory");
}
__device__ __forceinline__ void mbar_wait(uint32_t mbar, int ph) {
    asm volatile(
        "{\n\t.reg .pred P1;\n"
        "WL%=:\n\t"
        "mbarrier.try_wait.parity.acquire.cta.shared::cta.b64 P1, [%0], %1, 0x989680;\n\t"
        "@P1 bra.uni WD%=;\n\t"
        "bra.uni WL%=;\n"
        "WD%=:\n\t}"
        :: "r"(mbar), "r"(ph) : "memory");
}
__device__ __forceinline__ void ldm_x4(uint32_t* r, uint32_t addr) {
    asm volatile("ldmatrix.sync.aligned.m8n8.x4.shared.b16 {%0,%1,%2,%3}, [%4];"
                 : "=r"(r[0]), "=r"(r[1]), "=r"(r[2]), "=r"(r[3]) : "r"(addr));
}
__device__ __forceinline__ void mma16816(float* d, const uint32_t* a, const uint32_t* b) {
    asm volatile(
        "mma.sync.aligned.m16n8k16.row.col.f32.bf16.bf16.f32 "
        "{%0,%1,%2,%3}, {%4,%5,%6,%7}, {%8,%9}, {%0,%1,%2,%3};"
        : "+f"(d[0]), "+f"(d[1]), "+f"(d[2]), "+f"(d[3])
        : "r"(a[0]), "r"(a[1]), "r"(a[2]), "r"(a[3]), "r"(b[0]), "r"(b[1]));
}

// ---------------- fp32 -> blocked/swizzled bf16 hi/lo split -------------------
__global__ __launch_bounds__(256)
void split_blk(const float* __restrict__ src, __nv_bfloat16* __restrict__ hi,
               __nv_bfloat16* __restrict__ lo, int rows, int K,
               const int* __restrict__ gather)
{
    int idx = blockIdx.x * 256 + threadIdx.x;
    int ck_per_row = K >> 3;
    if (idx >= rows * ck_per_row) return;
    int row = idx / ck_per_row;
    int ck  = idx - row * ck_per_row;

    int srow = row;
    if (gather) srow = (row < BB) ? gather[row] : gather[row - BB];
    const float4* s = (const float4*)(src + (size_t)srow * K + ck * 8);
    float4 v0 = s[0], v1 = s[1];

    float f[8] = {v0.x, v0.y, v0.z, v0.w, v1.x, v1.y, v1.z, v1.w};
    __nv_bfloat16 hb[8], lb[8];
#pragma unroll
    for (int i = 0; i < 8; i++) {
        hb[i] = __float2bfloat16(f[i]);
        lb[i] = __float2bfloat16(f[i] - __bfloat162float(hb[i]));
    }

    int nb = row >> 7, nr = row & 127;
    int kc = ck >> 3;
    int chunk = ck & 7;
    size_t base = (((size_t)nb * (K >> 6)) + kc) << 13;
    int dof = nr * 64 + ((chunk ^ (nr & 7)) << 3);
    *(uint4*)(hi + base + dof) = *(uint4*)hb;
    *(uint4*)(lo + base + dof) = *(uint4*)lb;
}

// ---------------- barrier state init ------------------------------------------
__global__ void init_barrier() {
    if (threadIdx.x == 0) { g_cnt = 0; g_gen = 0; }
}

// ---------------- mma.sync bf16x3 GEMM on blocked operands --------------------
// 128x128 tile, BK=64, 3-stage ring fed by cp.async.bulk. NO __syncthreads in
// the mainloop: full[s] = tx mbarrier (stage loaded), empty[s] = 512-arrive
// mbarrier (stage consumed). Only the producer thread waits on empty; all
// compute warps free-run. MMA products interleaved (p outermost) so adjacent
// same-accumulator HMMAs are 8 instructions apart (>= result latency).
#define BKC 64
#define TILEB 16384
#define STAGEB (4 * TILEB)
#define NSTAGE 3

__global__ __launch_bounds__(512, 1)
void bgemm_mma(const __nv_bfloat16* __restrict__ Ah, const __nv_bfloat16* __restrict__ Al,
               const __nv_bfloat16* __restrict__ Bh, const __nv_bfloat16* __restrict__ Bl,
               const float* __restrict__ bias, float* __restrict__ C,
               int N, int K)
{
    extern __shared__ char smraw[];
    const uint32_t base = (smem_u32(smraw) + 1023) & ~1023u;
    const uint32_t fullb  = base;              // full[s]  at +0,+8,+16
    const uint32_t emptyb = base + 24;         // empty[s] at +24,+32,+40
    const uint32_t tiles  = base + 1024;

    const int tid  = threadIdx.x;
    const int lane = tid & 31;
    const int wid  = tid >> 5;
    const int warp_m = wid >> 2;
    const int warp_n = wid & 3;
    const int nchunk = K >> 6;

    const size_t aBase = (size_t)blockIdx.x * nchunk;
    const size_t bBase = (size_t)blockIdx.y * nchunk;

    if (tid == 0) {
#pragma unroll
        for (int s = 0; s < NSTAGE; s++) {
            mbar_init(fullb + s * 8, 1);
            mbar_init(emptyb + s * 8, 512);
        }
        asm volatile("fence.proxy.async.shared::cta;" ::: "memory");
    }
    __syncthreads();

    auto load_stage = [&](int c) {             // tid==0 only
        const int s = c % NSTAGE;
        const uint32_t sb = tiles + (uint32_t)s * STAGEB;
        const uint32_t mb = fullb + s * 8;
        mbar_expect_tx(mb, STAGEB);
        bulk_cp(sb + 0 * TILEB, Ah + ((aBase + c) << 13), TILEB, mb);
        bulk_cp(sb + 1 * TILEB, Al + ((aBase + c) << 13), TILEB, mb);
        bulk_cp(sb + 2 * TILEB, Bh + ((bBase + c) << 13), TILEB, mb);
        bulk_cp(sb + 3 * TILEB, Bl + ((bBase + c) << 13), TILEB, mb);
    };

    if (tid == 0) { load_stage(0); if (nchunk > 1) load_stage(1); }

    float acc[2][4][4];
#pragma unroll
    for (int mt = 0; mt < 2; mt++)
#pragma unroll
        for (int nt = 0; nt < 4; nt++)
#pragma unroll
            for (int e = 0; e < 4; e++) acc[mt][nt][e] = 0.f;

    const int g = lane >> 3;
    const int r = lane & 7;

    uint32_t aoff[2][4], boff[2][4];
#pragma unroll
    for (int ks = 0; ks < 4; ks++) {
#pragma unroll
        for (int mt = 0; mt < 2; mt++) {
            int row = warp_m * 32 + mt * 16 + ((g & 1) << 3) + r;
            int ch  = 2 * ks + (g >> 1);
            aoff[mt][ks] = (uint32_t)(row * 128 + ((ch ^ (row & 7)) << 4));
        }
#pragma unroll
        for (int np = 0; np < 2; np++) {
            int row = warp_n * 32 + np * 16 + ((g >> 1) << 3) + r;
            int ch  = 2 * ks + (g & 1);
            boff[np][ks] = (uint32_t)(row * 128 + ((ch ^ (row & 7)) << 4));
        }
    }

    for (int c = 0; c < nchunk; c++) {
        const int s = c % NSTAGE;
        mbar_wait(fullb + s * 8, (c / NSTAGE) & 1);

        // producer: refill stage (c+2)%3 once its previous consumer (chunk c-1)
        // has fully drained (empty arrivals from all 512 threads)
        if (tid == 0 && c + 2 < nchunk) {
            const int c2 = c + 2, s2 = c2 % NSTAGE;
            if (c2 >= NSTAGE)
                mbar_wait(emptyb + s2 * 8, ((c2 - NSTAGE - s2) / NSTAGE) & 1);
            load_stage(c2);
        }

        const uint32_t sb = tiles + (uint32_t)s * STAGEB;
        const uint32_t tAh = sb, tAl = sb + TILEB, tBh = sb + 2 * TILEB, tBl = sb + 3 * TILEB;

#pragma unroll
        for (int ks = 0; ks < 4; ks++) {
            uint32_t ah[2][4], al[2][4];
#pragma unroll
            for (int mt = 0; mt < 2; mt++) {
                ldm_x4(ah[mt], tAh + aoff[mt][ks]);
                ldm_x4(al[mt], tAl + aoff[mt][ks]);
            }
            uint32_t bh[4][2], bl[4][2];
#pragma unroll
            for (int np = 0; np < 2; np++) {
                uint32_t t0[4], t1[4];
                ldm_x4(t0, tBh + boff[np][ks]);
                ldm_x4(t1, tBl + boff[np][ks]);
                bh[2 * np][0] = t0[0]; bh[2 * np][1] = t0[1];
                bh[2 * np + 1][0] = t0[2]; bh[2 * np + 1][1] = t0[3];
                bl[2 * np][0] = t1[0]; bl[2 * np][1] = t1[1];
                bl[2 * np + 1][0] = t1[2]; bl[2 * np + 1][1] = t1[3];
            }
            // product-major order: same-acc HMMAs are 8 apart (>= HMMA latency)
#pragma unroll
            for (int mt = 0; mt < 2; mt++)
#pragma unroll
                for (int nt = 0; nt < 4; nt++)
                    mma16816(acc[mt][nt], ah[mt], bh[nt]);
#pragma unroll
            for (int mt = 0; mt < 2; mt++)
#pragma unroll
                for (int nt = 0; nt < 4; nt++)
                    mma16816(acc[mt][nt], ah[mt], bl[nt]);
#pragma unroll
            for (int mt = 0; mt < 2; mt++)
#pragma unroll
                for (int nt = 0; nt < 4; nt++)
                    mma16816(acc[mt][nt], al[mt], bh[nt]);
        }

        mbar_arrive(emptyb + s * 8);           // non-blocking consumption mark
    }

    const int bm = blockIdx.x * 128;
    const int bn = blockIdx.y * 128;
#pragma unroll
    for (int mt = 0; mt < 2; mt++) {
        int row0 = bm + warp_m * 32 + mt * 16 + (lane >> 2);
#pragma unroll
        for (int nt = 0; nt < 4; nt++) {
            int col = bn + warp_n * 32 + nt * 8 + ((lane & 3) << 1);
            float b0 = bias[col], b1 = bias[col + 1];
            float2 v0 = make_float2(acc[mt][nt][0] + b0, acc[mt][nt][1] + b1);
            float2 v1 = make_float2(acc[mt][nt][2] + b0, acc[mt][nt][3] + b1);
            *(float2*)(C + (size_t)row0 * N + col) = v0;
            *(float2*)(C + (size_t)(row0 + 8) * N + col) = v1;
        }
    }
}

// ---------------- persistent GRU recurrence (unchanged, passing) --------------
__global__ __launch_bounds__(256, 1)
void gru_persistent(const float* __restrict__ w_hh,
                    const float* __restrict__ b_hh,
                    const float* __restrict__ gx,
                    float* __restrict__ hall,
                    float* __restrict__ hidden)
{
    extern __shared__ float smem[];
    float* w_s = smem;
    float* h_s = smem + 24 * 1024;
    float* red = h_s;

    const int tid = threadIdx.x;
    const int c = blockIdx.x;

    for (int idx = tid; idx < 24 * 256; idx += 256) {
        int rr = idx >> 8;
        int kq = idx & 255;
        int uu = rr / 3, gg = rr % 3;
        int j = c * 8 + uu;
        float4 v = *(const float4*)(w_hh + ((size_t)(gg * HH + j)) * HH + kq * 4);
        *(float4*)&w_s[rr * HH + kq * 4] = v;
    }
    for (int idx = tid; idx < HH * (BB / 4); idx += 256)
        *(float4*)&h_s[idx * 4] = make_float4(0.f, 0.f, 0.f, 0.f);
    __syncthreads();

    const int warp = tid >> 5, lane = tid & 31;
    const int pair = warp & 3, khalf = warp >> 2;
    const int kg = lane >> 3, bg = lane & 7;
    const int j0 = c * 8 + pair * 2;

    float bh[2][3];
#pragma unroll
    for (int u = 0; u < 2; u++)
#pragma unroll
        for (int gg = 0; gg < 3; gg++)
            bh[u][gg] = b_hh[gg * HH + j0 + u];

    unsigned gen_base = 0;
    if (tid == 0) gen_base = ld_acq(&g_gen);

    for (int t = 0; t < TT; t++) {
        float acc[2][3][4];
#pragma unroll
        for (int u = 0; u < 2; u++)
#pragma unroll
            for (int gg = 0; gg < 3; gg++)
#pragma unroll
                for (int b = 0; b < 4; b++) acc[u][gg][b] = 0.f;

        const int kofs = khalf * 512 + kg * 4;
        const float* w0 = &w_s[(pair * 2 + 0) * 3 * HH];
        const float* w1 = &w_s[(pair * 2 + 1) * 3 * HH];

        for (int i = 0; i < 32; i++) {
            const int k = kofs + i * 16;
            float hm[4][4];
#pragma unroll
            for (int m = 0; m < 4; m++)
                *(float4*)hm[m] = *(const float4*)&h_s[(k + m) * BB + bg * 4];
            float wv[2][3][4];
#pragma unroll
            for (int gg = 0; gg < 3; gg++) {
                *(float4*)wv[0][gg] = *(const float4*)&w0[gg * HH + k];
                *(float4*)wv[1][gg] = *(const float4*)&w1[gg * HH + k];
            }
#pragma unroll
            for (int u = 0; u < 2; u++)
#pragma unroll
                for (int gg = 0; gg < 3; gg++)
#pragma unroll
                    for (int b = 0; b < 4; b++)
                        acc[u][gg][b] += hm[0][b] * wv[u][gg][0]
                                       + hm[1][b] * wv[u][gg][1]
                                       + hm[2][b] * wv[u][gg][2]
                                       + hm[3][b] * wv[u][gg][3];
        }

#pragma unroll
        for (int u = 0; u < 2; u++)
#pragma unroll
            for (int gg = 0; gg < 3; gg++)
#pragma unroll
                for (int b = 0; b < 4; b++) {
                    float v = acc[u][gg][b];
                    v += __shfl_xor_sync(0xffffffffu, v, 8);
                    v += __shfl_xor_sync(0xffffffffu, v, 16);
                    acc[u][gg][b] = v;
                }

        float hold[2][4];
        if (lane < 8) {
#pragma unroll
            for (int u = 0; u < 2; u++)
#pragma unroll
                for (int b = 0; b < 4; b++)
                    hold[u][b] = h_s[(j0 + u) * BB + bg * 4 + b];
        }
        __syncthreads();

        if (khalf == 1 && lane < 8) {
#pragma unroll
            for (int u = 0; u < 2; u++)
#pragma unroll
                for (int gg = 0; gg < 3; gg++)
#pragma unroll
                    for (int b = 0; b < 4; b++)
                        red[pair * 192 + bg * 24 + u * 12 + gg * 4 + b] = acc[u][gg][b];
        }
        __syncthreads();

        if (khalf == 0 && lane < 8) {
#pragma unroll
            for (int u = 0; u < 2; u++) {
                const int j = j0 + u;
#pragma unroll
                for (int b4 = 0; b4 < 4; b4++) {
                    const int b = bg * 4 + b4;
                    float hr = acc[u][0][b4] + red[pair * 192 + bg * 24 + u * 12 + 0 * 4 + b4] + bh[u][0];
                    float hz = acc[u][1][b4] + red[pair * 192 + bg * 24 + u * 12 + 1 * 4 + b4] + bh[u][1];
                    float hn = acc[u][2][b4] + red[pair * 192 + bg * 24 + u * 12 + 2 * 4 + b4] + bh[u][2];

                    const float* gxp = gx + ((size_t)t * BB + b) * GG;
                    float xr = gxp[j];
                    float xz = gxp[HH + j];
                    float xn = gxp[2 * HH + j];

                    float rr = 1.f / (1.f + expf(-(xr + hr)));
                    float zz = 1.f / (1.f + expf(-(xz + hz)));
                    float nn = tanhf(xn + rr * hn);
                    float hnew = (1.f - zz) * nn + zz * hold[u][b4];

                    hall[((size_t)t * BB + b) * HH + j] = hnew;
                    g_hT[t & 1][j * BB + b] = hnew;
                    if (t == TT - 1) hidden[b * HH + j] = hnew;
                }
            }
        }

        __threadfence();
        __syncthreads();
        if (tid == 0) {
            if (atomicAdd(&g_cnt, 1u) == NCTA - 1) {
                atomicExch(&g_cnt, 0u);
                __threadfence();
                atomicAdd(&g_gen, 1u);
            }
            unsigned target = gen_base + (unsigned)(t + 1);
            while ((int)(ld_acq(&g_gen) - target) < 0) {}
        }
        __syncthreads();

        if (t < TT - 1) {
            const float* hT = &g_hT[t & 1][0];
            for (int idx = tid; idx < HH * (BB / 4); idx += 256) {
                float4 v = ldcg4((const float4*)(hT + idx * 4));
                *(float4*)&h_s[idx * 4] = v;
            }
            __syncthreads();
        }
    }
}

// ---------------- launch -------------------------------------------------------
extern "C" void kernel_launch(void* const* d_in, const int* in_sizes, int n_in,
                              void* d_out, int out_size)
{
    const int*   inputs = (const int*)  d_in[0];
    const float* emb    = (const float*)d_in[3];
    const float* w_ih   = (const float*)d_in[4];
    const float* w_hh   = (const float*)d_in[5];
    const float* b_ih   = (const float*)d_in[6];
    const float* b_hh   = (const float*)d_in[7];
    const float* out_w  = (const float*)d_in[8];
    const float* out_b  = (const float*)d_in[9];

    float* logits = (float*)d_out;
    float* hidden = (float*)d_out + (size_t)MM * VV;

    float* gx;   cudaGetSymbolAddress((void**)&gx,   g_gx);
    float* hall; cudaGetSymbolAddress((void**)&hall, g_hall);
    __nv_bfloat16 *Xh, *Xl, *Wh, *Wl, *Bh, *Bl, *Ah, *Al;
    cudaGetSymbolAddress((void**)&Xh, g_Xh);
    cudaGetSymbolAddress((void**)&Xl, g_Xl);
    cudaGetSymbolAddress((void**)&Wh, g_Wh);
    cudaGetSymbolAddress((void**)&Wl, g_Wl);
    cudaGetSymbolAddress((void**)&Bh, g_Bh);
    cudaGetSymbolAddress((void**)&Bl, g_Bl);
    cudaGetSymbolAddress((void**)&Ah, g_Ah);
    cudaGetSymbolAddress((void**)&Al, g_Al);

    const int gemm_smem = 1024 + NSTAGE * STAGEB + 1024;
    cudaFuncSetAttribute(bgemm_mma, cudaFuncAttributeMaxDynamicSharedMemorySize, gemm_smem);

    split_blk<<<(MM * (EE / 8) + 255) / 256, 256>>>(emb, Xh, Xl, MM, EE, inputs);
    split_blk<<<(GG * (EE / 8) + 255) / 256, 256>>>(w_ih, Wh, Wl, GG, EE, nullptr);
    split_blk<<<(VV * (HH / 8) + 255) / 256, 256>>>(out_w, Bh, Bl, VV, HH, nullptr);

    // gx = X @ w_ih^T + b_ih
    {
        dim3 grid(MM / 128, GG / 128);
        bgemm_mma<<<grid, 512, gemm_smem>>>(Xh, Xl, Wh, Wl, b_ih, gx, GG, EE);
    }

    init_barrier<<<1, 32>>>();

    // GRU recurrence (persistent)
    {
        const int smem = (24 * HH + HH * BB) * sizeof(float);
        cudaFuncSetAttribute(gru_persistent,
                             cudaFuncAttributeMaxDynamicSharedMemorySize, smem);
        gru_persistent<<<NCTA, 256, smem>>>(w_hh, b_hh, gx, hall, hidden);
    }

    split_blk<<<(MM * (HH / 8) + 255) / 256, 256>>>(hall, Ah, Al, MM, HH, nullptr);

    // logits = hall @ out_w^T + out_b
    {
        dim3 grid(MM / 128, VV / 128);
        bgemm_mma<<<grid, 512, gemm_smem>>>(Ah, Al, Bh, Bl, out_b, logits, VV, HH);
    }
}

// round 10
// speedup vs baseline: 1.4779x; 1.3776x over previous
#include <cuda_runtime.h>
#include <cuda_bf16.h>
#include <cuda_fp16.h>
#include <math.h>
#include <stdint.h>

// Problem dims
#define TT 128
#define BB 32
#define EE 512
#define HH 1024
#define VV 32000
#define GG (3 * HH)       // 3072
#define MM (TT * BB)      // 4096
#define NCTA 128

// ---------------- scratch (device globals) ----------------------------------
__device__ float g_gx[MM * GG];
__device__ float g_hall[MM * HH];
__device__ float g_hT[2][HH * BB];
__device__ unsigned g_cnt = 0;
__device__ unsigned g_gen = 0;
__device__ __nv_bfloat16 g_Xh[MM * EE];        // gathered emb rows (gx A, bf16 hi)
__device__ __nv_bfloat16 g_Xl[MM * EE];
__device__ __nv_bfloat16 g_Wh[GG * EE];        // w_ih (gx B)
__device__ __nv_bfloat16 g_Wl[GG * EE];
__device__ __half g_Fw[VV * HH];               // out_w fp16 (logits B)
__device__ __half g_Fa[MM * HH];               // hall fp16 (logits A)

// ---------------- helpers ----------------------------------------------------
__device__ __forceinline__ uint32_t smem_u32(const void* p) {
    uint32_t a;
    asm("{ .reg .u64 t; cvta.to.shared.u64 t, %1; cvt.u32.u64 %0, t; }"
        : "=r"(a) : "l"(p));
    return a;
}
__device__ __forceinline__ unsigned ld_acq(unsigned* p) {
    unsigned v;
    asm volatile("ld.acquire.gpu.u32 %0, [%1];" : "=r"(v) : "l"(p) : "memory");
    return v;
}
__device__ __forceinline__ float4 ldcg4(const float4* p) {
    float4 v;
    asm volatile("ld.global.cg.v4.f32 {%0,%1,%2,%3}, [%4];"
                 : "=f"(v.x), "=f"(v.y), "=f"(v.z), "=f"(v.w) : "l"(p));
    return v;
}
__device__ __forceinline__ void mbar_init(uint32_t mbar, int cnt) {
    asm volatile("mbarrier.init.shared.b64 [%0], %1;" :: "r"(mbar), "r"(cnt) : "memory");
}
__device__ __forceinline__ void mbar_expect_tx(uint32_t mbar, uint32_t bytes) {
    asm volatile("mbarrier.arrive.expect_tx.shared.b64 _, [%0], %1;"
                 :: "r"(mbar), "r"(bytes) : "memory");
}
__device__ __forceinline__ void mbar_arrive(uint32_t mbar) {
    asm volatile("mbarrier.arrive.shared.b64 _, [%0];" :: "r"(mbar) : "memory");
}
__device__ __forceinline__ void bulk_cp(uint32_t dst, const void* src, uint32_t bytes,
                                        uint32_t mbar) {
    asm volatile(
        "cp.async.bulk.shared::cluster.global.mbarrier::complete_tx::bytes "
        "[%0], [%1], %2, [%3];"
        :: "r"(dst), "l"(src), "r"(bytes), "r"(mbar) : "memory");
}
__device__ __forceinline__ void mbar_wait(uint32_t mbar, int ph) {
    asm volatile(
        "{\n\t.reg .pred P1;\n"
        "WL%=:\n\t"
        "mbarrier.try_wait.parity.acquire.cta.shared::cta.b64 P1, [%0], %1, 0x989680;\n\t"
        "@P1 bra.uni WD%=;\n\t"
        "bra.uni WL%=;\n"
        "WD%=:\n\t}"
        :: "r"(mbar), "r"(ph) : "memory");
}
__device__ __forceinline__ void ldm_x4(uint32_t* r, uint32_t addr) {
    asm volatile("ldmatrix.sync.aligned.m8n8.x4.shared.b16 {%0,%1,%2,%3}, [%4];"
                 : "=r"(r[0]), "=r"(r[1]), "=r"(r[2]), "=r"(r[3]) : "r"(addr));
}
__device__ __forceinline__ void mma16816(float* d, const uint32_t* a, const uint32_t* b) {
    asm volatile(
        "mma.sync.aligned.m16n8k16.row.col.f32.bf16.bf16.f32 "
        "{%0,%1,%2,%3}, {%4,%5,%6,%7}, {%8,%9}, {%0,%1,%2,%3};"
        : "+f"(d[0]), "+f"(d[1]), "+f"(d[2]), "+f"(d[3])
        : "r"(a[0]), "r"(a[1]), "r"(a[2]), "r"(a[3]), "r"(b[0]), "r"(b[1]));
}
__device__ __forceinline__ void mma16816h(float* d, const uint32_t* a, const uint32_t* b) {
    asm volatile(
        "mma.sync.aligned.m16n8k16.row.col.f32.f16.f16.f32 "
        "{%0,%1,%2,%3}, {%4,%5,%6,%7}, {%8,%9}, {%0,%1,%2,%3};"
        : "+f"(d[0]), "+f"(d[1]), "+f"(d[2]), "+f"(d[3])
        : "r"(a[0]), "r"(a[1]), "r"(a[2]), "r"(a[3]), "r"(b[0]), "r"(b[1]));
}

// ---------------- fp32 -> blocked/swizzled bf16 hi/lo split -------------------
__global__ __launch_bounds__(256)
void split_blk(const float* __restrict__ src, __nv_bfloat16* __restrict__ hi,
               __nv_bfloat16* __restrict__ lo, int rows, int K,
               const int* __restrict__ gather)
{
    int idx = blockIdx.x * 256 + threadIdx.x;
    int ck_per_row = K >> 3;
    if (idx >= rows * ck_per_row) return;
    int row = idx / ck_per_row;
    int ck  = idx - row * ck_per_row;

    int srow = row;
    if (gather) srow = (row < BB) ? gather[row] : gather[row - BB];
    const float4* s = (const float4*)(src + (size_t)srow * K + ck * 8);
    float4 v0 = s[0], v1 = s[1];

    float f[8] = {v0.x, v0.y, v0.z, v0.w, v1.x, v1.y, v1.z, v1.w};
    __nv_bfloat16 hb[8], lb[8];
#pragma unroll
    for (int i = 0; i < 8; i++) {
        hb[i] = __float2bfloat16(f[i]);
        lb[i] = __float2bfloat16(f[i] - __bfloat162float(hb[i]));
    }

    int nb = row >> 7, nr = row & 127;
    int kc = ck >> 3;
    int chunk = ck & 7;
    size_t base = (((size_t)nb * (K >> 6)) + kc) << 13;
    int dof = nr * 64 + ((chunk ^ (nr & 7)) << 3);
    *(uint4*)(hi + base + dof) = *(uint4*)hb;
    *(uint4*)(lo + base + dof) = *(uint4*)lb;
}

// ---------------- fp32 -> blocked/swizzled fp16 (single) ----------------------
__global__ __launch_bounds__(256)
void split_f16(const float* __restrict__ src, __half* __restrict__ dst,
               int rows, int K)
{
    int idx = blockIdx.x * 256 + threadIdx.x;
    int ck_per_row = K >> 3;
    if (idx >= rows * ck_per_row) return;
    int row = idx / ck_per_row;
    int ck  = idx - row * ck_per_row;

    const float4* s = (const float4*)(src + (size_t)row * K + ck * 8);
    float4 v0 = s[0], v1 = s[1];
    float f[8] = {v0.x, v0.y, v0.z, v0.w, v1.x, v1.y, v1.z, v1.w};
    __half h[8];
#pragma unroll
    for (int i = 0; i < 8; i++) h[i] = __float2half(f[i]);

    int nb = row >> 7, nr = row & 127;
    int kc = ck >> 3;
    int chunk = ck & 7;
    size_t base = (((size_t)nb * (K >> 6)) + kc) << 13;
    int dof = nr * 64 + ((chunk ^ (nr & 7)) << 3);
    *(uint4*)(dst + base + dof) = *(uint4*)h;
}

// ---------------- barrier state init ------------------------------------------
__global__ void init_barrier() {
    if (threadIdx.x == 0) { g_cnt = 0; g_gen = 0; }
}

// ---------------- bf16x3 GEMM (gx only; proven) --------------------------------
#define TILEB 16384
#define STAGEB (4 * TILEB)
#define NSTAGE 3

__global__ __launch_bounds__(512, 1)
void bgemm_mma(const __nv_bfloat16* __restrict__ Ah, const __nv_bfloat16* __restrict__ Al,
               const __nv_bfloat16* __restrict__ Bh, const __nv_bfloat16* __restrict__ Bl,
               const float* __restrict__ bias, float* __restrict__ C,
               int N, int K)
{
    extern __shared__ char smraw[];
    const uint32_t base = (smem_u32(smraw) + 1023) & ~1023u;
    const uint32_t fullb  = base;
    const uint32_t emptyb = base + 24;
    const uint32_t tiles  = base + 1024;

    const int tid  = threadIdx.x;
    const int lane = tid & 31;
    const int wid  = tid >> 5;
    const int warp_m = wid >> 2;
    const int warp_n = wid & 3;
    const int nchunk = K >> 6;

    const size_t aBase = (size_t)blockIdx.x * nchunk;
    const size_t bBase = (size_t)blockIdx.y * nchunk;

    if (tid == 0) {
#pragma unroll
        for (int s = 0; s < NSTAGE; s++) {
            mbar_init(fullb + s * 8, 1);
            mbar_init(emptyb + s * 8, 512);
        }
        asm volatile("fence.proxy.async.shared::cta;" ::: "memory");
    }
    __syncthreads();

    auto load_stage = [&](int c) {
        const int s = c % NSTAGE;
        const uint32_t sb = tiles + (uint32_t)s * STAGEB;
        const uint32_t mb = fullb + s * 8;
        mbar_expect_tx(mb, STAGEB);
        bulk_cp(sb + 0 * TILEB, Ah + ((aBase + c) << 13), TILEB, mb);
        bulk_cp(sb + 1 * TILEB, Al + ((aBase + c) << 13), TILEB, mb);
        bulk_cp(sb + 2 * TILEB, Bh + ((bBase + c) << 13), TILEB, mb);
        bulk_cp(sb + 3 * TILEB, Bl + ((bBase + c) << 13), TILEB, mb);
    };

    if (tid == 0) { load_stage(0); if (nchunk > 1) load_stage(1); }

    float acc[2][4][4];
#pragma unroll
    for (int mt = 0; mt < 2; mt++)
#pragma unroll
        for (int nt = 0; nt < 4; nt++)
#pragma unroll
            for (int e = 0; e < 4; e++) acc[mt][nt][e] = 0.f;

    const int g = lane >> 3;
    const int r = lane & 7;

    uint32_t aoff[2][4], boff[2][4];
#pragma unroll
    for (int ks = 0; ks < 4; ks++) {
#pragma unroll
        for (int mt = 0; mt < 2; mt++) {
            int row = warp_m * 32 + mt * 16 + ((g & 1) << 3) + r;
            int ch  = 2 * ks + (g >> 1);
            aoff[mt][ks] = (uint32_t)(row * 128 + ((ch ^ (row & 7)) << 4));
        }
#pragma unroll
        for (int np = 0; np < 2; np++) {
            int row = warp_n * 32 + np * 16 + ((g >> 1) << 3) + r;
            int ch  = 2 * ks + (g & 1);
            boff[np][ks] = (uint32_t)(row * 128 + ((ch ^ (row & 7)) << 4));
        }
    }

    for (int c = 0; c < nchunk; c++) {
        const int s = c % NSTAGE;
        mbar_wait(fullb + s * 8, (c / NSTAGE) & 1);

        if (tid == 0 && c + 2 < nchunk) {
            const int c2 = c + 2, s2 = c2 % NSTAGE;
            if (c2 >= NSTAGE)
                mbar_wait(emptyb + s2 * 8, ((c2 - NSTAGE - s2) / NSTAGE) & 1);
            load_stage(c2);
        }

        const uint32_t sb = tiles + (uint32_t)s * STAGEB;
        const uint32_t tAh = sb, tAl = sb + TILEB, tBh = sb + 2 * TILEB, tBl = sb + 3 * TILEB;

#pragma unroll
        for (int ks = 0; ks < 4; ks++) {
            uint32_t ah[2][4], al[2][4];
#pragma unroll
            for (int mt = 0; mt < 2; mt++) {
                ldm_x4(ah[mt], tAh + aoff[mt][ks]);
                ldm_x4(al[mt], tAl + aoff[mt][ks]);
            }
            uint32_t bh[4][2], bl[4][2];
#pragma unroll
            for (int np = 0; np < 2; np++) {
                uint32_t t0[4], t1[4];
                ldm_x4(t0, tBh + boff[np][ks]);
                ldm_x4(t1, tBl + boff[np][ks]);
                bh[2 * np][0] = t0[0]; bh[2 * np][1] = t0[1];
                bh[2 * np + 1][0] = t0[2]; bh[2 * np + 1][1] = t0[3];
                bl[2 * np][0] = t1[0]; bl[2 * np][1] = t1[1];
                bl[2 * np + 1][0] = t1[2]; bl[2 * np + 1][1] = t1[3];
            }
#pragma unroll
            for (int mt = 0; mt < 2; mt++)
#pragma unroll
                for (int nt = 0; nt < 4; nt++)
                    mma16816(acc[mt][nt], ah[mt], bh[nt]);
#pragma unroll
            for (int mt = 0; mt < 2; mt++)
#pragma unroll
                for (int nt = 0; nt < 4; nt++)
                    mma16816(acc[mt][nt], ah[mt], bl[nt]);
#pragma unroll
            for (int mt = 0; mt < 2; mt++)
#pragma unroll
                for (int nt = 0; nt < 4; nt++)
                    mma16816(acc[mt][nt], al[mt], bh[nt]);
        }

        mbar_arrive(emptyb + s * 8);
    }

    const int bm = blockIdx.x * 128;
    const int bn = blockIdx.y * 128;
#pragma unroll
    for (int mt = 0; mt < 2; mt++) {
        int row0 = bm + warp_m * 32 + mt * 16 + (lane >> 2);
#pragma unroll
        for (int nt = 0; nt < 4; nt++) {
            int col = bn + warp_n * 32 + nt * 8 + ((lane & 3) << 1);
            float b0 = bias[col], b1 = bias[col + 1];
            float2 v0 = make_float2(acc[mt][nt][0] + b0, acc[mt][nt][1] + b1);
            float2 v1 = make_float2(acc[mt][nt][2] + b0, acc[mt][nt][3] + b1);
            *(float2*)(C + (size_t)row0 * N + col) = v0;
            *(float2*)(C + (size_t)(row0 + 8) * N + col) = v1;
        }
    }
}

// ---------------- fp16 single-product GEMM (logits) ----------------------------
// 1/3 the MMA work of bf16x3. 2 tiles/stage (A,B), 4-stage ring, register
// fragment double-buffering inside each chunk.
#define STAGEH (2 * TILEB)               // 32 KB
#define NSTAGEH 4

__global__ __launch_bounds__(512, 1)
void hgemm_mma(const __half* __restrict__ A, const __half* __restrict__ B,
               const float* __restrict__ bias, float* __restrict__ C,
               int N, int K)
{
    extern __shared__ char smraw[];
    const uint32_t base = (smem_u32(smraw) + 1023) & ~1023u;
    const uint32_t fullb  = base;              // 4 x 8B
    const uint32_t emptyb = base + 32;         // 4 x 8B
    const uint32_t tiles  = base + 1024;

    const int tid  = threadIdx.x;
    const int lane = tid & 31;
    const int wid  = tid >> 5;
    const int warp_m = wid >> 2;
    const int warp_n = wid & 3;
    const int nchunk = K >> 6;

    const size_t aBase = (size_t)blockIdx.x * nchunk;
    const size_t bBase = (size_t)blockIdx.y * nchunk;

    if (tid == 0) {
#pragma unroll
        for (int s = 0; s < NSTAGEH; s++) {
            mbar_init(fullb + s * 8, 1);
            mbar_init(emptyb + s * 8, 512);
        }
        asm volatile("fence.proxy.async.shared::cta;" ::: "memory");
    }
    __syncthreads();

    auto load_stage = [&](int c) {
        const int s = c % NSTAGEH;
        const uint32_t sb = tiles + (uint32_t)s * STAGEH;
        const uint32_t mb = fullb + s * 8;
        mbar_expect_tx(mb, STAGEH);
        bulk_cp(sb + 0 * TILEB, A + ((aBase + c) << 13), TILEB, mb);
        bulk_cp(sb + 1 * TILEB, B + ((bBase + c) << 13), TILEB, mb);
    };

    if (tid == 0) {
        load_stage(0);
        if (nchunk > 1) load_stage(1);
        if (nchunk > 2) load_stage(2);
    }

    float acc[2][4][4];
#pragma unroll
    for (int mt = 0; mt < 2; mt++)
#pragma unroll
        for (int nt = 0; nt < 4; nt++)
#pragma unroll
            for (int e = 0; e < 4; e++) acc[mt][nt][e] = 0.f;

    const int g = lane >> 3;
    const int r = lane & 7;

    uint32_t aoff[2][4], boff[2][4];
#pragma unroll
    for (int ks = 0; ks < 4; ks++) {
#pragma unroll
        for (int mt = 0; mt < 2; mt++) {
            int row = warp_m * 32 + mt * 16 + ((g & 1) << 3) + r;
            int ch  = 2 * ks + (g >> 1);
            aoff[mt][ks] = (uint32_t)(row * 128 + ((ch ^ (row & 7)) << 4));
        }
#pragma unroll
        for (int np = 0; np < 2; np++) {
            int row = warp_n * 32 + np * 16 + ((g >> 1) << 3) + r;
            int ch  = 2 * ks + (g & 1);
            boff[np][ks] = (uint32_t)(row * 128 + ((ch ^ (row & 7)) << 4));
        }
    }

    for (int c = 0; c < nchunk; c++) {
        const int s = c % NSTAGEH;
        mbar_wait(fullb + s * 8, (c / NSTAGEH) & 1);

        if (tid == 0 && c + 3 < nchunk) {
            const int c2 = c + 3, s2 = c2 % NSTAGEH;
            if (c2 >= NSTAGEH)
                mbar_wait(emptyb + s2 * 8, ((c2 - NSTAGEH - s2) / NSTAGEH) & 1);
            load_stage(c2);
        }

        const uint32_t sb = tiles + (uint32_t)s * STAGEH;
        const uint32_t tA = sb, tB = sb + TILEB;

        // register double-buffered fragments
        uint32_t aF[2][2][4], bF[2][2][4];
        auto ld_frags = [&](int ks, int buf) {
#pragma unroll
            for (int mt = 0; mt < 2; mt++)
                ldm_x4(aF[buf][mt], tA + aoff[mt][ks]);
#pragma unroll
            for (int np = 0; np < 2; np++)
                ldm_x4(bF[buf][np], tB + boff[np][ks]);
        };
        auto do_mma = [&](int buf) {
#pragma unroll
            for (int mt = 0; mt < 2; mt++)
#pragma unroll
                for (int nt = 0; nt < 4; nt++)
                    mma16816h(acc[mt][nt], aF[buf][mt], &bF[buf][nt >> 1][(nt & 1) * 2]);
        };

        ld_frags(0, 0);
        int buf = 0;
#pragma unroll
        for (int ks = 0; ks < 4; ks++) {
            if (ks < 3) ld_frags(ks + 1, buf ^ 1);
            do_mma(buf);
            buf ^= 1;
        }

        mbar_arrive(emptyb + s * 8);
    }

    const int bm = blockIdx.x * 128;
    const int bn = blockIdx.y * 128;
#pragma unroll
    for (int mt = 0; mt < 2; mt++) {
        int row0 = bm + warp_m * 32 + mt * 16 + (lane >> 2);
#pragma unroll
        for (int nt = 0; nt < 4; nt++) {
            int col = bn + warp_n * 32 + nt * 8 + ((lane & 3) << 1);
            float b0 = bias[col], b1 = bias[col + 1];
            float2 v0 = make_float2(acc[mt][nt][0] + b0, acc[mt][nt][1] + b1);
            float2 v1 = make_float2(acc[mt][nt][2] + b0, acc[mt][nt][3] + b1);
            *(float2*)(C + (size_t)row0 * N + col) = v0;
            *(float2*)(C + (size_t)(row0 + 8) * N + col) = v1;
        }
    }
}

// ---------------- persistent GRU recurrence (unchanged, passing) --------------
__global__ __launch_bounds__(256, 1)
void gru_persistent(const float* __restrict__ w_hh,
                    const float* __restrict__ b_hh,
                    const float* __restrict__ gx,
                    float* __restrict__ hall,
                    float* __restrict__ hidden)
{
    extern __shared__ float smem[];
    float* w_s = smem;
    float* h_s = smem + 24 * 1024;
    float* red = h_s;

    const int tid = threadIdx.x;
    const int c = blockIdx.x;

    for (int idx = tid; idx < 24 * 256; idx += 256) {
        int rr = idx >> 8;
        int kq = idx & 255;
        int uu = rr / 3, gg = rr % 3;
        int j = c * 8 + uu;
        float4 v = *(const float4*)(w_hh + ((size_t)(gg * HH + j)) * HH + kq * 4);
        *(float4*)&w_s[rr * HH + kq * 4] = v;
    }
    for (int idx = tid; idx < HH * (BB / 4); idx += 256)
        *(float4*)&h_s[idx * 4] = make_float4(0.f, 0.f, 0.f, 0.f);
    __syncthreads();

    const int warp = tid >> 5, lane = tid & 31;
    const int pair = warp & 3, khalf = warp >> 2;
    const int kg = lane >> 3, bg = lane & 7;
    const int j0 = c * 8 + pair * 2;

    float bh[2][3];
#pragma unroll
    for (int u = 0; u < 2; u++)
#pragma unroll
        for (int gg = 0; gg < 3; gg++)
            bh[u][gg] = b_hh[gg * HH + j0 + u];

    unsigned gen_base = 0;
    if (tid == 0) gen_base = ld_acq(&g_gen);

    for (int t = 0; t < TT; t++) {
        float acc[2][3][4];
#pragma unroll
        for (int u = 0; u < 2; u++)
#pragma unroll
            for (int gg = 0; gg < 3; gg++)
#pragma unroll
                for (int b = 0; b < 4; b++) acc[u][gg][b] = 0.f;

        const int kofs = khalf * 512 + kg * 4;
        const float* w0 = &w_s[(pair * 2 + 0) * 3 * HH];
        const float* w1 = &w_s[(pair * 2 + 1) * 3 * HH];

        for (int i = 0; i < 32; i++) {
            const int k = kofs + i * 16;
            float hm[4][4];
#pragma unroll
            for (int m = 0; m < 4; m++)
                *(float4*)hm[m] = *(const float4*)&h_s[(k + m) * BB + bg * 4];
            float wv[2][3][4];
#pragma unroll
            for (int gg = 0; gg < 3; gg++) {
                *(float4*)wv[0][gg] = *(const float4*)&w0[gg * HH + k];
                *(float4*)wv[1][gg] = *(const float4*)&w1[gg * HH + k];
            }
#pragma unroll
            for (int u = 0; u < 2; u++)
#pragma unroll
                for (int gg = 0; gg < 3; gg++)
#pragma unroll
                    for (int b = 0; b < 4; b++)
                        acc[u][gg][b] += hm[0][b] * wv[u][gg][0]
                                       + hm[1][b] * wv[u][gg][1]
                                       + hm[2][b] * wv[u][gg][2]
                                       + hm[3][b] * wv[u][gg][3];
        }

#pragma unroll
        for (int u = 0; u < 2; u++)
#pragma unroll
            for (int gg = 0; gg < 3; gg++)
#pragma unroll
                for (int b = 0; b < 4; b++) {
                    float v = acc[u][gg][b];
                    v += __shfl_xor_sync(0xffffffffu, v, 8);
                    v += __shfl_xor_sync(0xffffffffu, v, 16);
                    acc[u][gg][b] = v;
                }

        float hold[2][4];
        if (lane < 8) {
#pragma unroll
            for (int u = 0; u < 2; u++)
#pragma unroll
                for (int b = 0; b < 4; b++)
                    hold[u][b] = h_s[(j0 + u) * BB + bg * 4 + b];
        }
        __syncthreads();

        if (khalf == 1 && lane < 8) {
#pragma unroll
            for (int u = 0; u < 2; u++)
#pragma unroll
                for (int gg = 0; gg < 3; gg++)
#pragma unroll
                    for (int b = 0; b < 4; b++)
                        red[pair * 192 + bg * 24 + u * 12 + gg * 4 + b] = acc[u][gg][b];
        }
        __syncthreads();

        if (khalf == 0 && lane < 8) {
#pragma unroll
            for (int u = 0; u < 2; u++) {
                const int j = j0 + u;
#pragma unroll
                for (int b4 = 0; b4 < 4; b4++) {
                    const int b = bg * 4 + b4;
                    float hr = acc[u][0][b4] + red[pair * 192 + bg * 24 + u * 12 + 0 * 4 + b4] + bh[u][0];
                    float hz = acc[u][1][b4] + red[pair * 192 + bg * 24 + u * 12 + 1 * 4 + b4] + bh[u][1];
                    float hn = acc[u][2][b4] + red[pair * 192 + bg * 24 + u * 12 + 2 * 4 + b4] + bh[u][2];

                    const float* gxp = gx + ((size_t)t * BB + b) * GG;
                    float xr = gxp[j];
                    float xz = gxp[HH + j];
                    float xn = gxp[2 * HH + j];

                    float rr = 1.f / (1.f + expf(-(xr + hr)));
                    float zz = 1.f / (1.f + expf(-(xz + hz)));
                    float nn = tanhf(xn + rr * hn);
                    float hnew = (1.f - zz) * nn + zz * hold[u][b4];

                    hall[((size_t)t * BB + b) * HH + j] = hnew;
                    g_hT[t & 1][j * BB + b] = hnew;
                    if (t == TT - 1) hidden[b * HH + j] = hnew;
                }
            }
        }

        __threadfence();
        __syncthreads();
        if (tid == 0) {
            if (atomicAdd(&g_cnt, 1u) == NCTA - 1) {
                atomicExch(&g_cnt, 0u);
                __threadfence();
                atomicAdd(&g_gen, 1u);
            }
            unsigned target = gen_base + (unsigned)(t + 1);
            while ((int)(ld_acq(&g_gen) - target) < 0) {}
        }
        __syncthreads();

        if (t < TT - 1) {
            const float* hT = &g_hT[t & 1][0];
            for (int idx = tid; idx < HH * (BB / 4); idx += 256) {
                float4 v = ldcg4((const float4*)(hT + idx * 4));
                *(float4*)&h_s[idx * 4] = v;
            }
            __syncthreads();
        }
    }
}

// ---------------- launch -------------------------------------------------------
extern "C" void kernel_launch(void* const* d_in, const int* in_sizes, int n_in,
                              void* d_out, int out_size)
{
    const int*   inputs = (const int*)  d_in[0];
    const float* emb    = (const float*)d_in[3];
    const float* w_ih   = (const float*)d_in[4];
    const float* w_hh   = (const float*)d_in[5];
    const float* b_ih   = (const float*)d_in[6];
    const float* b_hh   = (const float*)d_in[7];
    const float* out_w  = (const float*)d_in[8];
    const float* out_b  = (const float*)d_in[9];

    float* logits = (float*)d_out;
    float* hidden = (float*)d_out + (size_t)MM * VV;

    float* gx;   cudaGetSymbolAddress((void**)&gx,   g_gx);
    float* hall; cudaGetSymbolAddress((void**)&hall, g_hall);
    __nv_bfloat16 *Xh, *Xl, *Wh, *Wl;
    __half *Fw, *Fa;
    cudaGetSymbolAddress((void**)&Xh, g_Xh);
    cudaGetSymbolAddress((void**)&Xl, g_Xl);
    cudaGetSymbolAddress((void**)&Wh, g_Wh);
    cudaGetSymbolAddress((void**)&Wl, g_Wl);
    cudaGetSymbolAddress((void**)&Fw, g_Fw);
    cudaGetSymbolAddress((void**)&Fa, g_Fa);

    const int bgemm_smem = 1024 + NSTAGE * STAGEB + 1024;
    cudaFuncSetAttribute(bgemm_mma, cudaFuncAttributeMaxDynamicSharedMemorySize, bgemm_smem);
    const int hgemm_smem = 1024 + NSTAGEH * STAGEH + 1024;
    cudaFuncSetAttribute(hgemm_mma, cudaFuncAttributeMaxDynamicSharedMemorySize, hgemm_smem);

    // 0-2: operand prep
    split_blk<<<(MM * (EE / 8) + 255) / 256, 256>>>(emb, Xh, Xl, MM, EE, inputs);
    split_blk<<<(GG * (EE / 8) + 255) / 256, 256>>>(w_ih, Wh, Wl, GG, EE, nullptr);
    split_f16<<<(VV * (HH / 8) + 255) / 256, 256>>>(out_w, Fw, VV, HH);

    // 3: gx = X @ w_ih^T + b_ih (bf16x3, error ~3e-6, feeds the recurrence)
    {
        dim3 grid(MM / 128, GG / 128);
        bgemm_mma<<<grid, 512, bgemm_smem>>>(Xh, Xl, Wh, Wl, b_ih, gx, GG, EE);
    }

    // 4: barrier state init
    init_barrier<<<1, 32>>>();

    // 5: GRU recurrence (persistent, exact fp32)
    {
        const int smem = (24 * HH + HH * BB) * sizeof(float);
        cudaFuncSetAttribute(gru_persistent,
                             cudaFuncAttributeMaxDynamicSharedMemorySize, smem);
        gru_persistent<<<NCTA, 256, smem>>>(w_hh, b_hh, gx, hall, hidden);
    }

    // 6: hall -> fp16 blocked
    split_f16<<<(MM * (HH / 8) + 255) / 256, 256>>>(hall, Fa, MM, HH);

    // 7: logits = hall @ out_w^T + out_b (fp16 single-product; output-only,
    //    no error propagation; predicted rel_err ~2e-4 < 1e-3)
    {
        dim3 grid(MM / 128, VV / 128);
        hgemm_mma<<<grid, 512, hgemm_smem>>>(Fa, Fw, out_b, logits, VV, HH);
    }
}

// round 11
// speedup vs baseline: 1.4920x; 1.0096x over previous
#include <cuda_runtime.h>
#include <cuda_bf16.h>
#include <cuda_fp16.h>
#include <math.h>
#include <stdint.h>

// Problem dims
#define TT 128
#define BB 32
#define EE 512
#define HH 1024
#define VV 32000
#define GG (3 * HH)       // 3072
#define MM (TT * BB)      // 4096
#define NCTA 128

// ---------------- scratch (device globals) ----------------------------------
__device__ float g_gx[MM * GG];
__device__ float g_hall[MM * HH];
__device__ float g_hT[2][HH * BB];
__device__ unsigned g_cnt = 0;
__device__ unsigned g_gen = 0;
__device__ __nv_bfloat16 g_Xh[MM * EE];
__device__ __nv_bfloat16 g_Xl[MM * EE];
__device__ __nv_bfloat16 g_Wh[GG * EE];
__device__ __nv_bfloat16 g_Wl[GG * EE];
__device__ __half g_Fw[VV * HH];
__device__ __half g_Fa[MM * HH];

// ---------------- helpers ----------------------------------------------------
__device__ __forceinline__ uint32_t smem_u32(const void* p) {
    uint32_t a;
    asm("{ .reg .u64 t; cvta.to.shared.u64 t, %1; cvt.u32.u64 %0, t; }"
        : "=r"(a) : "l"(p));
    return a;
}
__device__ __forceinline__ unsigned ld_acq(unsigned* p) {
    unsigned v;
    asm volatile("ld.acquire.gpu.u32 %0, [%1];" : "=r"(v) : "l"(p) : "memory");
    return v;
}
__device__ __forceinline__ void mbar_init(uint32_t mbar, int cnt) {
    asm volatile("mbarrier.init.shared.b64 [%0], %1;" :: "r"(mbar), "r"(cnt) : "memory");
}
__device__ __forceinline__ void mbar_expect_tx(uint32_t mbar, uint32_t bytes) {
    asm volatile("mbarrier.arrive.expect_tx.shared.b64 _, [%0], %1;"
                 :: "r"(mbar), "r"(bytes) : "memory");
}
__device__ __forceinline__ void mbar_arrive(uint32_t mbar) {
    asm volatile("mbarrier.arrive.shared.b64 _, [%0];" :: "r"(mbar) : "memory");
}
__device__ __forceinline__ void bulk_cp(uint32_t dst, const void* src, uint32_t bytes,
                                        uint32_t mbar) {
    asm volatile(
        "cp.async.bulk.shared::cluster.global.mbarrier::complete_tx::bytes "
        "[%0], [%1], %2, [%3];"
        :: "r"(dst), "l"(src), "r"(bytes), "r"(mbar) : "memory");
}
__device__ __forceinline__ void mbar_wait(uint32_t mbar, int ph) {
    asm volatile(
        "{\n\t.reg .pred P1;\n"
        "WL%=:\n\t"
        "mbarrier.try_wait.parity.acquire.cta.shared::cta.b64 P1, [%0], %1, 0x989680;\n\t"
        "@P1 bra.uni WD%=;\n\t"
        "bra.uni WL%=;\n"
        "WD%=:\n\t}"
        :: "r"(mbar), "r"(ph) : "memory");
}
__device__ __forceinline__ void ldm_x4(uint32_t* r, uint32_t addr) {
    asm volatile("ldmatrix.sync.aligned.m8n8.x4.shared.b16 {%0,%1,%2,%3}, [%4];"
                 : "=r"(r[0]), "=r"(r[1]), "=r"(r[2]), "=r"(r[3]) : "r"(addr));
}
__device__ __forceinline__ void mma16816(float* d, const uint32_t* a, const uint32_t* b) {
    asm volatile(
        "mma.sync.aligned.m16n8k16.row.col.f32.bf16.bf16.f32 "
        "{%0,%1,%2,%3}, {%4,%5,%6,%7}, {%8,%9}, {%0,%1,%2,%3};"
        : "+f"(d[0]), "+f"(d[1]), "+f"(d[2]), "+f"(d[3])
        : "r"(a[0]), "r"(a[1]), "r"(a[2]), "r"(a[3]), "r"(b[0]), "r"(b[1]));
}
__device__ __forceinline__ void mma16816h(float* d, const uint32_t* a, const uint32_t* b) {
    asm volatile(
        "mma.sync.aligned.m16n8k16.row.col.f32.f16.f16.f32 "
        "{%0,%1,%2,%3}, {%4,%5,%6,%7}, {%8,%9}, {%0,%1,%2,%3};"
        : "+f"(d[0]), "+f"(d[1]), "+f"(d[2]), "+f"(d[3])
        : "r"(a[0]), "r"(a[1]), "r"(a[2]), "r"(a[3]), "r"(b[0]), "r"(b[1]));
}

// ---------------- fused emb-gather + w_ih split (one launch) ------------------
// Both have K=EE. First MM rows: emb[x_idx] -> Xh/Xl; next GG rows: w_ih -> Wh/Wl.
__global__ __launch_bounds__(256)
void split_xw(const float* __restrict__ emb, const float* __restrict__ w_ih,
              __nv_bfloat16* __restrict__ Xh, __nv_bfloat16* __restrict__ Xl,
              __nv_bfloat16* __restrict__ Wh, __nv_bfloat16* __restrict__ Wl,
              const int* __restrict__ gather)
{
    int idx = blockIdx.x * 256 + threadIdx.x;
    const int ckpr = EE >> 3;                    // 64 chunks per row
    const int nX = MM * ckpr;
    const float* src;
    __nv_bfloat16 *hi, *lo;
    int row, ck;
    if (idx < nX) {
        row = idx / ckpr; ck = idx - row * ckpr;
        int srow = (row < BB) ? gather[row] : gather[row - BB];
        src = emb + (size_t)srow * EE + ck * 8;
        hi = Xh; lo = Xl;
    } else {
        idx -= nX;
        if (idx >= GG * ckpr) return;
        row = idx / ckpr; ck = idx - row * ckpr;
        src = w_ih + (size_t)row * EE + ck * 8;
        hi = Wh; lo = Wl;
    }

    float4 v0 = ((const float4*)src)[0], v1 = ((const float4*)src)[1];
    float f[8] = {v0.x, v0.y, v0.z, v0.w, v1.x, v1.y, v1.z, v1.w};
    __nv_bfloat16 hb[8], lb[8];
#pragma unroll
    for (int i = 0; i < 8; i++) {
        hb[i] = __float2bfloat16(f[i]);
        lb[i] = __float2bfloat16(f[i] - __bfloat162float(hb[i]));
    }

    int nb = row >> 7, nr = row & 127;
    int kc = ck >> 3, chunk = ck & 7;
    size_t base = (((size_t)nb * (EE >> 6)) + kc) << 13;
    int dof = nr * 64 + ((chunk ^ (nr & 7)) << 3);
    *(uint4*)(hi + base + dof) = *(uint4*)hb;
    *(uint4*)(lo + base + dof) = *(uint4*)lb;
}

// ---------------- fp32 -> blocked/swizzled fp16 -------------------------------
__global__ __launch_bounds__(256)
void split_f16(const float* __restrict__ src, __half* __restrict__ dst,
               int rows, int K)
{
    int idx = blockIdx.x * 256 + threadIdx.x;
    int ck_per_row = K >> 3;
    if (idx >= rows * ck_per_row) return;
    int row = idx / ck_per_row;
    int ck  = idx - row * ck_per_row;

    const float4* s = (const float4*)(src + (size_t)row * K + ck * 8);
    float4 v0 = s[0], v1 = s[1];
    float f[8] = {v0.x, v0.y, v0.z, v0.w, v1.x, v1.y, v1.z, v1.w};
    __half h[8];
#pragma unroll
    for (int i = 0; i < 8; i++) h[i] = __float2half(f[i]);

    int nb = row >> 7, nr = row & 127;
    int kc = ck >> 3, chunk = ck & 7;
    size_t base = (((size_t)nb * (K >> 6)) + kc) << 13;
    int dof = nr * 64 + ((chunk ^ (nr & 7)) << 3);
    *(uint4*)(dst + base + dof) = *(uint4*)h;
}

// ---------------- barrier state init ------------------------------------------
__global__ void init_barrier() {
    if (threadIdx.x == 0) { g_cnt = 0; g_gen = 0; }
}

// ---------------- bf16x3 GEMM (gx; unchanged, proven) --------------------------
#define TILEB 16384
#define STAGEB (4 * TILEB)
#define NSTAGE 3

__global__ __launch_bounds__(512, 1)
void bgemm_mma(const __nv_bfloat16* __restrict__ Ah, const __nv_bfloat16* __restrict__ Al,
               const __nv_bfloat16* __restrict__ Bh, const __nv_bfloat16* __restrict__ Bl,
               const float* __restrict__ bias, float* __restrict__ C,
               int N, int K)
{
    extern __shared__ char smraw[];
    const uint32_t base = (smem_u32(smraw) + 1023) & ~1023u;
    const uint32_t fullb  = base;
    const uint32_t emptyb = base + 24;
    const uint32_t tiles  = base + 1024;

    const int tid  = threadIdx.x;
    const int lane = tid & 31;
    const int wid  = tid >> 5;
    const int warp_m = wid >> 2;
    const int warp_n = wid & 3;
    const int nchunk = K >> 6;

    const size_t aBase = (size_t)blockIdx.x * nchunk;
    const size_t bBase = (size_t)blockIdx.y * nchunk;

    if (tid == 0) {
#pragma unroll
        for (int s = 0; s < NSTAGE; s++) {
            mbar_init(fullb + s * 8, 1);
            mbar_init(emptyb + s * 8, 512);
        }
        asm volatile("fence.proxy.async.shared::cta;" ::: "memory");
    }
    __syncthreads();

    auto load_stage = [&](int c) {
        const int s = c % NSTAGE;
        const uint32_t sb = tiles + (uint32_t)s * STAGEB;
        const uint32_t mb = fullb + s * 8;
        mbar_expect_tx(mb, STAGEB);
        bulk_cp(sb + 0 * TILEB, Ah + ((aBase + c) << 13), TILEB, mb);
        bulk_cp(sb + 1 * TILEB, Al + ((aBase + c) << 13), TILEB, mb);
        bulk_cp(sb + 2 * TILEB, Bh + ((bBase + c) << 13), TILEB, mb);
        bulk_cp(sb + 3 * TILEB, Bl + ((bBase + c) << 13), TILEB, mb);
    };

    if (tid == 0) { load_stage(0); if (nchunk > 1) load_stage(1); }

    float acc[2][4][4];
#pragma unroll
    for (int mt = 0; mt < 2; mt++)
#pragma unroll
        for (int nt = 0; nt < 4; nt++)
#pragma unroll
            for (int e = 0; e < 4; e++) acc[mt][nt][e] = 0.f;

    const int g = lane >> 3;
    const int r = lane & 7;

    uint32_t aoff[2][4], boff[2][4];
#pragma unroll
    for (int ks = 0; ks < 4; ks++) {
#pragma unroll
        for (int mt = 0; mt < 2; mt++) {
            int row = warp_m * 32 + mt * 16 + ((g & 1) << 3) + r;
            int ch  = 2 * ks + (g >> 1);
            aoff[mt][ks] = (uint32_t)(row * 128 + ((ch ^ (row & 7)) << 4));
        }
#pragma unroll
        for (int np = 0; np < 2; np++) {
            int row = warp_n * 32 + np * 16 + ((g >> 1) << 3) + r;
            int ch  = 2 * ks + (g & 1);
            boff[np][ks] = (uint32_t)(row * 128 + ((ch ^ (row & 7)) << 4));
        }
    }

    for (int c = 0; c < nchunk; c++) {
        const int s = c % NSTAGE;
        mbar_wait(fullb + s * 8, (c / NSTAGE) & 1);

        if (tid == 0 && c + 2 < nchunk) {
            const int c2 = c + 2, s2 = c2 % NSTAGE;
            if (c2 >= NSTAGE)
                mbar_wait(emptyb + s2 * 8, ((c2 - NSTAGE - s2) / NSTAGE) & 1);
            load_stage(c2);
        }

        const uint32_t sb = tiles + (uint32_t)s * STAGEB;
        const uint32_t tAh = sb, tAl = sb + TILEB, tBh = sb + 2 * TILEB, tBl = sb + 3 * TILEB;

#pragma unroll
        for (int ks = 0; ks < 4; ks++) {
            uint32_t ah[2][4], al[2][4];
#pragma unroll
            for (int mt = 0; mt < 2; mt++) {
                ldm_x4(ah[mt], tAh + aoff[mt][ks]);
                ldm_x4(al[mt], tAl + aoff[mt][ks]);
            }
            uint32_t bh[4][2], bl[4][2];
#pragma unroll
            for (int np = 0; np < 2; np++) {
                uint32_t t0[4], t1[4];
                ldm_x4(t0, tBh + boff[np][ks]);
                ldm_x4(t1, tBl + boff[np][ks]);
                bh[2 * np][0] = t0[0]; bh[2 * np][1] = t0[1];
                bh[2 * np + 1][0] = t0[2]; bh[2 * np + 1][1] = t0[3];
                bl[2 * np][0] = t1[0]; bl[2 * np][1] = t1[1];
                bl[2 * np + 1][0] = t1[2]; bl[2 * np + 1][1] = t1[3];
            }
#pragma unroll
            for (int mt = 0; mt < 2; mt++)
#pragma unroll
                for (int nt = 0; nt < 4; nt++)
                    mma16816(acc[mt][nt], ah[mt], bh[nt]);
#pragma unroll
            for (int mt = 0; mt < 2; mt++)
#pragma unroll
                for (int nt = 0; nt < 4; nt++)
                    mma16816(acc[mt][nt], ah[mt], bl[nt]);
#pragma unroll
            for (int mt = 0; mt < 2; mt++)
#pragma unroll
                for (int nt = 0; nt < 4; nt++)
                    mma16816(acc[mt][nt], al[mt], bh[nt]);
        }

        mbar_arrive(emptyb + s * 8);
    }

    const int bm = blockIdx.x * 128;
    const int bn = blockIdx.y * 128;
#pragma unroll
    for (int mt = 0; mt < 2; mt++) {
        int row0 = bm + warp_m * 32 + mt * 16 + (lane >> 2);
#pragma unroll
        for (int nt = 0; nt < 4; nt++) {
            int col = bn + warp_n * 32 + nt * 8 + ((lane & 3) << 1);
            float b0 = bias[col], b1 = bias[col + 1];
            float2 v0 = make_float2(acc[mt][nt][0] + b0, acc[mt][nt][1] + b1);
            float2 v1 = make_float2(acc[mt][nt][2] + b0, acc[mt][nt][3] + b1);
            *(float2*)(C + (size_t)row0 * N + col) = v0;
            *(float2*)(C + (size_t)(row0 + 8) * N + col) = v1;
        }
    }
}

// ---------------- fp16 single-product GEMM (logits; unchanged) -----------------
#define STAGEH (2 * TILEB)
#define NSTAGEH 4

__global__ __launch_bounds__(512, 1)
void hgemm_mma(const __half* __restrict__ A, const __half* __restrict__ B,
               const float* __restrict__ bias, float* __restrict__ C,
               int N, int K)
{
    extern __shared__ char smraw[];
    const uint32_t base = (smem_u32(smraw) + 1023) & ~1023u;
    const uint32_t fullb  = base;
    const uint32_t emptyb = base + 32;
    const uint32_t tiles  = base + 1024;

    const int tid  = threadIdx.x;
    const int lane = tid & 31;
    const int wid  = tid >> 5;
    const int warp_m = wid >> 2;
    const int warp_n = wid & 3;
    const int nchunk = K >> 6;

    const size_t aBase = (size_t)blockIdx.x * nchunk;
    const size_t bBase = (size_t)blockIdx.y * nchunk;

    if (tid == 0) {
#pragma unroll
        for (int s = 0; s < NSTAGEH; s++) {
            mbar_init(fullb + s * 8, 1);
            mbar_init(emptyb + s * 8, 512);
        }
        asm volatile("fence.proxy.async.shared::cta;" ::: "memory");
    }
    __syncthreads();

    auto load_stage = [&](int c) {
        const int s = c % NSTAGEH;
        const uint32_t sb = tiles + (uint32_t)s * STAGEH;
        const uint32_t mb = fullb + s * 8;
        mbar_expect_tx(mb, STAGEH);
        bulk_cp(sb + 0 * TILEB, A + ((aBase + c) << 13), TILEB, mb);
        bulk_cp(sb + 1 * TILEB, B + ((bBase + c) << 13), TILEB, mb);
    };

    if (tid == 0) {
        load_stage(0);
        if (nchunk > 1) load_stage(1);
        if (nchunk > 2) load_stage(2);
    }

    float acc[2][4][4];
#pragma unroll
    for (int mt = 0; mt < 2; mt++)
#pragma unroll
        for (int nt = 0; nt < 4; nt++)
#pragma unroll
            for (int e = 0; e < 4; e++) acc[mt][nt][e] = 0.f;

    const int g = lane >> 3;
    const int r = lane & 7;

    uint32_t aoff[2][4], boff[2][4];
#pragma unroll
    for (int ks = 0; ks < 4; ks++) {
#pragma unroll
        for (int mt = 0; mt < 2; mt++) {
            int row = warp_m * 32 + mt * 16 + ((g & 1) << 3) + r;
            int ch  = 2 * ks + (g >> 1);
            aoff[mt][ks] = (uint32_t)(row * 128 + ((ch ^ (row & 7)) << 4));
        }
#pragma unroll
        for (int np = 0; np < 2; np++) {
            int row = warp_n * 32 + np * 16 + ((g >> 1) << 3) + r;
            int ch  = 2 * ks + (g & 1);
            boff[np][ks] = (uint32_t)(row * 128 + ((ch ^ (row & 7)) << 4));
        }
    }

    for (int c = 0; c < nchunk; c++) {
        const int s = c % NSTAGEH;
        mbar_wait(fullb + s * 8, (c / NSTAGEH) & 1);

        if (tid == 0 && c + 3 < nchunk) {
            const int c2 = c + 3, s2 = c2 % NSTAGEH;
            if (c2 >= NSTAGEH)
                mbar_wait(emptyb + s2 * 8, ((c2 - NSTAGEH - s2) / NSTAGEH) & 1);
            load_stage(c2);
        }

        const uint32_t sb = tiles + (uint32_t)s * STAGEH;
        const uint32_t tA = sb, tB = sb + TILEB;

        uint32_t aF[2][2][4], bF[2][2][4];
        auto ld_frags = [&](int ks, int buf) {
#pragma unroll
            for (int mt = 0; mt < 2; mt++)
                ldm_x4(aF[buf][mt], tA + aoff[mt][ks]);
#pragma unroll
            for (int np = 0; np < 2; np++)
                ldm_x4(bF[buf][np], tB + boff[np][ks]);
        };
        auto do_mma = [&](int buf) {
#pragma unroll
            for (int mt = 0; mt < 2; mt++)
#pragma unroll
                for (int nt = 0; nt < 4; nt++)
                    mma16816h(acc[mt][nt], aF[buf][mt], &bF[buf][nt >> 1][(nt & 1) * 2]);
        };

        ld_frags(0, 0);
        int buf = 0;
#pragma unroll
        for (int ks = 0; ks < 4; ks++) {
            if (ks < 3) ld_frags(ks + 1, buf ^ 1);
            do_mma(buf);
            buf ^= 1;
        }

        mbar_arrive(emptyb + s * 8);
    }

    const int bm = blockIdx.x * 128;
    const int bn = blockIdx.y * 128;
#pragma unroll
    for (int mt = 0; mt < 2; mt++) {
        int row0 = bm + warp_m * 32 + mt * 16 + (lane >> 2);
#pragma unroll
        for (int nt = 0; nt < 4; nt++) {
            int col = bn + warp_n * 32 + nt * 8 + ((lane & 3) << 1);
            float b0 = bias[col], b1 = bias[col + 1];
            float2 v0 = make_float2(acc[mt][nt][0] + b0, acc[mt][nt][1] + b1);
            float2 v1 = make_float2(acc[mt][nt][2] + b0, acc[mt][nt][3] + b1);
            *(float2*)(C + (size_t)row0 * N + col) = v0;
            *(float2*)(C + (size_t)(row0 + 8) * N + col) = v1;
        }
    }
}

// ---------------- persistent GRU: bulk-copy h reload ---------------------------
__global__ __launch_bounds__(256, 1)
void gru_persistent(const float* __restrict__ w_hh,
                    const float* __restrict__ b_hh,
                    const float* __restrict__ gx,
                    float* __restrict__ hall,
                    float* __restrict__ hidden)
{
    extern __shared__ float smem[];
    __shared__ uint64_t h_mbar_store;
    float* w_s = smem;
    float* h_s = smem + 24 * 1024;
    float* red = h_s;
    const uint32_t hmb = smem_u32(&h_mbar_store);
    const uint32_t hs_addr = smem_u32(h_s);

    const int tid = threadIdx.x;
    const int c = blockIdx.x;

    if (tid == 0) {
        mbar_init(hmb, 1);
        asm volatile("fence.proxy.async.shared::cta;" ::: "memory");
    }
    for (int idx = tid; idx < 24 * 256; idx += 256) {
        int rr = idx >> 8;
        int kq = idx & 255;
        int uu = rr / 3, gg = rr % 3;
        int j = c * 8 + uu;
        float4 v = *(const float4*)(w_hh + ((size_t)(gg * HH + j)) * HH + kq * 4);
        *(float4*)&w_s[rr * HH + kq * 4] = v;
    }
    for (int idx = tid; idx < HH * (BB / 4); idx += 256)
        *(float4*)&h_s[idx * 4] = make_float4(0.f, 0.f, 0.f, 0.f);
    __syncthreads();

    const int warp = tid >> 5, lane = tid & 31;
    const int pair = warp & 3, khalf = warp >> 2;
    const int kg = lane >> 3, bg = lane & 7;
    const int j0 = c * 8 + pair * 2;

    float bh[2][3];
#pragma unroll
    for (int u = 0; u < 2; u++)
#pragma unroll
        for (int gg = 0; gg < 3; gg++)
            bh[u][gg] = b_hh[gg * HH + j0 + u];

    unsigned gen_base = 0;
    if (tid == 0) gen_base = ld_acq(&g_gen);
    int hph = 0;

    for (int t = 0; t < TT; t++) {
        float acc[2][3][4];
#pragma unroll
        for (int u = 0; u < 2; u++)
#pragma unroll
            for (int gg = 0; gg < 3; gg++)
#pragma unroll
                for (int b = 0; b < 4; b++) acc[u][gg][b] = 0.f;

        const int kofs = khalf * 512 + kg * 4;
        const float* w0 = &w_s[(pair * 2 + 0) * 3 * HH];
        const float* w1 = &w_s[(pair * 2 + 1) * 3 * HH];

        for (int i = 0; i < 32; i++) {
            const int k = kofs + i * 16;
            float hm[4][4];
#pragma unroll
            for (int m = 0; m < 4; m++)
                *(float4*)hm[m] = *(const float4*)&h_s[(k + m) * BB + bg * 4];
            float wv[2][3][4];
#pragma unroll
            for (int gg = 0; gg < 3; gg++) {
                *(float4*)wv[0][gg] = *(const float4*)&w0[gg * HH + k];
                *(float4*)wv[1][gg] = *(const float4*)&w1[gg * HH + k];
            }
#pragma unroll
            for (int u = 0; u < 2; u++)
#pragma unroll
                for (int gg = 0; gg < 3; gg++)
#pragma unroll
                    for (int b = 0; b < 4; b++)
                        acc[u][gg][b] += hm[0][b] * wv[u][gg][0]
                                       + hm[1][b] * wv[u][gg][1]
                                       + hm[2][b] * wv[u][gg][2]
                                       + hm[3][b] * wv[u][gg][3];
        }

#pragma unroll
        for (int u = 0; u < 2; u++)
#pragma unroll
            for (int gg = 0; gg < 3; gg++)
#pragma unroll
                for (int b = 0; b < 4; b++) {
                    float v = acc[u][gg][b];
                    v += __shfl_xor_sync(0xffffffffu, v, 8);
                    v += __shfl_xor_sync(0xffffffffu, v, 16);
                    acc[u][gg][b] = v;
                }

        float hold[2][4];
        if (lane < 8) {
#pragma unroll
            for (int u = 0; u < 2; u++)
#pragma unroll
                for (int b = 0; b < 4; b++)
                    hold[u][b] = h_s[(j0 + u) * BB + bg * 4 + b];
        }
        __syncthreads();

        if (khalf == 1 && lane < 8) {
#pragma unroll
            for (int u = 0; u < 2; u++)
#pragma unroll
                for (int gg = 0; gg < 3; gg++)
#pragma unroll
                    for (int b = 0; b < 4; b++)
                        red[pair * 192 + bg * 24 + u * 12 + gg * 4 + b] = acc[u][gg][b];
        }
        __syncthreads();

        if (khalf == 0 && lane < 8) {
#pragma unroll
            for (int u = 0; u < 2; u++) {
                const int j = j0 + u;
#pragma unroll
                for (int b4 = 0; b4 < 4; b4++) {
                    const int b = bg * 4 + b4;
                    float hr = acc[u][0][b4] + red[pair * 192 + bg * 24 + u * 12 + 0 * 4 + b4] + bh[u][0];
                    float hz = acc[u][1][b4] + red[pair * 192 + bg * 24 + u * 12 + 1 * 4 + b4] + bh[u][1];
                    float hn = acc[u][2][b4] + red[pair * 192 + bg * 24 + u * 12 + 2 * 4 + b4] + bh[u][2];

                    const float* gxp = gx + ((size_t)t * BB + b) * GG;
                    float xr = gxp[j];
                    float xz = gxp[HH + j];
                    float xn = gxp[2 * HH + j];

                    float rr = 1.f / (1.f + expf(-(xr + hr)));
                    float zz = 1.f / (1.f + expf(-(xz + hz)));
                    float nn = tanhf(xn + rr * hn);
                    float hnew = (1.f - zz) * nn + zz * hold[u][b4];

                    hall[((size_t)t * BB + b) * HH + j] = hnew;
                    g_hT[t & 1][j * BB + b] = hnew;
                    if (t == TT - 1) hidden[b * HH + j] = hnew;
                }
            }
            __threadfence();        // only writers fence their global stores
        }
        __syncthreads();

        if (tid == 0) {
            if (atomicAdd(&g_cnt, 1u) == NCTA - 1) {
                atomicExch(&g_cnt, 0u);
                __threadfence();
                atomicAdd(&g_gen, 1u);
            }
            unsigned target = gen_base + (unsigned)(t + 1);
            while ((int)(ld_acq(&g_gen) - target) < 0) {}
        }
        __syncthreads();

        // reload next-step h (128 KB) with ONE bulk copy instead of 8192 LDGs
        if (t < TT - 1) {
            if (tid == 0) {
                mbar_expect_tx(hmb, BB * HH * 4);
                bulk_cp(hs_addr, &g_hT[t & 1][0], BB * HH * 4, hmb);
            }
            mbar_wait(hmb, hph);
            hph ^= 1;
        }
    }
}

// ---------------- launch -------------------------------------------------------
extern "C" void kernel_launch(void* const* d_in, const int* in_sizes, int n_in,
                              void* d_out, int out_size)
{
    const int*   inputs = (const int*)  d_in[0];
    const float* emb    = (const float*)d_in[3];
    const float* w_ih   = (const float*)d_in[4];
    const float* w_hh   = (const float*)d_in[5];
    const float* b_ih   = (const float*)d_in[6];
    const float* b_hh   = (const float*)d_in[7];
    const float* out_w  = (const float*)d_in[8];
    const float* out_b  = (const float*)d_in[9];

    float* logits = (float*)d_out;
    float* hidden = (float*)d_out + (size_t)MM * VV;

    float* gx;   cudaGetSymbolAddress((void**)&gx,   g_gx);
    float* hall; cudaGetSymbolAddress((void**)&hall, g_hall);
    __nv_bfloat16 *Xh, *Xl, *Wh, *Wl;
    __half *Fw, *Fa;
    cudaGetSymbolAddress((void**)&Xh, g_Xh);
    cudaGetSymbolAddress((void**)&Xl, g_Xl);
    cudaGetSymbolAddress((void**)&Wh, g_Wh);
    cudaGetSymbolAddress((void**)&Wl, g_Wl);
    cudaGetSymbolAddress((void**)&Fw, g_Fw);
    cudaGetSymbolAddress((void**)&Fa, g_Fa);

    const int bgemm_smem = 1024 + NSTAGE * STAGEB + 1024;
    cudaFuncSetAttribute(bgemm_mma, cudaFuncAttributeMaxDynamicSharedMemorySize, bgemm_smem);
    const int hgemm_smem = 1024 + NSTAGEH * STAGEH + 1024;
    cudaFuncSetAttribute(hgemm_mma, cudaFuncAttributeMaxDynamicSharedMemorySize, hgemm_smem);

    // 0: fused emb-gather + w_ih split (one launch)
    {
        int total = (MM + GG) * (EE / 8);
        split_xw<<<(total + 255) / 256, 256>>>(emb, w_ih, Xh, Xl, Wh, Wl, inputs);
    }

    // 1: gx = X @ w_ih^T + b_ih (bf16x3)
    {
        dim3 grid(MM / 128, GG / 128);
        bgemm_mma<<<grid, 512, bgemm_smem>>>(Xh, Xl, Wh, Wl, b_ih, gx, GG, EE);
    }

    // 2: barrier state init
    init_barrier<<<1, 32>>>();

    // 3: GRU recurrence (persistent; lands at ncu capture slot)
    {
        const int smem = (24 * HH + HH * BB) * sizeof(float);
        cudaFuncSetAttribute(gru_persistent,
                             cudaFuncAttributeMaxDynamicSharedMemorySize, smem);
        gru_persistent<<<NCTA, 256, smem>>>(w_hh, b_hh, gx, hall, hidden);
    }

    // 4-5: fp16 blocked conversions (out_w split moved after GRU; independent)
    split_f16<<<(MM * (HH / 8) + 255) / 256, 256>>>(hall, Fa, MM, HH);
    split_f16<<<(VV * (HH / 8) + 255) / 256, 256>>>(out_w, Fw, VV, HH);

    // 6: logits = hall @ out_w^T + out_b (fp16 single-product)
    {
        dim3 grid(MM / 128, VV / 128);
        hgemm_mma<<<grid, 512, hgemm_smem>>>(Fa, Fw, out_b, logits, VV, HH);
    }
}

// round 12
// speedup vs baseline: 1.6247x; 1.0889x over previous
#include <cuda_runtime.h>
#include <cuda_bf16.h>
#include <cuda_fp16.h>
#include <math.h>
#include <stdint.h>

// Problem dims
#define TT 128
#define BB 32
#define EE 512
#define HH 1024
#define VV 32000
#define GG (3 * HH)       // 3072
#define MM (TT * BB)      // 4096
#define NCTA 128

// ---------------- scratch (device globals) ----------------------------------
__device__ float g_gx[MM * GG];
__device__ float g_hT[2][HH * BB];
__device__ unsigned g_cnt = 0;
__device__ unsigned g_gen = 0;
__device__ __nv_bfloat16 g_Xh[MM * EE];
__device__ __nv_bfloat16 g_Xl[MM * EE];
__device__ __nv_bfloat16 g_Wh[GG * EE];
__device__ __nv_bfloat16 g_Wl[GG * EE];
__device__ __half g_Fw[VV * HH];
__device__ __half g_Fa[MM * HH];

// ---------------- helpers ----------------------------------------------------
__device__ __forceinline__ uint32_t smem_u32(const void* p) {
    uint32_t a;
    asm("{ .reg .u64 t; cvta.to.shared.u64 t, %1; cvt.u32.u64 %0, t; }"
        : "=r"(a) : "l"(p));
    return a;
}
__device__ __forceinline__ unsigned ld_acq(unsigned* p) {
    unsigned v;
    asm volatile("ld.acquire.gpu.u32 %0, [%1];" : "=r"(v) : "l"(p) : "memory");
    return v;
}
__device__ __forceinline__ void mbar_init(uint32_t mbar, int cnt) {
    asm volatile("mbarrier.init.shared.b64 [%0], %1;" :: "r"(mbar), "r"(cnt) : "memory");
}
__device__ __forceinline__ void mbar_expect_tx(uint32_t mbar, uint32_t bytes) {
    asm volatile("mbarrier.arrive.expect_tx.shared.b64 _, [%0], %1;"
                 :: "r"(mbar), "r"(bytes) : "memory");
}
__device__ __forceinline__ void mbar_arrive(uint32_t mbar) {
    asm volatile("mbarrier.arrive.shared.b64 _, [%0];" :: "r"(mbar) : "memory");
}
__device__ __forceinline__ void bulk_cp(uint32_t dst, const void* src, uint32_t bytes,
                                        uint32_t mbar) {
    asm volatile(
        "cp.async.bulk.shared::cluster.global.mbarrier::complete_tx::bytes "
        "[%0], [%1], %2, [%3];"
        :: "r"(dst), "l"(src), "r"(bytes), "r"(mbar) : "memory");
}
__device__ __forceinline__ void mbar_wait(uint32_t mbar, int ph) {
    asm volatile(
        "{\n\t.reg .pred P1;\n"
        "WL%=:\n\t"
        "mbarrier.try_wait.parity.acquire.cta.shared::cta.b64 P1, [%0], %1, 0x989680;\n\t"
        "@P1 bra.uni WD%=;\n\t"
        "bra.uni WL%=;\n"
        "WD%=:\n\t}"
        :: "r"(mbar), "r"(ph) : "memory");
}
__device__ __forceinline__ void ldm_x4(uint32_t* r, uint32_t addr) {
    asm volatile("ldmatrix.sync.aligned.m8n8.x4.shared.b16 {%0,%1,%2,%3}, [%4];"
                 : "=r"(r[0]), "=r"(r[1]), "=r"(r[2]), "=r"(r[3]) : "r"(addr));
}
__device__ __forceinline__ void mma16816(float* d, const uint32_t* a, const uint32_t* b) {
    asm volatile(
        "mma.sync.aligned.m16n8k16.row.col.f32.bf16.bf16.f32 "
        "{%0,%1,%2,%3}, {%4,%5,%6,%7}, {%8,%9}, {%0,%1,%2,%3};"
        : "+f"(d[0]), "+f"(d[1]), "+f"(d[2]), "+f"(d[3])
        : "r"(a[0]), "r"(a[1]), "r"(a[2]), "r"(a[3]), "r"(b[0]), "r"(b[1]));
}
__device__ __forceinline__ void mma16816h(float* d, const uint32_t* a, const uint32_t* b) {
    asm volatile(
        "mma.sync.aligned.m16n8k16.row.col.f32.f16.f16.f32 "
        "{%0,%1,%2,%3}, {%4,%5,%6,%7}, {%8,%9}, {%0,%1,%2,%3};"
        : "+f"(d[0]), "+f"(d[1]), "+f"(d[2]), "+f"(d[3])
        : "r"(a[0]), "r"(a[1]), "r"(a[2]), "r"(a[3]), "r"(b[0]), "r"(b[1]));
}

// ---------------- fused emb-gather + w_ih split (one launch) ------------------
__global__ __launch_bounds__(256)
void split_xw(const float* __restrict__ emb, const float* __restrict__ w_ih,
              __nv_bfloat16* __restrict__ Xh, __nv_bfloat16* __restrict__ Xl,
              __nv_bfloat16* __restrict__ Wh, __nv_bfloat16* __restrict__ Wl,
              const int* __restrict__ gather)
{
    int idx = blockIdx.x * 256 + threadIdx.x;
    const int ckpr = EE >> 3;
    const int nX = MM * ckpr;
    const float* src;
    __nv_bfloat16 *hi, *lo;
    int row, ck;
    if (idx < nX) {
        row = idx / ckpr; ck = idx - row * ckpr;
        int srow = (row < BB) ? gather[row] : gather[row - BB];
        src = emb + (size_t)srow * EE + ck * 8;
        hi = Xh; lo = Xl;
    } else {
        idx -= nX;
        if (idx >= GG * ckpr) return;
        row = idx / ckpr; ck = idx - row * ckpr;
        src = w_ih + (size_t)row * EE + ck * 8;
        hi = Wh; lo = Wl;
    }

    float4 v0 = ((const float4*)src)[0], v1 = ((const float4*)src)[1];
    float f[8] = {v0.x, v0.y, v0.z, v0.w, v1.x, v1.y, v1.z, v1.w};
    __nv_bfloat16 hb[8], lb[8];
#pragma unroll
    for (int i = 0; i < 8; i++) {
        hb[i] = __float2bfloat16(f[i]);
        lb[i] = __float2bfloat16(f[i] - __bfloat162float(hb[i]));
    }

    int nb = row >> 7, nr = row & 127;
    int kc = ck >> 3, chunk = ck & 7;
    size_t base = (((size_t)nb * (EE >> 6)) + kc) << 13;
    int dof = nr * 64 + ((chunk ^ (nr & 7)) << 3);
    *(uint4*)(hi + base + dof) = *(uint4*)hb;
    *(uint4*)(lo + base + dof) = *(uint4*)lb;
}

// ---------------- fp32 -> blocked/swizzled fp16 -------------------------------
__global__ __launch_bounds__(256)
void split_f16(const float* __restrict__ src, __half* __restrict__ dst,
               int rows, int K)
{
    int idx = blockIdx.x * 256 + threadIdx.x;
    int ck_per_row = K >> 3;
    if (idx >= rows * ck_per_row) return;
    int row = idx / ck_per_row;
    int ck  = idx - row * ck_per_row;

    const float4* s = (const float4*)(src + (size_t)row * K + ck * 8);
    float4 v0 = s[0], v1 = s[1];
    float f[8] = {v0.x, v0.y, v0.z, v0.w, v1.x, v1.y, v1.z, v1.w};
    __half h[8];
#pragma unroll
    for (int i = 0; i < 8; i++) h[i] = __float2half(f[i]);

    int nb = row >> 7, nr = row & 127;
    int kc = ck >> 3, chunk = ck & 7;
    size_t base = (((size_t)nb * (K >> 6)) + kc) << 13;
    int dof = nr * 64 + ((chunk ^ (nr & 7)) << 3);
    *(uint4*)(dst + base + dof) = *(uint4*)h;
}

// ---------------- barrier state init ------------------------------------------
__global__ void init_barrier() {
    if (threadIdx.x == 0) { g_cnt = 0; g_gen = 0; }
}

// ---------------- bf16x3 GEMM (gx; unchanged, proven) --------------------------
#define TILEB 16384
#define STAGEB (4 * TILEB)
#define NSTAGE 3

__global__ __launch_bounds__(512, 1)
void bgemm_mma(const __nv_bfloat16* __restrict__ Ah, const __nv_bfloat16* __restrict__ Al,
               const __nv_bfloat16* __restrict__ Bh, const __nv_bfloat16* __restrict__ Bl,
               const float* __restrict__ bias, float* __restrict__ C,
               int N, int K)
{
    extern __shared__ char smraw[];
    const uint32_t base = (smem_u32(smraw) + 1023) & ~1023u;
    const uint32_t fullb  = base;
    const uint32_t emptyb = base + 24;
    const uint32_t tiles  = base + 1024;

    const int tid  = threadIdx.x;
    const int lane = tid & 31;
    const int wid  = tid >> 5;
    const int warp_m = wid >> 2;
    const int warp_n = wid & 3;
    const int nchunk = K >> 6;

    const size_t aBase = (size_t)blockIdx.x * nchunk;
    const size_t bBase = (size_t)blockIdx.y * nchunk;

    if (tid == 0) {
#pragma unroll
        for (int s = 0; s < NSTAGE; s++) {
            mbar_init(fullb + s * 8, 1);
            mbar_init(emptyb + s * 8, 512);
        }
        asm volatile("fence.proxy.async.shared::cta;" ::: "memory");
    }
    __syncthreads();

    auto load_stage = [&](int c) {
        const int s = c % NSTAGE;
        const uint32_t sb = tiles + (uint32_t)s * STAGEB;
        const uint32_t mb = fullb + s * 8;
        mbar_expect_tx(mb, STAGEB);
        bulk_cp(sb + 0 * TILEB, Ah + ((aBase + c) << 13), TILEB, mb);
        bulk_cp(sb + 1 * TILEB, Al + ((aBase + c) << 13), TILEB, mb);
        bulk_cp(sb + 2 * TILEB, Bh + ((bBase + c) << 13), TILEB, mb);
        bulk_cp(sb + 3 * TILEB, Bl + ((bBase + c) << 13), TILEB, mb);
    };

    if (tid == 0) { load_stage(0); if (nchunk > 1) load_stage(1); }

    float acc[2][4][4];
#pragma unroll
    for (int mt = 0; mt < 2; mt++)
#pragma unroll
        for (int nt = 0; nt < 4; nt++)
#pragma unroll
            for (int e = 0; e < 4; e++) acc[mt][nt][e] = 0.f;

    const int g = lane >> 3;
    const int r = lane & 7;

    uint32_t aoff[2][4], boff[2][4];
#pragma unroll
    for (int ks = 0; ks < 4; ks++) {
#pragma unroll
        for (int mt = 0; mt < 2; mt++) {
            int row = warp_m * 32 + mt * 16 + ((g & 1) << 3) + r;
            int ch  = 2 * ks + (g >> 1);
            aoff[mt][ks] = (uint32_t)(row * 128 + ((ch ^ (row & 7)) << 4));
        }
#pragma unroll
        for (int np = 0; np < 2; np++) {
            int row = warp_n * 32 + np * 16 + ((g >> 1) << 3) + r;
            int ch  = 2 * ks + (g & 1);
            boff[np][ks] = (uint32_t)(row * 128 + ((ch ^ (row & 7)) << 4));
        }
    }

    for (int c = 0; c < nchunk; c++) {
        const int s = c % NSTAGE;
        mbar_wait(fullb + s * 8, (c / NSTAGE) & 1);

        if (tid == 0 && c + 2 < nchunk) {
            const int c2 = c + 2, s2 = c2 % NSTAGE;
            if (c2 >= NSTAGE)
                mbar_wait(emptyb + s2 * 8, ((c2 - NSTAGE - s2) / NSTAGE) & 1);
            load_stage(c2);
        }

        const uint32_t sb = tiles + (uint32_t)s * STAGEB;
        const uint32_t tAh = sb, tAl = sb + TILEB, tBh = sb + 2 * TILEB, tBl = sb + 3 * TILEB;

#pragma unroll
        for (int ks = 0; ks < 4; ks++) {
            uint32_t ah[2][4], al[2][4];
#pragma unroll
            for (int mt = 0; mt < 2; mt++) {
                ldm_x4(ah[mt], tAh + aoff[mt][ks]);
                ldm_x4(al[mt], tAl + aoff[mt][ks]);
            }
            uint32_t bh[4][2], bl[4][2];
#pragma unroll
            for (int np = 0; np < 2; np++) {
                uint32_t t0[4], t1[4];
                ldm_x4(t0, tBh + boff[np][ks]);
                ldm_x4(t1, tBl + boff[np][ks]);
                bh[2 * np][0] = t0[0]; bh[2 * np][1] = t0[1];
                bh[2 * np + 1][0] = t0[2]; bh[2 * np + 1][1] = t0[3];
                bl[2 * np][0] = t1[0]; bl[2 * np][1] = t1[1];
                bl[2 * np + 1][0] = t1[2]; bl[2 * np + 1][1] = t1[3];
            }
#pragma unroll
            for (int mt = 0; mt < 2; mt++)
#pragma unroll
                for (int nt = 0; nt < 4; nt++)
                    mma16816(acc[mt][nt], ah[mt], bh[nt]);
#pragma unroll
            for (int mt = 0; mt < 2; mt++)
#pragma unroll
                for (int nt = 0; nt < 4; nt++)
                    mma16816(acc[mt][nt], ah[mt], bl[nt]);
#pragma unroll
            for (int mt = 0; mt < 2; mt++)
#pragma unroll
                for (int nt = 0; nt < 4; nt++)
                    mma16816(acc[mt][nt], al[mt], bh[nt]);
        }

        mbar_arrive(emptyb + s * 8);
    }

    const int bm = blockIdx.x * 128;
    const int bn = blockIdx.y * 128;
#pragma unroll
    for (int mt = 0; mt < 2; mt++) {
        int row0 = bm + warp_m * 32 + mt * 16 + (lane >> 2);
#pragma unroll
        for (int nt = 0; nt < 4; nt++) {
            int col = bn + warp_n * 32 + nt * 8 + ((lane & 3) << 1);
            float b0 = bias[col], b1 = bias[col + 1];
            float2 v0 = make_float2(acc[mt][nt][0] + b0, acc[mt][nt][1] + b1);
            float2 v1 = make_float2(acc[mt][nt][2] + b0, acc[mt][nt][3] + b1);
            *(float2*)(C + (size_t)row0 * N + col) = v0;
            *(float2*)(C + (size_t)(row0 + 8) * N + col) = v1;
        }
    }
}

// ---------------- fp16 single-product GEMM (logits; unchanged) -----------------
#define STAGEH (2 * TILEB)
#define NSTAGEH 4

__global__ __launch_bounds__(512, 1)
void hgemm_mma(const __half* __restrict__ A, const __half* __restrict__ B,
               const float* __restrict__ bias, float* __restrict__ C,
               int N, int K)
{
    extern __shared__ char smraw[];
    const uint32_t base = (smem_u32(smraw) + 1023) & ~1023u;
    const uint32_t fullb  = base;
    const uint32_t emptyb = base + 32;
    const uint32_t tiles  = base + 1024;

    const int tid  = threadIdx.x;
    const int lane = tid & 31;
    const int wid  = tid >> 5;
    const int warp_m = wid >> 2;
    const int warp_n = wid & 3;
    const int nchunk = K >> 6;

    const size_t aBase = (size_t)blockIdx.x * nchunk;
    const size_t bBase = (size_t)blockIdx.y * nchunk;

    if (tid == 0) {
#pragma unroll
        for (int s = 0; s < NSTAGEH; s++) {
            mbar_init(fullb + s * 8, 1);
            mbar_init(emptyb + s * 8, 512);
        }
        asm volatile("fence.proxy.async.shared::cta;" ::: "memory");
    }
    __syncthreads();

    auto load_stage = [&](int c) {
        const int s = c % NSTAGEH;
        const uint32_t sb = tiles + (uint32_t)s * STAGEH;
        const uint32_t mb = fullb + s * 8;
        mbar_expect_tx(mb, STAGEH);
        bulk_cp(sb + 0 * TILEB, A + ((aBase + c) << 13), TILEB, mb);
        bulk_cp(sb + 1 * TILEB, B + ((bBase + c) << 13), TILEB, mb);
    };

    if (tid == 0) {
        load_stage(0);
        if (nchunk > 1) load_stage(1);
        if (nchunk > 2) load_stage(2);
    }

    float acc[2][4][4];
#pragma unroll
    for (int mt = 0; mt < 2; mt++)
#pragma unroll
        for (int nt = 0; nt < 4; nt++)
#pragma unroll
            for (int e = 0; e < 4; e++) acc[mt][nt][e] = 0.f;

    const int g = lane >> 3;
    const int r = lane & 7;

    uint32_t aoff[2][4], boff[2][4];
#pragma unroll
    for (int ks = 0; ks < 4; ks++) {
#pragma unroll
        for (int mt = 0; mt < 2; mt++) {
            int row = warp_m * 32 + mt * 16 + ((g & 1) << 3) + r;
            int ch  = 2 * ks + (g >> 1);
            aoff[mt][ks] = (uint32_t)(row * 128 + ((ch ^ (row & 7)) << 4));
        }
#pragma unroll
        for (int np = 0; np < 2; np++) {
            int row = warp_n * 32 + np * 16 + ((g >> 1) << 3) + r;
            int ch  = 2 * ks + (g & 1);
            boff[np][ks] = (uint32_t)(row * 128 + ((ch ^ (row & 7)) << 4));
        }
    }

    for (int c = 0; c < nchunk; c++) {
        const int s = c % NSTAGEH;
        mbar_wait(fullb + s * 8, (c / NSTAGEH) & 1);

        if (tid == 0 && c + 3 < nchunk) {
            const int c2 = c + 3, s2 = c2 % NSTAGEH;
            if (c2 >= NSTAGEH)
                mbar_wait(emptyb + s2 * 8, ((c2 - NSTAGEH - s2) / NSTAGEH) & 1);
            load_stage(c2);
        }

        const uint32_t sb = tiles + (uint32_t)s * STAGEH;
        const uint32_t tA = sb, tB = sb + TILEB;

        uint32_t aF[2][2][4], bF[2][2][4];
        auto ld_frags = [&](int ks, int buf) {
#pragma unroll
            for (int mt = 0; mt < 2; mt++)
                ldm_x4(aF[buf][mt], tA + aoff[mt][ks]);
#pragma unroll
            for (int np = 0; np < 2; np++)
                ldm_x4(bF[buf][np], tB + boff[np][ks]);
        };
        auto do_mma = [&](int buf) {
#pragma unroll
            for (int mt = 0; mt < 2; mt++)
#pragma unroll
                for (int nt = 0; nt < 4; nt++)
                    mma16816h(acc[mt][nt], aF[buf][mt], &bF[buf][nt >> 1][(nt & 1) * 2]);
        };

        ld_frags(0, 0);
        int buf = 0;
#pragma unroll
        for (int ks = 0; ks < 4; ks++) {
            if (ks < 3) ld_frags(ks + 1, buf ^ 1);
            do_mma(buf);
            buf ^= 1;
        }

        mbar_arrive(emptyb + s * 8);
    }

    const int bm = blockIdx.x * 128;
    const int bn = blockIdx.y * 128;
#pragma unroll
    for (int mt = 0; mt < 2; mt++) {
        int row0 = bm + warp_m * 32 + mt * 16 + (lane >> 2);
#pragma unroll
        for (int nt = 0; nt < 4; nt++) {
            int col = bn + warp_n * 32 + nt * 8 + ((lane & 3) << 1);
            float b0 = bias[col], b1 = bias[col + 1];
            float2 v0 = make_float2(acc[mt][nt][0] + b0, acc[mt][nt][1] + b1);
            float2 v1 = make_float2(acc[mt][nt][2] + b0, acc[mt][nt][3] + b1);
            *(float2*)(C + (size_t)row0 * N + col) = v0;
            *(float2*)(C + (size_t)(row0 + 8) * N + col) = v1;
        }
    }
}

// ---------------- persistent GRU: 512 threads, fused fp16 output ---------------
// 16 warps: pair = warp&3 (2 units each), kq = warp>>2 (4-way k split, 256 k).
// lane: kg = lane>>3 (4 k subgroups), bg = lane&7 (4 batches each).
// Reduction: shuffle over kg, then smem across the 3 kq>=1 partials.
// Epilogue writes g_Fa (blocked fp16, the logits-GEMM A operand) directly.
__global__ __launch_bounds__(512, 1)
void gru_persistent(const float* __restrict__ w_hh,
                    const float* __restrict__ b_hh,
                    const float* __restrict__ gx,
                    __half* __restrict__ Fa,
                    float* __restrict__ hidden)
{
    extern __shared__ float smem[];
    __shared__ uint64_t h_mbar_store;
    float* w_s = smem;                    // 24*1024 floats
    float* h_s = smem + 24 * 1024;        // 1024*32 floats
    float* red = h_s;                     // 2304 floats alias (rows k<72)
    const uint32_t hmb = smem_u32(&h_mbar_store);
    const uint32_t hs_addr = smem_u32(h_s);

    const int tid = threadIdx.x;
    const int c = blockIdx.x;

    if (tid == 0) {
        mbar_init(hmb, 1);
        asm volatile("fence.proxy.async.shared::cta;" ::: "memory");
    }
    for (int idx = tid; idx < 24 * 256; idx += 512) {
        int rr = idx >> 8;
        int kq4 = idx & 255;
        int uu = rr / 3, gg = rr % 3;
        int j = c * 8 + uu;
        float4 v = *(const float4*)(w_hh + ((size_t)(gg * HH + j)) * HH + kq4 * 4);
        *(float4*)&w_s[rr * HH + kq4 * 4] = v;
    }
    for (int idx = tid; idx < HH * (BB / 4); idx += 512)
        *(float4*)&h_s[idx * 4] = make_float4(0.f, 0.f, 0.f, 0.f);
    __syncthreads();

    const int warp = tid >> 5, lane = tid & 31;
    const int pair = warp & 3, kq = warp >> 2;      // kq 0..3
    const int bg = lane & 7;
    const int j0 = c * 8 + pair * 2;
    const bool pw = (kq == 0 && lane < 8);           // pointwise/reduce owner

    float bh[2][3];
#pragma unroll
    for (int u = 0; u < 2; u++)
#pragma unroll
        for (int gg = 0; gg < 3; gg++)
            bh[u][gg] = b_hh[gg * HH + j0 + u];

    unsigned gen_base = 0;
    if (tid == 0) gen_base = ld_acq(&g_gen);
    int hph = 0;

    for (int t = 0; t < TT; t++) {
        float acc[2][3][4];
#pragma unroll
        for (int u = 0; u < 2; u++)
#pragma unroll
            for (int gg = 0; gg < 3; gg++)
#pragma unroll
                for (int b = 0; b < 4; b++) acc[u][gg][b] = 0.f;

        const int kofs = kq * 256 + (lane >> 3) * 4;
        const float* w0 = &w_s[(pair * 2 + 0) * 3 * HH];
        const float* w1 = &w_s[(pair * 2 + 1) * 3 * HH];

        for (int i = 0; i < 16; i++) {
            const int k = kofs + i * 16;
            float hm[4][4];
#pragma unroll
            for (int m = 0; m < 4; m++)
                *(float4*)hm[m] = *(const float4*)&h_s[(k + m) * BB + bg * 4];
            float wv[2][3][4];
#pragma unroll
            for (int gg = 0; gg < 3; gg++) {
                *(float4*)wv[0][gg] = *(const float4*)&w0[gg * HH + k];
                *(float4*)wv[1][gg] = *(const float4*)&w1[gg * HH + k];
            }
#pragma unroll
            for (int u = 0; u < 2; u++)
#pragma unroll
                for (int gg = 0; gg < 3; gg++)
#pragma unroll
                    for (int b = 0; b < 4; b++)
                        acc[u][gg][b] += hm[0][b] * wv[u][gg][0]
                                       + hm[1][b] * wv[u][gg][1]
                                       + hm[2][b] * wv[u][gg][2]
                                       + hm[3][b] * wv[u][gg][3];
        }

        // reduce over kg within warp
#pragma unroll
        for (int u = 0; u < 2; u++)
#pragma unroll
            for (int gg = 0; gg < 3; gg++)
#pragma unroll
                for (int b = 0; b < 4; b++) {
                    float v = acc[u][gg][b];
                    v += __shfl_xor_sync(0xffffffffu, v, 8);
                    v += __shfl_xor_sync(0xffffffffu, v, 16);
                    acc[u][gg][b] = v;
                }

        // snapshot h_old and prefetch gx BEFORE red aliases h_s rows
        float hold[2][4], pgx[2][3][4];
        if (pw) {
#pragma unroll
            for (int u = 0; u < 2; u++)
#pragma unroll
                for (int b = 0; b < 4; b++)
                    hold[u][b] = h_s[(j0 + u) * BB + bg * 4 + b];
#pragma unroll
            for (int b4 = 0; b4 < 4; b4++) {
                const float* gxp = gx + ((size_t)t * BB + bg * 4 + b4) * GG;
#pragma unroll
                for (int u = 0; u < 2; u++) {
                    pgx[u][0][b4] = gxp[j0 + u];
                    pgx[u][1][b4] = gxp[HH + j0 + u];
                    pgx[u][2][b4] = gxp[2 * HH + j0 + u];
                }
            }
        }
        __syncthreads();

        if (kq >= 1 && lane < 8) {
            float* rp = &red[(kq - 1) * 768 + pair * 192 + bg * 24];
#pragma unroll
            for (int u = 0; u < 2; u++)
#pragma unroll
                for (int gg = 0; gg < 3; gg++)
#pragma unroll
                    for (int b = 0; b < 4; b++)
                        rp[u * 12 + gg * 4 + b] = acc[u][gg][b];
        }
        __syncthreads();

        if (pw) {
            const float* rp = &red[pair * 192 + bg * 24];
#pragma unroll
            for (int u = 0; u < 2; u++) {
                const int j = j0 + u;
                const int kc = j >> 6, chunk = (j >> 3) & 7, je = j & 7;
#pragma unroll
                for (int b4 = 0; b4 < 4; b4++) {
                    const int b = bg * 4 + b4;
                    float hr = acc[u][0][b4] + bh[u][0];
                    float hz = acc[u][1][b4] + bh[u][1];
                    float hn = acc[u][2][b4] + bh[u][2];
#pragma unroll
                    for (int q = 0; q < 3; q++) {
                        hr += rp[q * 768 + u * 12 + 0 * 4 + b4];
                        hz += rp[q * 768 + u * 12 + 1 * 4 + b4];
                        hn += rp[q * 768 + u * 12 + 2 * 4 + b4];
                    }

                    float rr = 1.f / (1.f + expf(-(pgx[u][0][b4] + hr)));
                    float zz = 1.f / (1.f + expf(-(pgx[u][1][b4] + hz)));
                    float nn = tanhf(pgx[u][2][b4] + rr * hn);
                    float hnew = (1.f - zz) * nn + zz * hold[u][b4];

                    // fused fp16 blocked write (logits-GEMM A operand)
                    int row = t * BB + b;
                    int nb = row >> 7, nr = row & 127;
                    size_t basef = (((size_t)nb * (HH >> 6)) + kc) << 13;
                    Fa[basef + nr * 64 + ((chunk ^ (nr & 7)) << 3) + je] =
                        __float2half(hnew);

                    g_hT[t & 1][j * BB + b] = hnew;
                    if (t == TT - 1) hidden[b * HH + j] = hnew;
                }
            }
            __threadfence();
        }
        __syncthreads();

        if (tid == 0) {
            if (atomicAdd(&g_cnt, 1u) == NCTA - 1) {
                atomicExch(&g_cnt, 0u);
                __threadfence();
                atomicAdd(&g_gen, 1u);
            }
            unsigned target = gen_base + (unsigned)(t + 1);
            while ((int)(ld_acq(&g_gen) - target) < 0) {}
        }
        __syncthreads();

        if (t < TT - 1) {
            if (tid == 0) {
                mbar_expect_tx(hmb, BB * HH * 4);
                bulk_cp(hs_addr, &g_hT[t & 1][0], BB * HH * 4, hmb);
            }
            mbar_wait(hmb, hph);
            hph ^= 1;
        }
    }
}

// ---------------- launch -------------------------------------------------------
extern "C" void kernel_launch(void* const* d_in, const int* in_sizes, int n_in,
                              void* d_out, int out_size)
{
    const int*   inputs = (const int*)  d_in[0];
    const float* emb    = (const float*)d_in[3];
    const float* w_ih   = (const float*)d_in[4];
    const float* w_hh   = (const float*)d_in[5];
    const float* b_ih   = (const float*)d_in[6];
    const float* b_hh   = (const float*)d_in[7];
    const float* out_w  = (const float*)d_in[8];
    const float* out_b  = (const float*)d_in[9];

    float* logits = (float*)d_out;
    float* hidden = (float*)d_out + (size_t)MM * VV;

    float* gx;   cudaGetSymbolAddress((void**)&gx,   g_gx);
    __nv_bfloat16 *Xh, *Xl, *Wh, *Wl;
    __half *Fw, *Fa;
    cudaGetSymbolAddress((void**)&Xh, g_Xh);
    cudaGetSymbolAddress((void**)&Xl, g_Xl);
    cudaGetSymbolAddress((void**)&Wh, g_Wh);
    cudaGetSymbolAddress((void**)&Wl, g_Wl);
    cudaGetSymbolAddress((void**)&Fw, g_Fw);
    cudaGetSymbolAddress((void**)&Fa, g_Fa);

    const int bgemm_smem = 1024 + NSTAGE * STAGEB + 1024;
    cudaFuncSetAttribute(bgemm_mma, cudaFuncAttributeMaxDynamicSharedMemorySize, bgemm_smem);
    const int hgemm_smem = 1024 + NSTAGEH * STAGEH + 1024;
    cudaFuncSetAttribute(hgemm_mma, cudaFuncAttributeMaxDynamicSharedMemorySize, hgemm_smem);

    // 0: fused emb-gather + w_ih split
    {
        int total = (MM + GG) * (EE / 8);
        split_xw<<<(total + 255) / 256, 256>>>(emb, w_ih, Xh, Xl, Wh, Wl, inputs);
    }

    // 1: gx = X @ w_ih^T + b_ih (bf16x3)
    {
        dim3 grid(MM / 128, GG / 128);
        bgemm_mma<<<grid, 512, bgemm_smem>>>(Xh, Xl, Wh, Wl, b_ih, gx, GG, EE);
    }

    // 2: barrier state init
    init_barrier<<<1, 32>>>();

    // 3: GRU recurrence (512 threads; writes Fa directly)
    {
        const int smem = (24 * HH + HH * BB) * sizeof(float);
        cudaFuncSetAttribute(gru_persistent,
                             cudaFuncAttributeMaxDynamicSharedMemorySize, smem);
        gru_persistent<<<NCTA, 512, smem>>>(w_hh, b_hh, gx, Fa, hidden);
    }

    // 4: out_w -> fp16 blocked
    split_f16<<<(VV * (HH / 8) + 255) / 256, 256>>>(out_w, Fw, VV, HH);

    // 5: logits = hall @ out_w^T + out_b (fp16 single-product)
    {
        dim3 grid(MM / 128, VV / 128);
        hgemm_mma<<<grid, 512, hgemm_smem>>>(Fa, Fw, out_b, logits, VV, HH);
    }
}

// round 13
// speedup vs baseline: 2.1921x; 1.3492x over previous
#include <cuda_runtime.h>
#include <cuda_bf16.h>
#include <cuda_fp16.h>
#include <math.h>
#include <stdint.h>

// Problem dims
#define TT 128
#define BB 32
#define EE 512
#define HH 1024
#define VV 32000
#define GG (3 * HH)       // 3072
#define MM (TT * BB)      // 4096
#define NCTA 128

// ---------------- scratch (device globals) ----------------------------------
__device__ float g_gx[MM * GG];
__device__ __nv_bfloat16 g_hBh[2][BB * HH];    // ping-pong h, bf16 hi, blocked [b][k=j]
__device__ __nv_bfloat16 g_hBl[2][BB * HH];    // bf16 lo
__device__ unsigned g_cnt = 0;
__device__ __nv_bfloat16 g_Xh[MM * EE];
__device__ __nv_bfloat16 g_Xl[MM * EE];
__device__ __nv_bfloat16 g_Wh[GG * EE];
__device__ __nv_bfloat16 g_Wl[GG * EE];
__device__ __half g_Fw[VV * HH];
__device__ __half g_Fa[MM * HH];

// ---------------- helpers ----------------------------------------------------
__device__ __forceinline__ uint32_t smem_u32(const void* p) {
    uint32_t a;
    asm("{ .reg .u64 t; cvta.to.shared.u64 t, %1; cvt.u32.u64 %0, t; }"
        : "=r"(a) : "l"(p));
    return a;
}
__device__ __forceinline__ unsigned ld_acq(unsigned* p) {
    unsigned v;
    asm volatile("ld.acquire.gpu.u32 %0, [%1];" : "=r"(v) : "l"(p) : "memory");
    return v;
}
__device__ __forceinline__ void mbar_init(uint32_t mbar, int cnt) {
    asm volatile("mbarrier.init.shared.b64 [%0], %1;" :: "r"(mbar), "r"(cnt) : "memory");
}
__device__ __forceinline__ void mbar_expect_tx(uint32_t mbar, uint32_t bytes) {
    asm volatile("mbarrier.arrive.expect_tx.shared.b64 _, [%0], %1;"
                 :: "r"(mbar), "r"(bytes) : "memory");
}
__device__ __forceinline__ void mbar_arrive(uint32_t mbar) {
    asm volatile("mbarrier.arrive.shared.b64 _, [%0];" :: "r"(mbar) : "memory");
}
__device__ __forceinline__ void bulk_cp(uint32_t dst, const void* src, uint32_t bytes,
                                        uint32_t mbar) {
    asm volatile(
        "cp.async.bulk.shared::cluster.global.mbarrier::complete_tx::bytes "
        "[%0], [%1], %2, [%3];"
        :: "r"(dst), "l"(src), "r"(bytes), "r"(mbar) : "memory");
}
__device__ __forceinline__ void mbar_wait(uint32_t mbar, int ph) {
    asm volatile(
        "{\n\t.reg .pred P1;\n"
        "WL%=:\n\t"
        "mbarrier.try_wait.parity.acquire.cta.shared::cta.b64 P1, [%0], %1, 0x989680;\n\t"
        "@P1 bra.uni WD%=;\n\t"
        "bra.uni WL%=;\n"
        "WD%=:\n\t}"
        :: "r"(mbar), "r"(ph) : "memory");
}
__device__ __forceinline__ void ldm_x4(uint32_t* r, uint32_t addr) {
    asm volatile("ldmatrix.sync.aligned.m8n8.x4.shared.b16 {%0,%1,%2,%3}, [%4];"
                 : "=r"(r[0]), "=r"(r[1]), "=r"(r[2]), "=r"(r[3]) : "r"(addr));
}
__device__ __forceinline__ void ldm_x2(uint32_t* r, uint32_t addr) {
    asm volatile("ldmatrix.sync.aligned.m8n8.x2.shared.b16 {%0,%1}, [%2];"
                 : "=r"(r[0]), "=r"(r[1]) : "r"(addr));
}
__device__ __forceinline__ void mma16816(float* d, const uint32_t* a, const uint32_t* b) {
    asm volatile(
        "mma.sync.aligned.m16n8k16.row.col.f32.bf16.bf16.f32 "
        "{%0,%1,%2,%3}, {%4,%5,%6,%7}, {%8,%9}, {%0,%1,%2,%3};"
        : "+f"(d[0]), "+f"(d[1]), "+f"(d[2]), "+f"(d[3])
        : "r"(a[0]), "r"(a[1]), "r"(a[2]), "r"(a[3]), "r"(b[0]), "r"(b[1]));
}
__device__ __forceinline__ void mma16816h(float* d, const uint32_t* a, const uint32_t* b) {
    asm volatile(
        "mma.sync.aligned.m16n8k16.row.col.f32.f16.f16.f32 "
        "{%0,%1,%2,%3}, {%4,%5,%6,%7}, {%8,%9}, {%0,%1,%2,%3};"
        : "+f"(d[0]), "+f"(d[1]), "+f"(d[2]), "+f"(d[3])
        : "r"(a[0]), "r"(a[1]), "r"(a[2]), "r"(a[3]), "r"(b[0]), "r"(b[1]));
}

// ---------------- fused emb-gather + w_ih split (one launch) ------------------
__global__ __launch_bounds__(256)
void split_xw(const float* __restrict__ emb, const float* __restrict__ w_ih,
              __nv_bfloat16* __restrict__ Xh, __nv_bfloat16* __restrict__ Xl,
              __nv_bfloat16* __restrict__ Wh, __nv_bfloat16* __restrict__ Wl,
              const int* __restrict__ gather)
{
    int idx = blockIdx.x * 256 + threadIdx.x;
    const int ckpr = EE >> 3;
    const int nX = MM * ckpr;
    const float* src;
    __nv_bfloat16 *hi, *lo;
    int row, ck;
    if (idx < nX) {
        row = idx / ckpr; ck = idx - row * ckpr;
        int srow = (row < BB) ? gather[row] : gather[row - BB];
        src = emb + (size_t)srow * EE + ck * 8;
        hi = Xh; lo = Xl;
    } else {
        idx -= nX;
        if (idx >= GG * ckpr) return;
        row = idx / ckpr; ck = idx - row * ckpr;
        src = w_ih + (size_t)row * EE + ck * 8;
        hi = Wh; lo = Wl;
    }

    float4 v0 = ((const float4*)src)[0], v1 = ((const float4*)src)[1];
    float f[8] = {v0.x, v0.y, v0.z, v0.w, v1.x, v1.y, v1.z, v1.w};
    __nv_bfloat16 hb[8], lb[8];
#pragma unroll
    for (int i = 0; i < 8; i++) {
        hb[i] = __float2bfloat16(f[i]);
        lb[i] = __float2bfloat16(f[i] - __bfloat162float(hb[i]));
    }

    int nb = row >> 7, nr = row & 127;
    int kc = ck >> 3, chunk = ck & 7;
    size_t base = (((size_t)nb * (EE >> 6)) + kc) << 13;
    int dof = nr * 64 + ((chunk ^ (nr & 7)) << 3);
    *(uint4*)(hi + base + dof) = *(uint4*)hb;
    *(uint4*)(lo + base + dof) = *(uint4*)lb;
}

// ---------------- fp32 -> blocked/swizzled fp16 -------------------------------
__global__ __launch_bounds__(256)
void split_f16(const float* __restrict__ src, __half* __restrict__ dst,
               int rows, int K)
{
    int idx = blockIdx.x * 256 + threadIdx.x;
    int ck_per_row = K >> 3;
    if (idx >= rows * ck_per_row) return;
    int row = idx / ck_per_row;
    int ck  = idx - row * ck_per_row;

    const float4* s = (const float4*)(src + (size_t)row * K + ck * 8);
    float4 v0 = s[0], v1 = s[1];
    float f[8] = {v0.x, v0.y, v0.z, v0.w, v1.x, v1.y, v1.z, v1.w};
    __half h[8];
#pragma unroll
    for (int i = 0; i < 8; i++) h[i] = __float2half(f[i]);

    int nb = row >> 7, nr = row & 127;
    int kc = ck >> 3, chunk = ck & 7;
    size_t base = (((size_t)nb * (K >> 6)) + kc) << 13;
    int dof = nr * 64 + ((chunk ^ (nr & 7)) << 3);
    *(uint4*)(dst + base + dof) = *(uint4*)h;
}

// ---------------- barrier state init ------------------------------------------
__global__ void init_barrier() {
    if (threadIdx.x == 0) g_cnt = 0;
}

// ---------------- bf16x3 GEMM (gx; unchanged, proven) --------------------------
#define TILEB 16384
#define STAGEB (4 * TILEB)
#define NSTAGE 3

__global__ __launch_bounds__(512, 1)
void bgemm_mma(const __nv_bfloat16* __restrict__ Ah, const __nv_bfloat16* __restrict__ Al,
               const __nv_bfloat16* __restrict__ Bh, const __nv_bfloat16* __restrict__ Bl,
               const float* __restrict__ bias, float* __restrict__ C,
               int N, int K)
{
    extern __shared__ char smraw[];
    const uint32_t base = (smem_u32(smraw) + 1023) & ~1023u;
    const uint32_t fullb  = base;
    const uint32_t emptyb = base + 24;
    const uint32_t tiles  = base + 1024;

    const int tid  = threadIdx.x;
    const int lane = tid & 31;
    const int wid  = tid >> 5;
    const int warp_m = wid >> 2;
    const int warp_n = wid & 3;
    const int nchunk = K >> 6;

    const size_t aBase = (size_t)blockIdx.x * nchunk;
    const size_t bBase = (size_t)blockIdx.y * nchunk;

    if (tid == 0) {
#pragma unroll
        for (int s = 0; s < NSTAGE; s++) {
            mbar_init(fullb + s * 8, 1);
            mbar_init(emptyb + s * 8, 512);
        }
        asm volatile("fence.proxy.async.shared::cta;" ::: "memory");
    }
    __syncthreads();

    auto load_stage = [&](int c) {
        const int s = c % NSTAGE;
        const uint32_t sb = tiles + (uint32_t)s * STAGEB;
        const uint32_t mb = fullb + s * 8;
        mbar_expect_tx(mb, STAGEB);
        bulk_cp(sb + 0 * TILEB, Ah + ((aBase + c) << 13), TILEB, mb);
        bulk_cp(sb + 1 * TILEB, Al + ((aBase + c) << 13), TILEB, mb);
        bulk_cp(sb + 2 * TILEB, Bh + ((bBase + c) << 13), TILEB, mb);
        bulk_cp(sb + 3 * TILEB, Bl + ((bBase + c) << 13), TILEB, mb);
    };

    if (tid == 0) { load_stage(0); if (nchunk > 1) load_stage(1); }

    float acc[2][4][4];
#pragma unroll
    for (int mt = 0; mt < 2; mt++)
#pragma unroll
        for (int nt = 0; nt < 4; nt++)
#pragma unroll
            for (int e = 0; e < 4; e++) acc[mt][nt][e] = 0.f;

    const int g = lane >> 3;
    const int r = lane & 7;

    uint32_t aoff[2][4], boff[2][4];
#pragma unroll
    for (int ks = 0; ks < 4; ks++) {
#pragma unroll
        for (int mt = 0; mt < 2; mt++) {
            int row = warp_m * 32 + mt * 16 + ((g & 1) << 3) + r;
            int ch  = 2 * ks + (g >> 1);
            aoff[mt][ks] = (uint32_t)(row * 128 + ((ch ^ (row & 7)) << 4));
        }
#pragma unroll
        for (int np = 0; np < 2; np++) {
            int row = warp_n * 32 + np * 16 + ((g >> 1) << 3) + r;
            int ch  = 2 * ks + (g & 1);
            boff[np][ks] = (uint32_t)(row * 128 + ((ch ^ (row & 7)) << 4));
        }
    }

    for (int c = 0; c < nchunk; c++) {
        const int s = c % NSTAGE;
        mbar_wait(fullb + s * 8, (c / NSTAGE) & 1);

        if (tid == 0 && c + 2 < nchunk) {
            const int c2 = c + 2, s2 = c2 % NSTAGE;
            if (c2 >= NSTAGE)
                mbar_wait(emptyb + s2 * 8, ((c2 - NSTAGE - s2) / NSTAGE) & 1);
            load_stage(c2);
        }

        const uint32_t sb = tiles + (uint32_t)s * STAGEB;
        const uint32_t tAh = sb, tAl = sb + TILEB, tBh = sb + 2 * TILEB, tBl = sb + 3 * TILEB;

#pragma unroll
        for (int ks = 0; ks < 4; ks++) {
            uint32_t ah[2][4], al[2][4];
#pragma unroll
            for (int mt = 0; mt < 2; mt++) {
                ldm_x4(ah[mt], tAh + aoff[mt][ks]);
                ldm_x4(al[mt], tAl + aoff[mt][ks]);
            }
            uint32_t bh[4][2], bl[4][2];
#pragma unroll
            for (int np = 0; np < 2; np++) {
                uint32_t t0[4], t1[4];
                ldm_x4(t0, tBh + boff[np][ks]);
                ldm_x4(t1, tBl + boff[np][ks]);
                bh[2 * np][0] = t0[0]; bh[2 * np][1] = t0[1];
                bh[2 * np + 1][0] = t0[2]; bh[2 * np + 1][1] = t0[3];
                bl[2 * np][0] = t1[0]; bl[2 * np][1] = t1[1];
                bl[2 * np + 1][0] = t1[2]; bl[2 * np + 1][1] = t1[3];
            }
#pragma unroll
            for (int mt = 0; mt < 2; mt++)
#pragma unroll
                for (int nt = 0; nt < 4; nt++)
                    mma16816(acc[mt][nt], ah[mt], bh[nt]);
#pragma unroll
            for (int mt = 0; mt < 2; mt++)
#pragma unroll
                for (int nt = 0; nt < 4; nt++)
                    mma16816(acc[mt][nt], ah[mt], bl[nt]);
#pragma unroll
            for (int mt = 0; mt < 2; mt++)
#pragma unroll
                for (int nt = 0; nt < 4; nt++)
                    mma16816(acc[mt][nt], al[mt], bh[nt]);
        }

        mbar_arrive(emptyb + s * 8);
    }

    const int bm = blockIdx.x * 128;
    const int bn = blockIdx.y * 128;
#pragma unroll
    for (int mt = 0; mt < 2; mt++) {
        int row0 = bm + warp_m * 32 + mt * 16 + (lane >> 2);
#pragma unroll
        for (int nt = 0; nt < 4; nt++) {
            int col = bn + warp_n * 32 + nt * 8 + ((lane & 3) << 1);
            float b0 = bias[col], b1 = bias[col + 1];
            float2 v0 = make_float2(acc[mt][nt][0] + b0, acc[mt][nt][1] + b1);
            float2 v1 = make_float2(acc[mt][nt][2] + b0, acc[mt][nt][3] + b1);
            *(float2*)(C + (size_t)row0 * N + col) = v0;
            *(float2*)(C + (size_t)(row0 + 8) * N + col) = v1;
        }
    }
}

// ---------------- fp16 single-product GEMM (logits; unchanged) -----------------
#define STAGEH (2 * TILEB)
#define NSTAGEH 4

__global__ __launch_bounds__(512, 1)
void hgemm_mma(const __half* __restrict__ A, const __half* __restrict__ B,
               const float* __restrict__ bias, float* __restrict__ C,
               int N, int K)
{
    extern __shared__ char smraw[];
    const uint32_t base = (smem_u32(smraw) + 1023) & ~1023u;
    const uint32_t fullb  = base;
    const uint32_t emptyb = base + 32;
    const uint32_t tiles  = base + 1024;

    const int tid  = threadIdx.x;
    const int lane = tid & 31;
    const int wid  = tid >> 5;
    const int warp_m = wid >> 2;
    const int warp_n = wid & 3;
    const int nchunk = K >> 6;

    const size_t aBase = (size_t)blockIdx.x * nchunk;
    const size_t bBase = (size_t)blockIdx.y * nchunk;

    if (tid == 0) {
#pragma unroll
        for (int s = 0; s < NSTAGEH; s++) {
            mbar_init(fullb + s * 8, 1);
            mbar_init(emptyb + s * 8, 512);
        }
        asm volatile("fence.proxy.async.shared::cta;" ::: "memory");
    }
    __syncthreads();

    auto load_stage = [&](int c) {
        const int s = c % NSTAGEH;
        const uint32_t sb = tiles + (uint32_t)s * STAGEH;
        const uint32_t mb = fullb + s * 8;
        mbar_expect_tx(mb, STAGEH);
        bulk_cp(sb + 0 * TILEB, A + ((aBase + c) << 13), TILEB, mb);
        bulk_cp(sb + 1 * TILEB, B + ((bBase + c) << 13), TILEB, mb);
    };

    if (tid == 0) {
        load_stage(0);
        if (nchunk > 1) load_stage(1);
        if (nchunk > 2) load_stage(2);
    }

    float acc[2][4][4];
#pragma unroll
    for (int mt = 0; mt < 2; mt++)
#pragma unroll
        for (int nt = 0; nt < 4; nt++)
#pragma unroll
            for (int e = 0; e < 4; e++) acc[mt][nt][e] = 0.f;

    const int g = lane >> 3;
    const int r = lane & 7;

    uint32_t aoff[2][4], boff[2][4];
#pragma unroll
    for (int ks = 0; ks < 4; ks++) {
#pragma unroll
        for (int mt = 0; mt < 2; mt++) {
            int row = warp_m * 32 + mt * 16 + ((g & 1) << 3) + r;
            int ch  = 2 * ks + (g >> 1);
            aoff[mt][ks] = (uint32_t)(row * 128 + ((ch ^ (row & 7)) << 4));
        }
#pragma unroll
        for (int np = 0; np < 2; np++) {
            int row = warp_n * 32 + np * 16 + ((g >> 1) << 3) + r;
            int ch  = 2 * ks + (g & 1);
            boff[np][ks] = (uint32_t)(row * 128 + ((ch ^ (row & 7)) << 4));
        }
    }

    for (int c = 0; c < nchunk; c++) {
        const int s = c % NSTAGEH;
        mbar_wait(fullb + s * 8, (c / NSTAGEH) & 1);

        if (tid == 0 && c + 3 < nchunk) {
            const int c2 = c + 3, s2 = c2 % NSTAGEH;
            if (c2 >= NSTAGEH)
                mbar_wait(emptyb + s2 * 8, ((c2 - NSTAGEH - s2) / NSTAGEH) & 1);
            load_stage(c2);
        }

        const uint32_t sb = tiles + (uint32_t)s * STAGEH;
        const uint32_t tA = sb, tB = sb + TILEB;

        uint32_t aF[2][2][4], bF[2][2][4];
        auto ld_frags = [&](int ks, int buf) {
#pragma unroll
            for (int mt = 0; mt < 2; mt++)
                ldm_x4(aF[buf][mt], tA + aoff[mt][ks]);
#pragma unroll
            for (int np = 0; np < 2; np++)
                ldm_x4(bF[buf][np], tB + boff[np][ks]);
        };
        auto do_mma = [&](int buf) {
#pragma unroll
            for (int mt = 0; mt < 2; mt++)
#pragma unroll
                for (int nt = 0; nt < 4; nt++)
                    mma16816h(acc[mt][nt], aF[buf][mt], &bF[buf][nt >> 1][(nt & 1) * 2]);
        };

        ld_frags(0, 0);
        int buf = 0;
#pragma unroll
        for (int ks = 0; ks < 4; ks++) {
            if (ks < 3) ld_frags(ks + 1, buf ^ 1);
            do_mma(buf);
            buf ^= 1;
        }

        mbar_arrive(emptyb + s * 8);
    }

    const int bm = blockIdx.x * 128;
    const int bn = blockIdx.y * 128;
#pragma unroll
    for (int mt = 0; mt < 2; mt++) {
        int row0 = bm + warp_m * 32 + mt * 16 + (lane >> 2);
#pragma unroll
        for (int nt = 0; nt < 4; nt++) {
            int col = bn + warp_n * 32 + nt * 8 + ((lane & 3) << 1);
            float b0 = bias[col], b1 = bias[col + 1];
            float2 v0 = make_float2(acc[mt][nt][0] + b0, acc[mt][nt][1] + b1);
            float2 v1 = make_float2(acc[mt][nt][2] + b0, acc[mt][nt][3] + b1);
            *(float2*)(C + (size_t)row0 * N + col) = v0;
            *(float2*)(C + (size_t)(row0 + 8) * N + col) = v1;
        }
    }
}

// ---------------- persistent GRU: tensor-core dots (bf16x3) --------------------
// Per CTA per step: gh^T(32b x 24n) = h(32 x 1024, bf16x3) @ W(24 x 1024)^T.
// A = h [b][k] blocked (16 chunks x 32rows x 128B, swizzled), bulk-copied from
// global ping-pong each step. B = W (24 rows = 3 gate n-tiles), smem-resident.
// 16 warps = (kq 0..7) x (mt 0..1); 72 HMMA/warp/step; cross-warp k-reduction
// via smem scratch aliasing the h region. h_old kept exact fp32 per own unit.
// smem: Wh 48K | Wl 48K | Ah 64K | Al 64K | hloc 1K  = 230400 B
#define SM_WH 0
#define SM_WL 49152
#define SM_AH 98304
#define SM_AL 163840
#define SM_HLOC 229376
#define GRU_SMEM 230400

__global__ __launch_bounds__(512, 1)
void gru_persistent(const float* __restrict__ w_hh,
                    const float* __restrict__ b_hh,
                    const float* __restrict__ gx,
                    __half* __restrict__ Fa,
                    float* __restrict__ hidden)
{
    extern __shared__ char smem[];
    __shared__ uint64_t h_mbar_store;
    const uint32_t sb   = smem_u32(smem);
    const uint32_t tWh  = sb + SM_WH;
    const uint32_t tWl  = sb + SM_WL;
    const uint32_t tAh  = sb + SM_AH;
    const uint32_t tAl  = sb + SM_AL;
    float* hloc    = (float*)(smem + SM_HLOC);     // [8 uu][32 b] fp32
    float* scratch = (float*)(smem + SM_AH);       // aliases Ah (24 KB used)
    const uint32_t hmb = smem_u32(&h_mbar_store);

    const int tid = threadIdx.x;
    const int c = blockIdx.x;

    if (tid == 0) {
        mbar_init(hmb, 1);
        asm volatile("fence.proxy.async.shared::cta;" ::: "memory");
    }

    // ---- one-time: W (24 x 1024) -> smem bf16 hi/lo, blocked/swizzled ----
    // row n = gate*8 + uu  (n-tile == gate). chunk kc: 24 rows x 128B = 3072 B.
    for (int i = tid; i < 24 * 256; i += 512) {
        int n = i >> 8;                       // 0..23
        int k = (i & 255) * 4;
        int gate = n >> 3, uu = n & 7;
        float4 v = *(const float4*)(w_hh + ((size_t)(gate * HH + c * 8 + uu)) * HH + k);
        float f[4] = {v.x, v.y, v.z, v.w};
        __nv_bfloat16 hb[4], lb[4];
#pragma unroll
        for (int q = 0; q < 4; q++) {
            hb[q] = __float2bfloat16(f[q]);
            lb[q] = __float2bfloat16(f[q] - __bfloat162float(hb[q]));
        }
        int kc = k >> 6, e = k & 63, ch = e >> 3;
        uint32_t off = kc * 3072 + n * 128 + ((ch ^ (n & 7)) << 4) + (e & 7) * 2;
        *(uint2*)(smem + SM_WH + off) = *(uint2*)hb;
        *(uint2*)(smem + SM_WL + off) = *(uint2*)lb;
    }
    // ---- h(0) = 0 ----
    for (int i = tid; i < (65536 * 2) / 16; i += 512)
        *(uint4*)(smem + SM_AH + i * 16) = make_uint4(0, 0, 0, 0);
    for (int i = tid; i < 256; i += 512) hloc[i] = 0.f;
    __syncthreads();

    const int warp = tid >> 5, lane = tid & 31;
    const int mt = warp & 1, kq = warp >> 1;       // mt: b 0-15 / 16-31; kq: k slice
    const int g = lane >> 3, r = lane & 7;
    const int ln = lane & 15, r2 = ln & 7, half2 = ln >> 3;

    // fragment offsets (within chunk) for the 4 k-steps of a 64-k chunk
    uint32_t aoff[4], boff4[4], boff2[4];
#pragma unroll
    for (int ks = 0; ks < 4; ks++) {
        int rowa = mt * 16 + ((g & 1) << 3) + r;
        int cha  = 2 * ks + (g >> 1);
        aoff[ks]  = (uint32_t)(rowa * 128 + ((cha ^ (rowa & 7)) << 4));
        int rowb = ((g >> 1) << 3) + r;            // n 0-15 (x4)
        int chb  = 2 * ks + (g & 1);
        boff4[ks] = (uint32_t)(rowb * 128 + ((chb ^ (rowb & 7)) << 4));
        int rowb2 = 16 + r2;                       // n 16-23 (x2)
        int chb2  = 2 * ks + half2;
        boff2[ks] = (uint32_t)(rowb2 * 128 + ((chb2 ^ (rowb2 & 7)) << 4));
    }

    // pointwise ownership: tid < 256 -> (uu, b)
    const int uu = tid >> 5, bb = tid & 31;
    const bool pw = (tid < 256);
    float bh3[3];
    if (pw) {
#pragma unroll
        for (int gg = 0; gg < 3; gg++)
            bh3[gg] = b_hh[gg * HH + c * 8 + uu];
    }
    // pw scratch read indexing: value (b=bb, n=gate*8+uu)
    const int mtb = bb >> 4;
    const int lsrc = (bb & 7) * 4 + (uu >> 1);
    const int epos = 2 * ((bb & 15) >> 3) + (uu & 1);
    // pw global h write offsets (elements): j = c*8+uu
    const int j = c * 8 + uu;
    const int kcj = j >> 6, chj = (j >> 3) & 7, ej = j & 7;
    const int hoff = kcj * 2048 + bb * 64 + ((chj ^ (bb & 7)) << 3) + ej;
    // pw Fa write: col j in blocked fp16 layout
    const int kc_f = j >> 6, ch_f = (j >> 3) & 7, je_f = j & 7;

    int hph = 0;

    for (int t = 0; t < TT; t++) {
        // prefetch gx for pointwise (hidden under MMA)
        float pgx[3];
        if (pw) {
            const float* gxp = gx + ((size_t)t * BB + bb) * GG;
            pgx[0] = gxp[j];
            pgx[1] = gxp[HH + j];
            pgx[2] = gxp[2 * HH + j];
        }

        // ---- MMA: 8 k-steps over this warp's 128-k slice ----
        float acc[3][4];
#pragma unroll
        for (int nt = 0; nt < 3; nt++)
#pragma unroll
            for (int e = 0; e < 4; e++) acc[nt][e] = 0.f;

#pragma unroll
        for (int s = 0; s < 8; s++) {
            const int kc = kq * 2 + (s >> 2);
            const int ks = s & 3;
            const uint32_t ab = (uint32_t)(kc * 4096);
            const uint32_t wb = (uint32_t)(kc * 3072);
            uint32_t ah[4], al[4];
            ldm_x4(ah, tAh + ab + aoff[ks]);
            ldm_x4(al, tAl + ab + aoff[ks]);
            uint32_t bhf[3][2], blf[3][2];
            {
                uint32_t t0[4], t1[4];
                ldm_x4(t0, tWh + wb + boff4[ks]);
                ldm_x4(t1, tWl + wb + boff4[ks]);
                bhf[0][0] = t0[0]; bhf[0][1] = t0[1];
                bhf[1][0] = t0[2]; bhf[1][1] = t0[3];
                blf[0][0] = t1[0]; blf[0][1] = t1[1];
                blf[1][0] = t1[2]; blf[1][1] = t1[3];
                ldm_x2(bhf[2], tWh + wb + boff2[ks]);
                ldm_x2(blf[2], tWl + wb + boff2[ks]);
            }
#pragma unroll
            for (int nt = 0; nt < 3; nt++) mma16816(acc[nt], ah, bhf[nt]);
#pragma unroll
            for (int nt = 0; nt < 3; nt++) mma16816(acc[nt], ah, blf[nt]);
#pragma unroll
            for (int nt = 0; nt < 3; nt++) mma16816(acc[nt], al, bhf[nt]);
        }

        __syncthreads();                      // all MMA reads of Ah done
        // write partials: scratch[warp*384 + lane*12 + nt*4 + e]
        {
            float* sp = &scratch[warp * 384 + lane * 12];
#pragma unroll
            for (int nt = 0; nt < 3; nt++)
                *(float4*)(sp + nt * 4) = *(float4*)acc[nt];
        }
        __syncthreads();

        // ---- pointwise (256 threads own (uu, b)) ----
        if (pw) {
            float gh[3];
#pragma unroll
            for (int nt = 0; nt < 3; nt++) {
                float s0 = 0.f;
#pragma unroll
                for (int kq2 = 0; kq2 < 8; kq2++)
                    s0 += scratch[(kq2 * 2 + mtb) * 384 + lsrc * 12 + nt * 4 + epos];
                gh[nt] = s0 + bh3[nt];
            }
            float hold = hloc[uu * 32 + bb];
            float rr = 1.f / (1.f + expf(-(pgx[0] + gh[0])));
            float zz = 1.f / (1.f + expf(-(pgx[1] + gh[1])));
            float nn = tanhf(pgx[2] + rr * gh[2]);
            float hnew = (1.f - zz) * nn + zz * hold;

            hloc[uu * 32 + bb] = hnew;

            // fp16 logits-A operand (blocked)
            {
                int row = t * BB + bb;
                int nb = row >> 7, nr = row & 127;
                size_t basef = (((size_t)nb * (HH >> 6)) + kc_f) << 13;
                Fa[basef + nr * 64 + ((ch_f ^ (nr & 7)) << 3) + je_f] = __float2half(hnew);
            }
            // bf16 hi/lo h exchange (blocked A layout for next step's MMA)
            {
                __nv_bfloat16 hb = __float2bfloat16(hnew);
                __nv_bfloat16 lb = __float2bfloat16(hnew - __bfloat162float(hb));
                g_hBh[(t + 1) & 1][hoff] = hb;
                g_hBl[(t + 1) & 1][hoff] = lb;
            }
            if (t == TT - 1) hidden[bb * HH + j] = hnew;
            __threadfence();
        }
        __syncthreads();

        if (t < TT - 1) {
            // monotonic-counter grid barrier
            if (tid == 0) {
                atomicAdd(&g_cnt, 1u);
                unsigned target = (unsigned)(t + 1) * NCTA;
                while (ld_acq(&g_cnt) < target) {}
            }
            __syncthreads();
            // bulk-copy next h (hi + lo, 128 KB) into Ah/Al (overwrites scratch)
            if (tid == 0) {
                mbar_expect_tx(hmb, 2 * 65536);
                bulk_cp(tAh, &g_hBh[(t + 1) & 1][0], 65536, hmb);
                bulk_cp(tAl, &g_hBl[(t + 1) & 1][0], 65536, hmb);
            }
            mbar_wait(hmb, hph);
            hph ^= 1;
        }
    }
}

// ---------------- launch -------------------------------------------------------
extern "C" void kernel_launch(void* const* d_in, const int* in_sizes, int n_in,
                              void* d_out, int out_size)
{
    const int*   inputs = (const int*)  d_in[0];
    const float* emb    = (const float*)d_in[3];
    const float* w_ih   = (const float*)d_in[4];
    const float* w_hh   = (const float*)d_in[5];
    const float* b_ih   = (const float*)d_in[6];
    const float* b_hh   = (const float*)d_in[7];
    const float* out_w  = (const float*)d_in[8];
    const float* out_b  = (const float*)d_in[9];

    float* logits = (float*)d_out;
    float* hidden = (float*)d_out + (size_t)MM * VV;

    float* gx;   cudaGetSymbolAddress((void**)&gx,   g_gx);
    __nv_bfloat16 *Xh, *Xl, *Wh, *Wl;
    __half *Fw, *Fa;
    cudaGetSymbolAddress((void**)&Xh, g_Xh);
    cudaGetSymbolAddress((void**)&Xl, g_Xl);
    cudaGetSymbolAddress((void**)&Wh, g_Wh);
    cudaGetSymbolAddress((void**)&Wl, g_Wl);
    cudaGetSymbolAddress((void**)&Fw, g_Fw);
    cudaGetSymbolAddress((void**)&Fa, g_Fa);

    const int bgemm_smem = 1024 + NSTAGE * STAGEB + 1024;
    cudaFuncSetAttribute(bgemm_mma, cudaFuncAttributeMaxDynamicSharedMemorySize, bgemm_smem);
    const int hgemm_smem = 1024 + NSTAGEH * STAGEH + 1024;
    cudaFuncSetAttribute(hgemm_mma, cudaFuncAttributeMaxDynamicSharedMemorySize, hgemm_smem);
    cudaFuncSetAttribute(gru_persistent, cudaFuncAttributeMaxDynamicSharedMemorySize, GRU_SMEM);

    // 0: fused emb-gather + w_ih split
    {
        int total = (MM + GG) * (EE / 8);
        split_xw<<<(total + 255) / 256, 256>>>(emb, w_ih, Xh, Xl, Wh, Wl, inputs);
    }

    // 1: gx = X @ w_ih^T + b_ih (bf16x3)
    {
        dim3 grid(MM / 128, GG / 128);
        bgemm_mma<<<grid, 512, bgemm_smem>>>(Xh, Xl, Wh, Wl, b_ih, gx, GG, EE);
    }

    // 2: barrier state init
    init_barrier<<<1, 32>>>();

    // 3: GRU recurrence (tensor-core dots; writes Fa directly)
    gru_persistent<<<NCTA, 512, GRU_SMEM>>>(w_hh, b_hh, gx, Fa, hidden);

    // 4: out_w -> fp16 blocked
    split_f16<<<(VV * (HH / 8) + 255) / 256, 256>>>(out_w, Fw, VV, HH);

    // 5: logits = hall @ out_w^T + out_b (fp16 single-product)
    {
        dim3 grid(MM / 128, VV / 128);
        hgemm_mma<<<grid, 512, hgemm_smem>>>(Fa, Fw, out_b, logits, VV, HH);
    }
}

// round 14
// speedup vs baseline: 2.3003x; 1.0493x over previous
#include <cuda_runtime.h>
#include <cuda_bf16.h>
#include <cuda_fp16.h>
#include <math.h>
#include <stdint.h>

// Problem dims
#define TT 128
#define BB 32
#define EE 512
#define HH 1024
#define VV 32000
#define GG (3 * HH)       // 3072
#define MM (TT * BB)      // 4096
#define NCTA 128

// ---------------- scratch (device globals) ----------------------------------
__device__ float g_gx[MM * GG];
__device__ __nv_bfloat16 g_hBh[2][BB * HH];    // ping-pong h, bf16 hi, blocked
__device__ __nv_bfloat16 g_hBl[2][BB * HH];    // bf16 lo
__device__ unsigned g_cnt = 0;
__device__ __nv_bfloat16 g_Xh[MM * EE];
__device__ __nv_bfloat16 g_Xl[MM * EE];
__device__ __nv_bfloat16 g_Wh[GG * EE];
__device__ __nv_bfloat16 g_Wl[GG * EE];
__device__ __half g_Fw[VV * HH];
__device__ __half g_Fa[MM * HH];

// ---------------- helpers ----------------------------------------------------
__device__ __forceinline__ uint32_t smem_u32(const void* p) {
    uint32_t a;
    asm("{ .reg .u64 t; cvta.to.shared.u64 t, %1; cvt.u32.u64 %0, t; }"
        : "=r"(a) : "l"(p));
    return a;
}
__device__ __forceinline__ unsigned ld_acq(unsigned* p) {
    unsigned v;
    asm volatile("ld.acquire.gpu.u32 %0, [%1];" : "=r"(v) : "l"(p) : "memory");
    return v;
}
__device__ __forceinline__ void mbar_init(uint32_t mbar, int cnt) {
    asm volatile("mbarrier.init.shared.b64 [%0], %1;" :: "r"(mbar), "r"(cnt) : "memory");
}
__device__ __forceinline__ void mbar_expect_tx(uint32_t mbar, uint32_t bytes) {
    asm volatile("mbarrier.arrive.expect_tx.shared.b64 _, [%0], %1;"
                 :: "r"(mbar), "r"(bytes) : "memory");
}
__device__ __forceinline__ void mbar_arrive(uint32_t mbar) {
    asm volatile("mbarrier.arrive.shared.b64 _, [%0];" :: "r"(mbar) : "memory");
}
__device__ __forceinline__ void bulk_cp(uint32_t dst, const void* src, uint32_t bytes,
                                        uint32_t mbar) {
    asm volatile(
        "cp.async.bulk.shared::cluster.global.mbarrier::complete_tx::bytes "
        "[%0], [%1], %2, [%3];"
        :: "r"(dst), "l"(src), "r"(bytes), "r"(mbar) : "memory");
}
__device__ __forceinline__ void mbar_wait(uint32_t mbar, int ph) {
    asm volatile(
        "{\n\t.reg .pred P1;\n"
        "WL%=:\n\t"
        "mbarrier.try_wait.parity.acquire.cta.shared::cta.b64 P1, [%0], %1, 0x989680;\n\t"
        "@P1 bra.uni WD%=;\n\t"
        "bra.uni WL%=;\n"
        "WD%=:\n\t}"
        :: "r"(mbar), "r"(ph) : "memory");
}
__device__ __forceinline__ void ldm_x4(uint32_t* r, uint32_t addr) {
    asm volatile("ldmatrix.sync.aligned.m8n8.x4.shared.b16 {%0,%1,%2,%3}, [%4];"
                 : "=r"(r[0]), "=r"(r[1]), "=r"(r[2]), "=r"(r[3]) : "r"(addr));
}
__device__ __forceinline__ void ldm_x2(uint32_t* r, uint32_t addr) {
    asm volatile("ldmatrix.sync.aligned.m8n8.x2.shared.b16 {%0,%1}, [%2];"
                 : "=r"(r[0]), "=r"(r[1]) : "r"(addr));
}
__device__ __forceinline__ void mma16816(float* d, const uint32_t* a, const uint32_t* b) {
    asm volatile(
        "mma.sync.aligned.m16n8k16.row.col.f32.bf16.bf16.f32 "
        "{%0,%1,%2,%3}, {%4,%5,%6,%7}, {%8,%9}, {%0,%1,%2,%3};"
        : "+f"(d[0]), "+f"(d[1]), "+f"(d[2]), "+f"(d[3])
        : "r"(a[0]), "r"(a[1]), "r"(a[2]), "r"(a[3]), "r"(b[0]), "r"(b[1]));
}
__device__ __forceinline__ void mma16816h(float* d, const uint32_t* a, const uint32_t* b) {
    asm volatile(
        "mma.sync.aligned.m16n8k16.row.col.f32.f16.f16.f32 "
        "{%0,%1,%2,%3}, {%4,%5,%6,%7}, {%8,%9}, {%0,%1,%2,%3};"
        : "+f"(d[0]), "+f"(d[1]), "+f"(d[2]), "+f"(d[3])
        : "r"(a[0]), "r"(a[1]), "r"(a[2]), "r"(a[3]), "r"(b[0]), "r"(b[1]));
}

// ---------------- fused emb-gather + w_ih split (one launch) ------------------
__global__ __launch_bounds__(256)
void split_xw(const float* __restrict__ emb, const float* __restrict__ w_ih,
              __nv_bfloat16* __restrict__ Xh, __nv_bfloat16* __restrict__ Xl,
              __nv_bfloat16* __restrict__ Wh, __nv_bfloat16* __restrict__ Wl,
              const int* __restrict__ gather)
{
    int idx = blockIdx.x * 256 + threadIdx.x;
    const int ckpr = EE >> 3;
    const int nX = MM * ckpr;
    const float* src;
    __nv_bfloat16 *hi, *lo;
    int row, ck;
    if (idx < nX) {
        row = idx / ckpr; ck = idx - row * ckpr;
        int srow = (row < BB) ? gather[row] : gather[row - BB];
        src = emb + (size_t)srow * EE + ck * 8;
        hi = Xh; lo = Xl;
    } else {
        idx -= nX;
        if (idx >= GG * ckpr) return;
        row = idx / ckpr; ck = idx - row * ckpr;
        src = w_ih + (size_t)row * EE + ck * 8;
        hi = Wh; lo = Wl;
    }

    float4 v0 = ((const float4*)src)[0], v1 = ((const float4*)src)[1];
    float f[8] = {v0.x, v0.y, v0.z, v0.w, v1.x, v1.y, v1.z, v1.w};
    __nv_bfloat16 hb[8], lb[8];
#pragma unroll
    for (int i = 0; i < 8; i++) {
        hb[i] = __float2bfloat16(f[i]);
        lb[i] = __float2bfloat16(f[i] - __bfloat162float(hb[i]));
    }

    int nb = row >> 7, nr = row & 127;
    int kc = ck >> 3, chunk = ck & 7;
    size_t base = (((size_t)nb * (EE >> 6)) + kc) << 13;
    int dof = nr * 64 + ((chunk ^ (nr & 7)) << 3);
    *(uint4*)(hi + base + dof) = *(uint4*)hb;
    *(uint4*)(lo + base + dof) = *(uint4*)lb;
}

// ---------------- fp32 -> blocked/swizzled fp16 -------------------------------
__global__ __launch_bounds__(256)
void split_f16(const float* __restrict__ src, __half* __restrict__ dst,
               int rows, int K)
{
    int idx = blockIdx.x * 256 + threadIdx.x;
    int ck_per_row = K >> 3;
    if (idx >= rows * ck_per_row) return;
    int row = idx / ck_per_row;
    int ck  = idx - row * ck_per_row;

    const float4* s = (const float4*)(src + (size_t)row * K + ck * 8);
    float4 v0 = s[0], v1 = s[1];
    float f[8] = {v0.x, v0.y, v0.z, v0.w, v1.x, v1.y, v1.z, v1.w};
    __half h[8];
#pragma unroll
    for (int i = 0; i < 8; i++) h[i] = __float2half(f[i]);

    int nb = row >> 7, nr = row & 127;
    int kc = ck >> 3, chunk = ck & 7;
    size_t base = (((size_t)nb * (K >> 6)) + kc) << 13;
    int dof = nr * 64 + ((chunk ^ (nr & 7)) << 3);
    *(uint4*)(dst + base + dof) = *(uint4*)h;
}

// ---------------- barrier state init ------------------------------------------
__global__ void init_barrier() {
    if (threadIdx.x == 0) g_cnt = 0;
}

// ---------------- bf16x3 GEMM (gx; unchanged, proven) --------------------------
#define TILEB 16384
#define STAGEB (4 * TILEB)
#define NSTAGE 3

__global__ __launch_bounds__(512, 1)
void bgemm_mma(const __nv_bfloat16* __restrict__ Ah, const __nv_bfloat16* __restrict__ Al,
               const __nv_bfloat16* __restrict__ Bh, const __nv_bfloat16* __restrict__ Bl,
               const float* __restrict__ bias, float* __restrict__ C,
               int N, int K)
{
    extern __shared__ char smraw[];
    const uint32_t base = (smem_u32(smraw) + 1023) & ~1023u;
    const uint32_t fullb  = base;
    const uint32_t emptyb = base + 24;
    const uint32_t tiles  = base + 1024;

    const int tid  = threadIdx.x;
    const int lane = tid & 31;
    const int wid  = tid >> 5;
    const int warp_m = wid >> 2;
    const int warp_n = wid & 3;
    const int nchunk = K >> 6;

    const size_t aBase = (size_t)blockIdx.x * nchunk;
    const size_t bBase = (size_t)blockIdx.y * nchunk;

    if (tid == 0) {
#pragma unroll
        for (int s = 0; s < NSTAGE; s++) {
            mbar_init(fullb + s * 8, 1);
            mbar_init(emptyb + s * 8, 512);
        }
        asm volatile("fence.proxy.async.shared::cta;" ::: "memory");
    }
    __syncthreads();

    auto load_stage = [&](int c) {
        const int s = c % NSTAGE;
        const uint32_t sb = tiles + (uint32_t)s * STAGEB;
        const uint32_t mb = fullb + s * 8;
        mbar_expect_tx(mb, STAGEB);
        bulk_cp(sb + 0 * TILEB, Ah + ((aBase + c) << 13), TILEB, mb);
        bulk_cp(sb + 1 * TILEB, Al + ((aBase + c) << 13), TILEB, mb);
        bulk_cp(sb + 2 * TILEB, Bh + ((bBase + c) << 13), TILEB, mb);
        bulk_cp(sb + 3 * TILEB, Bl + ((bBase + c) << 13), TILEB, mb);
    };

    if (tid == 0) { load_stage(0); if (nchunk > 1) load_stage(1); }

    float acc[2][4][4];
#pragma unroll
    for (int mt = 0; mt < 2; mt++)
#pragma unroll
        for (int nt = 0; nt < 4; nt++)
#pragma unroll
            for (int e = 0; e < 4; e++) acc[mt][nt][e] = 0.f;

    const int g = lane >> 3;
    const int r = lane & 7;

    uint32_t aoff[2][4], boff[2][4];
#pragma unroll
    for (int ks = 0; ks < 4; ks++) {
#pragma unroll
        for (int mt = 0; mt < 2; mt++) {
            int row = warp_m * 32 + mt * 16 + ((g & 1) << 3) + r;
            int ch  = 2 * ks + (g >> 1);
            aoff[mt][ks] = (uint32_t)(row * 128 + ((ch ^ (row & 7)) << 4));
        }
#pragma unroll
        for (int np = 0; np < 2; np++) {
            int row = warp_n * 32 + np * 16 + ((g >> 1) << 3) + r;
            int ch  = 2 * ks + (g & 1);
            boff[np][ks] = (uint32_t)(row * 128 + ((ch ^ (row & 7)) << 4));
        }
    }

    for (int c = 0; c < nchunk; c++) {
        const int s = c % NSTAGE;
        mbar_wait(fullb + s * 8, (c / NSTAGE) & 1);

        if (tid == 0 && c + 2 < nchunk) {
            const int c2 = c + 2, s2 = c2 % NSTAGE;
            if (c2 >= NSTAGE)
                mbar_wait(emptyb + s2 * 8, ((c2 - NSTAGE - s2) / NSTAGE) & 1);
            load_stage(c2);
        }

        const uint32_t sb = tiles + (uint32_t)s * STAGEB;
        const uint32_t tAh = sb, tAl = sb + TILEB, tBh = sb + 2 * TILEB, tBl = sb + 3 * TILEB;

#pragma unroll
        for (int ks = 0; ks < 4; ks++) {
            uint32_t ah[2][4], al[2][4];
#pragma unroll
            for (int mt = 0; mt < 2; mt++) {
                ldm_x4(ah[mt], tAh + aoff[mt][ks]);
                ldm_x4(al[mt], tAl + aoff[mt][ks]);
            }
            uint32_t bh[4][2], bl[4][2];
#pragma unroll
            for (int np = 0; np < 2; np++) {
                uint32_t t0[4], t1[4];
                ldm_x4(t0, tBh + boff[np][ks]);
                ldm_x4(t1, tBl + boff[np][ks]);
                bh[2 * np][0] = t0[0]; bh[2 * np][1] = t0[1];
                bh[2 * np + 1][0] = t0[2]; bh[2 * np + 1][1] = t0[3];
                bl[2 * np][0] = t1[0]; bl[2 * np][1] = t1[1];
                bl[2 * np + 1][0] = t1[2]; bl[2 * np + 1][1] = t1[3];
            }
#pragma unroll
            for (int mt = 0; mt < 2; mt++)
#pragma unroll
                for (int nt = 0; nt < 4; nt++)
                    mma16816(acc[mt][nt], ah[mt], bh[nt]);
#pragma unroll
            for (int mt = 0; mt < 2; mt++)
#pragma unroll
                for (int nt = 0; nt < 4; nt++)
                    mma16816(acc[mt][nt], ah[mt], bl[nt]);
#pragma unroll
            for (int mt = 0; mt < 2; mt++)
#pragma unroll
                for (int nt = 0; nt < 4; nt++)
                    mma16816(acc[mt][nt], al[mt], bh[nt]);
        }

        mbar_arrive(emptyb + s * 8);
    }

    const int bm = blockIdx.x * 128;
    const int bn = blockIdx.y * 128;
#pragma unroll
    for (int mt = 0; mt < 2; mt++) {
        int row0 = bm + warp_m * 32 + mt * 16 + (lane >> 2);
#pragma unroll
        for (int nt = 0; nt < 4; nt++) {
            int col = bn + warp_n * 32 + nt * 8 + ((lane & 3) << 1);
            float b0 = bias[col], b1 = bias[col + 1];
            float2 v0 = make_float2(acc[mt][nt][0] + b0, acc[mt][nt][1] + b1);
            float2 v1 = make_float2(acc[mt][nt][2] + b0, acc[mt][nt][3] + b1);
            *(float2*)(C + (size_t)row0 * N + col) = v0;
            *(float2*)(C + (size_t)(row0 + 8) * N + col) = v1;
        }
    }
}

// ---------------- fp16 GEMM, 128m x 256n tiles (logits) ------------------------
// 3 blocked tiles per stage (A, B0, B1) = 48 KB; 4 stages. 16 warps @ 32m x 64n.
// Halves per-output L2 B-traffic vs 128-wide tiles.
#define STAGEH (3 * TILEB)               // 48 KB
#define NSTAGEH 4

__global__ __launch_bounds__(512, 1)
void hgemm_mma(const __half* __restrict__ A, const __half* __restrict__ B,
               const float* __restrict__ bias, float* __restrict__ C,
               int N, int K)
{
    extern __shared__ char smraw[];
    const uint32_t base = (smem_u32(smraw) + 1023) & ~1023u;
    const uint32_t fullb  = base;
    const uint32_t emptyb = base + 32;
    const uint32_t tiles  = base + 1024;

    const int tid  = threadIdx.x;
    const int lane = tid & 31;
    const int wid  = tid >> 5;
    const int warp_m = wid >> 2;          // 0..3 (32 m-rows each)
    const int warp_n = wid & 3;           // 0..3 (64 n-cols each)
    const int nchunk = K >> 6;

    const size_t aBase  = (size_t)blockIdx.x * nchunk;
    const size_t b0Base = (size_t)(blockIdx.y * 2) * nchunk;
    const size_t b1Base = (size_t)(blockIdx.y * 2 + 1) * nchunk;

    if (tid == 0) {
#pragma unroll
        for (int s = 0; s < NSTAGEH; s++) {
            mbar_init(fullb + s * 8, 1);
            mbar_init(emptyb + s * 8, 512);
        }
        asm volatile("fence.proxy.async.shared::cta;" ::: "memory");
    }
    __syncthreads();

    auto load_stage = [&](int c) {
        const int s = c % NSTAGEH;
        const uint32_t sb = tiles + (uint32_t)s * STAGEH;
        const uint32_t mb = fullb + s * 8;
        mbar_expect_tx(mb, STAGEH);
        bulk_cp(sb + 0 * TILEB, A + ((aBase + c) << 13), TILEB, mb);
        bulk_cp(sb + 1 * TILEB, B + ((b0Base + c) << 13), TILEB, mb);
        bulk_cp(sb + 2 * TILEB, B + ((b1Base + c) << 13), TILEB, mb);
    };

    if (tid == 0) {
        load_stage(0);
        if (nchunk > 1) load_stage(1);
        if (nchunk > 2) load_stage(2);
    }

    float acc[2][8][4];
#pragma unroll
    for (int mt = 0; mt < 2; mt++)
#pragma unroll
        for (int nt = 0; nt < 8; nt++)
#pragma unroll
            for (int e = 0; e < 4; e++) acc[mt][nt][e] = 0.f;

    const int g = lane >> 3;
    const int r = lane & 7;
    // this warp's B tile: warp_n 0,1 -> B0; 2,3 -> B1. local n base:
    const uint32_t bsel = (warp_n >= 2) ? 2u * TILEB : 1u * TILEB;
    const int nbase = (warp_n & 1) * 64;

    uint32_t aoff[2][4], boff[4][4];
#pragma unroll
    for (int ks = 0; ks < 4; ks++) {
#pragma unroll
        for (int mt = 0; mt < 2; mt++) {
            int row = warp_m * 32 + mt * 16 + ((g & 1) << 3) + r;
            int ch  = 2 * ks + (g >> 1);
            aoff[mt][ks] = (uint32_t)(row * 128 + ((ch ^ (row & 7)) << 4));
        }
#pragma unroll
        for (int np = 0; np < 4; np++) {
            int row = nbase + np * 16 + ((g >> 1) << 3) + r;
            int ch  = 2 * ks + (g & 1);
            boff[np][ks] = (uint32_t)(row * 128 + ((ch ^ (row & 7)) << 4));
        }
    }

    for (int c = 0; c < nchunk; c++) {
        const int s = c % NSTAGEH;
        mbar_wait(fullb + s * 8, (c / NSTAGEH) & 1);

        if (tid == 0 && c + 3 < nchunk) {
            const int c2 = c + 3, s2 = c2 % NSTAGEH;
            if (c2 >= NSTAGEH)
                mbar_wait(emptyb + s2 * 8, ((c2 - NSTAGEH - s2) / NSTAGEH) & 1);
            load_stage(c2);
        }

        const uint32_t sb = tiles + (uint32_t)s * STAGEH;
        const uint32_t tA = sb, tB = sb + bsel;

#pragma unroll
        for (int ks = 0; ks < 4; ks++) {
            uint32_t aF[2][4];
#pragma unroll
            for (int mt = 0; mt < 2; mt++)
                ldm_x4(aF[mt], tA + aoff[mt][ks]);
            uint32_t bF[8][2];
#pragma unroll
            for (int np = 0; np < 4; np++) {
                uint32_t t0[4];
                ldm_x4(t0, tB + boff[np][ks]);
                bF[2 * np][0] = t0[0]; bF[2 * np][1] = t0[1];
                bF[2 * np + 1][0] = t0[2]; bF[2 * np + 1][1] = t0[3];
            }
#pragma unroll
            for (int mt = 0; mt < 2; mt++)
#pragma unroll
                for (int nt = 0; nt < 8; nt++)
                    mma16816h(acc[mt][nt], aF[mt], bF[nt]);
        }

        mbar_arrive(emptyb + s * 8);
    }

    const int bm = blockIdx.x * 128;
    const int bn = blockIdx.y * 256;
#pragma unroll
    for (int mt = 0; mt < 2; mt++) {
        int row0 = bm + warp_m * 32 + mt * 16 + (lane >> 2);
#pragma unroll
        for (int nt = 0; nt < 8; nt++) {
            int col = bn + warp_n * 64 + nt * 8 + ((lane & 3) << 1);
            float b0 = bias[col], b1 = bias[col + 1];
            float2 v0 = make_float2(acc[mt][nt][0] + b0, acc[mt][nt][1] + b1);
            float2 v1 = make_float2(acc[mt][nt][2] + b0, acc[mt][nt][3] + b1);
            *(float2*)(C + (size_t)row0 * N + col) = v0;
            *(float2*)(C + (size_t)(row0 + 8) * N + col) = v1;
        }
    }
}

// ---------------- persistent GRU: tensor-core dots, split hi/lo pipeline -------
#define SM_WH 0
#define SM_WL 49152
#define SM_AH 98304
#define SM_AL 163840
#define SM_HLOC 229376
#define GRU_SMEM 230400

__global__ __launch_bounds__(512, 1)
void gru_persistent(const float* __restrict__ w_hh,
                    const float* __restrict__ b_hh,
                    const float* __restrict__ gx,
                    __half* __restrict__ Fa,
                    float* __restrict__ hidden)
{
    extern __shared__ char smem[];
    __shared__ uint64_t h_mbar_store[2];
    const uint32_t sb   = smem_u32(smem);
    const uint32_t tWh  = sb + SM_WH;
    const uint32_t tWl  = sb + SM_WL;
    const uint32_t tAh  = sb + SM_AH;
    const uint32_t tAl  = sb + SM_AL;
    float* hloc    = (float*)(smem + SM_HLOC);
    float* scratch = (float*)(smem + SM_AH);       // aliases Ah (24 KB used)
    const uint32_t hmbH = smem_u32(&h_mbar_store[0]);
    const uint32_t hmbL = smem_u32(&h_mbar_store[1]);

    const int tid = threadIdx.x;
    const int c = blockIdx.x;

    if (tid == 0) {
        mbar_init(hmbH, 1);
        mbar_init(hmbL, 1);
        asm volatile("fence.proxy.async.shared::cta;" ::: "memory");
    }

    // one-time: W (24 x 1024) -> smem bf16 hi/lo, blocked/swizzled
    for (int i = tid; i < 24 * 256; i += 512) {
        int n = i >> 8;
        int k = (i & 255) * 4;
        int gate = n >> 3, uu = n & 7;
        float4 v = *(const float4*)(w_hh + ((size_t)(gate * HH + c * 8 + uu)) * HH + k);
        float f[4] = {v.x, v.y, v.z, v.w};
        __nv_bfloat16 hb[4], lb[4];
#pragma unroll
        for (int q = 0; q < 4; q++) {
            hb[q] = __float2bfloat16(f[q]);
            lb[q] = __float2bfloat16(f[q] - __bfloat162float(hb[q]));
        }
        int kc = k >> 6, e = k & 63, ch = e >> 3;
        uint32_t off = kc * 3072 + n * 128 + ((ch ^ (n & 7)) << 4) + (e & 7) * 2;
        *(uint2*)(smem + SM_WH + off) = *(uint2*)hb;
        *(uint2*)(smem + SM_WL + off) = *(uint2*)lb;
    }
    for (int i = tid; i < (65536 * 2) / 16; i += 512)
        *(uint4*)(smem + SM_AH + i * 16) = make_uint4(0, 0, 0, 0);
    for (int i = tid; i < 256; i += 512) hloc[i] = 0.f;
    __syncthreads();

    const int warp = tid >> 5, lane = tid & 31;
    const int mt = warp & 1, kq = warp >> 1;
    const int g = lane >> 3, r = lane & 7;
    const int ln = lane & 15, r2 = ln & 7, half2 = ln >> 3;

    uint32_t aoff[4], boff4[4], boff2[4];
#pragma unroll
    for (int ks = 0; ks < 4; ks++) {
        int rowa = mt * 16 + ((g & 1) << 3) + r;
        int cha  = 2 * ks + (g >> 1);
        aoff[ks]  = (uint32_t)(rowa * 128 + ((cha ^ (rowa & 7)) << 4));
        int rowb = ((g >> 1) << 3) + r;
        int chb  = 2 * ks + (g & 1);
        boff4[ks] = (uint32_t)(rowb * 128 + ((chb ^ (rowb & 7)) << 4));
        int rowb2 = 16 + r2;
        int chb2  = 2 * ks + half2;
        boff2[ks] = (uint32_t)(rowb2 * 128 + ((chb2 ^ (rowb2 & 7)) << 4));
    }

    const int uu = tid >> 5, bb = tid & 31;
    const bool pw = (tid < 256);
    float bh3[3];
    if (pw) {
#pragma unroll
        for (int gg = 0; gg < 3; gg++)
            bh3[gg] = b_hh[gg * HH + c * 8 + uu];
    }
    const int mtb = bb >> 4;
    const int lsrc = (bb & 7) * 4 + (uu >> 1);
    const int epos = 2 * ((bb & 15) >> 3) + (uu & 1);
    const int j = c * 8 + uu;
    const int kcj = j >> 6, chj = (j >> 3) & 7, ej = j & 7;
    const int hoff = kcj * 2048 + bb * 64 + ((chj ^ (bb & 7)) << 3) + ej;
    const int kc_f = j >> 6, ch_f = (j >> 3) & 7, je_f = j & 7;

    int hph = 0;

    for (int t = 0; t < TT; t++) {
        float pgx[3];
        if (pw) {
            const float* gxp = gx + ((size_t)t * BB + bb) * GG;
            pgx[0] = gxp[j];
            pgx[1] = gxp[HH + j];
            pgx[2] = gxp[2 * HH + j];
        }

        float acc[3][4];
#pragma unroll
        for (int nt = 0; nt < 3; nt++)
#pragma unroll
            for (int e = 0; e < 4; e++) acc[nt][e] = 0.f;

        // ---- half-1: needs only Ah (hi) ----
        if (t > 0) mbar_wait(hmbH, hph);
#pragma unroll
        for (int s = 0; s < 8; s++) {
            const int kc = kq * 2 + (s >> 2);
            const int ks = s & 3;
            const uint32_t ab = (uint32_t)(kc * 4096);
            const uint32_t wb = (uint32_t)(kc * 3072);
            uint32_t ah[4];
            ldm_x4(ah, tAh + ab + aoff[ks]);
            uint32_t bhf[3][2], blf[3][2];
            {
                uint32_t t0[4], t1[4];
                ldm_x4(t0, tWh + wb + boff4[ks]);
                ldm_x4(t1, tWl + wb + boff4[ks]);
                bhf[0][0] = t0[0]; bhf[0][1] = t0[1];
                bhf[1][0] = t0[2]; bhf[1][1] = t0[3];
                blf[0][0] = t1[0]; blf[0][1] = t1[1];
                blf[1][0] = t1[2]; blf[1][1] = t1[3];
                ldm_x2(bhf[2], tWh + wb + boff2[ks]);
                ldm_x2(blf[2], tWl + wb + boff2[ks]);
            }
#pragma unroll
            for (int nt = 0; nt < 3; nt++) mma16816(acc[nt], ah, bhf[nt]);
#pragma unroll
            for (int nt = 0; nt < 3; nt++) mma16816(acc[nt], ah, blf[nt]);
        }

        // ---- half-2: needs Al (lo) ----
        if (t > 0) { mbar_wait(hmbL, hph); hph ^= 1; }
#pragma unroll
        for (int s = 0; s < 8; s++) {
            const int kc = kq * 2 + (s >> 2);
            const int ks = s & 3;
            const uint32_t ab = (uint32_t)(kc * 4096);
            const uint32_t wb = (uint32_t)(kc * 3072);
            uint32_t al[4];
            ldm_x4(al, tAl + ab + aoff[ks]);
            uint32_t bhf[3][2];
            {
                uint32_t t0[4];
                ldm_x4(t0, tWh + wb + boff4[ks]);
                bhf[0][0] = t0[0]; bhf[0][1] = t0[1];
                bhf[1][0] = t0[2]; bhf[1][1] = t0[3];
                ldm_x2(bhf[2], tWh + wb + boff2[ks]);
            }
#pragma unroll
            for (int nt = 0; nt < 3; nt++) mma16816(acc[nt], al, bhf[nt]);
        }

        __syncthreads();                      // all MMA reads of Ah/Al done
        {
            float* sp = &scratch[warp * 384 + lane * 12];
#pragma unroll
            for (int nt = 0; nt < 3; nt++)
                *(float4*)(sp + nt * 4) = *(float4*)acc[nt];
        }
        __syncthreads();

        if (pw) {
            float gh[3];
#pragma unroll
            for (int nt = 0; nt < 3; nt++) {
                float s0 = 0.f;
#pragma unroll
                for (int kq2 = 0; kq2 < 8; kq2++)
                    s0 += scratch[(kq2 * 2 + mtb) * 384 + lsrc * 12 + nt * 4 + epos];
                gh[nt] = s0 + bh3[nt];
            }
            float hold = hloc[uu * 32 + bb];
            float rr = 1.f / (1.f + expf(-(pgx[0] + gh[0])));
            float zz = 1.f / (1.f + expf(-(pgx[1] + gh[1])));
            float nn = tanhf(pgx[2] + rr * gh[2]);
            float hnew = (1.f - zz) * nn + zz * hold;

            hloc[uu * 32 + bb] = hnew;

            {
                int row = t * BB + bb;
                int nb = row >> 7, nr = row & 127;
                size_t basef = (((size_t)nb * (HH >> 6)) + kc_f) << 13;
                Fa[basef + nr * 64 + ((ch_f ^ (nr & 7)) << 3) + je_f] = __float2half(hnew);
            }
            {
                __nv_bfloat16 hb = __float2bfloat16(hnew);
                __nv_bfloat16 lb = __float2bfloat16(hnew - __bfloat162float(hb));
                g_hBh[(t + 1) & 1][hoff] = hb;
                g_hBl[(t + 1) & 1][hoff] = lb;
            }
            if (t == TT - 1) hidden[bb * HH + j] = hnew;
            __threadfence();
        }
        __syncthreads();

        if (t < TT - 1 && tid == 0) {
            // monotonic-counter grid barrier, then launch both copies; the
            // other threads proceed straight to the hmbH wait of step t+1.
            atomicAdd(&g_cnt, 1u);
            unsigned target = (unsigned)(t + 1) * NCTA;
            while (ld_acq(&g_cnt) < target) {}
            mbar_expect_tx(hmbH, 65536);
            bulk_cp(tAh, &g_hBh[(t + 1) & 1][0], 65536, hmbH);
            mbar_expect_tx(hmbL, 65536);
            bulk_cp(tAl, &g_hBl[(t + 1) & 1][0], 65536, hmbL);
        }
    }
}

// ---------------- launch -------------------------------------------------------
extern "C" void kernel_launch(void* const* d_in, const int* in_sizes, int n_in,
                              void* d_out, int out_size)
{
    const int*   inputs = (const int*)  d_in[0];
    const float* emb    = (const float*)d_in[3];
    const float* w_ih   = (const float*)d_in[4];
    const float* w_hh   = (const float*)d_in[5];
    const float* b_ih   = (const float*)d_in[6];
    const float* b_hh   = (const float*)d_in[7];
    const float* out_w  = (const float*)d_in[8];
    const float* out_b  = (const float*)d_in[9];

    float* logits = (float*)d_out;
    float* hidden = (float*)d_out + (size_t)MM * VV;

    float* gx;   cudaGetSymbolAddress((void**)&gx,   g_gx);
    __nv_bfloat16 *Xh, *Xl, *Wh, *Wl;
    __half *Fw, *Fa;
    cudaGetSymbolAddress((void**)&Xh, g_Xh);
    cudaGetSymbolAddress((void**)&Xl, g_Xl);
    cudaGetSymbolAddress((void**)&Wh, g_Wh);
    cudaGetSymbolAddress((void**)&Wl, g_Wl);
    cudaGetSymbolAddress((void**)&Fw, g_Fw);
    cudaGetSymbolAddress((void**)&Fa, g_Fa);

    const int bgemm_smem = 1024 + NSTAGE * STAGEB + 1024;
    cudaFuncSetAttribute(bgemm_mma, cudaFuncAttributeMaxDynamicSharedMemorySize, bgemm_smem);
    const int hgemm_smem = 1024 + NSTAGEH * STAGEH + 1024;
    cudaFuncSetAttribute(hgemm_mma, cudaFuncAttributeMaxDynamicSharedMemorySize, hgemm_smem);
    cudaFuncSetAttribute(gru_persistent, cudaFuncAttributeMaxDynamicSharedMemorySize, GRU_SMEM);

    // 0: fused emb-gather + w_ih split
    {
        int total = (MM + GG) * (EE / 8);
        split_xw<<<(total + 255) / 256, 256>>>(emb, w_ih, Xh, Xl, Wh, Wl, inputs);
    }

    // 1: gx = X @ w_ih^T + b_ih (bf16x3)
    {
        dim3 grid(MM / 128, GG / 128);
        bgemm_mma<<<grid, 512, bgemm_smem>>>(Xh, Xl, Wh, Wl, b_ih, gx, GG, EE);
    }

    // 2: barrier state init
    init_barrier<<<1, 32>>>();

    // 3: GRU recurrence (tensor-core dots; split hi/lo h pipeline)
    gru_persistent<<<NCTA, 512, GRU_SMEM>>>(w_hh, b_hh, gx, Fa, hidden);

    // 4: out_w -> fp16 blocked
    split_f16<<<(VV * (HH / 8) + 255) / 256, 256>>>(out_w, Fw, VV, HH);

    // 5: logits = hall @ out_w^T + out_b (fp16, 128x256 tiles)
    {
        dim3 grid(MM / 128, VV / 256);   // (32, 125)
        hgemm_mma<<<grid, 512, hgemm_smem>>>(Fa, Fw, out_b, logits, VV, HH);
    }
}